// round 13
// baseline (speedup 1.0000x reference)
#include <cuda_runtime.h>
#include <cuda_fp16.h>
#include <math.h>
#include <cstdint>

#define H 16
#define S 2048
#define D 1024
#define DH 64
#define RANK 16

// ---------------- scratch (device globals; no allocation allowed) ----------------
__device__ float g_q[H * S * DH];
__device__ float g_k[H * S * DH];
__device__ float g_v[H * S * DH];
__device__ float g_alpha[H * S * DH];
__device__ __half g_alphaH[H * S * DH];
__device__ float g_r[H * S * DH];
__device__ __half g_ctxH[H * S * DH];   // normalized ctx = K'@alpha (hi)
__device__ __half g_ctxL[H * S * DH];   // normalized ctx (lo)
__device__ __half g_Kh[(size_t)H * S * S];       // 128 MB fp16 row-normalized kernel
__device__ float g_scale[H * S];                 // per-row scale exp(-dmin*inv)
__device__ float g_qn[H * S];
__device__ float g_kn[H * S];
__device__ float g_diagp[H * S];
__device__ float g_U[H * S * RANK];
__device__ float g_utr_part[32 * H * RANK * DH];   // 32 partial blocks (one per M tile)

// split fp16 operands
__device__ __half g_xh[S * D],  g_xl[S * D];
__device__ __half g_Wh[3 * D * D], g_Wl[3 * D * D];   // Wq, Wk, Wv
__device__ __half g_Woh[D * D], g_Wol[D * D];
__device__ __half g_qhh[H * S * DH], g_qll[H * S * DH];
__device__ __half g_khh[H * S * DH], g_kll[H * S * DH];
__device__ __half g_kTh[H * DH * S], g_kTl[H * DH * S];  // transposed k

__device__ __forceinline__ float softplusf(float x) {
    return (x > 20.f) ? x : log1pf(expf(x));
}

// ======================= HMMA helpers (mma.sync + ldmatrix) =======================
__device__ __forceinline__ uint32_t smem_u32(const void* p) {
    uint32_t a;
    asm("{ .reg .u64 t; cvta.to.shared.u64 t, %1; cvt.u32.u64 %0, t; }" : "=r"(a) : "l"(p));
    return a;
}
__device__ __forceinline__ void ldm_x4(uint32_t* r, uint32_t addr) {
    asm volatile("ldmatrix.sync.aligned.m8n8.x4.shared.b16 {%0,%1,%2,%3}, [%4];"
                 : "=r"(r[0]), "=r"(r[1]), "=r"(r[2]), "=r"(r[3]) : "r"(addr));
}
__device__ __forceinline__ void ldm_x4_trans(uint32_t* r, uint32_t addr) {
    asm volatile("ldmatrix.sync.aligned.m8n8.x4.trans.shared.b16 {%0,%1,%2,%3}, [%4];"
                 : "=r"(r[0]), "=r"(r[1]), "=r"(r[2]), "=r"(r[3]) : "r"(addr));
}
__device__ __forceinline__ void mma16816(float* c, const uint32_t* a, uint32_t b0, uint32_t b1) {
    asm volatile(
        "mma.sync.aligned.m16n8k16.row.col.f32.f16.f16.f32 "
        "{%0,%1,%2,%3}, {%4,%5,%6,%7}, {%8,%9}, {%0,%1,%2,%3};"
        : "+f"(c[0]), "+f"(c[1]), "+f"(c[2]), "+f"(c[3])
        : "r"(a[0]), "r"(a[1]), "r"(a[2]), "r"(a[3]), "r"(b0), "r"(b1));
}
__device__ __forceinline__ void cp_async16(uint32_t saddr, const void* gaddr) {
    asm volatile("cp.async.cg.shared.global [%0], [%1], 16;" :: "r"(saddr), "l"(gaddr) : "memory");
}

// ---------------- fp32 -> (hi, lo) fp16 split conversion (merged) -----------------
__global__ void cvt_all(const float* __restrict__ x, const float* __restrict__ wq,
                        const float* __restrict__ wk, const float* __restrict__ wv,
                        const float* __restrict__ wo) {
    int i = blockIdx.x * blockDim.x + threadIdx.x;
    const int NX = S * D, NW = D * D;
    const float* src;
    __half *hi, *lo;
    int off;
    if (i < NX)               { src = x;  hi = g_xh;           lo = g_xl;           off = i; }
    else if (i < NX + NW)     { src = wq; hi = g_Wh;           lo = g_Wl;           off = i - NX; }
    else if (i < NX + 2 * NW) { src = wk; hi = g_Wh + NW;      lo = g_Wl + NW;      off = i - NX - NW; }
    else if (i < NX + 3 * NW) { src = wv; hi = g_Wh + 2 * NW;  lo = g_Wl + 2 * NW;  off = i - NX - 2 * NW; }
    else if (i < NX + 4 * NW) { src = wo; hi = g_Woh;          lo = g_Wol;          off = i - NX - 3 * NW; }
    else return;
    float v = src[off];
    __half h = __float2half(v);
    hi[off] = h;
    lo[off] = __float2half(v - __half2float(h));
}

// ===== QKV split-fp16 tensor GEMM: C = x @ W_z, output heads layout + hi/lo =======
__global__ void __launch_bounds__(256) qkv_tc() {
    extern __shared__ __align__(16) char sm[];
    __half* Ah = (__half*)sm;                 // [128][72]
    __half* Alo = (__half*)(sm + 18432);
    __half* Bh = (__half*)(sm + 36864);       // [64][136]
    __half* Bl = (__half*)(sm + 54272);

    int tid = threadIdx.x, lane = tid & 31, wid = tid >> 5;
    int wm = wid >> 1, wn = wid & 1;
    int row0 = blockIdx.y * 128, col0 = blockIdx.x * 128;
    int which = blockIdx.z;
    const __half* Whp = g_Wh + (size_t)which * D * D;
    const __half* Wlp = g_Wl + (size_t)which * D * D;

    float acc[2][8][4];
#pragma unroll
    for (int i = 0; i < 2; i++)
#pragma unroll
        for (int j = 0; j < 8; j++)
#pragma unroll
            for (int l = 0; l < 4; l++) acc[i][j][l] = 0.f;

    uint32_t ah_b = smem_u32(Ah), al_b = smem_u32(Alo);
    uint32_t bh_b = smem_u32(Bh), bl_b = smem_u32(Bl);
    int lm = lane & 15, lh = lane >> 4;

    for (int k0 = 0; k0 < D; k0 += 64) {
#pragma unroll
        for (int e = 0; e < 4; e++) {
            int idx = tid + 256 * e;           // 0..1023
            int m = idx >> 3, c8 = idx & 7;
            *(uint4*)&Ah[m * 72 + c8 * 8]  = *(const uint4*)&g_xh[(size_t)(row0 + m) * D + k0 + c8 * 8];
            *(uint4*)&Alo[m * 72 + c8 * 8] = *(const uint4*)&g_xl[(size_t)(row0 + m) * D + k0 + c8 * 8];
            int kb = idx >> 4, c16 = idx & 15;
            *(uint4*)&Bh[kb * 136 + c16 * 8] = *(const uint4*)&Whp[(size_t)(k0 + kb) * D + col0 + c16 * 8];
            *(uint4*)&Bl[kb * 136 + c16 * 8] = *(const uint4*)&Wlp[(size_t)(k0 + kb) * D + col0 + c16 * 8];
        }
        __syncthreads();
#pragma unroll
        for (int kk = 0; kk < 64; kk += 16) {
            uint32_t a_h[2][4], a_l[2][4];
#pragma unroll
            for (int mt = 0; mt < 2; mt++) {
                ldm_x4(a_h[mt], ah_b + ((wm * 32 + mt * 16 + lm) * 72 + kk + lh * 8) * 2);
                ldm_x4(a_l[mt], al_b + ((wm * 32 + mt * 16 + lm) * 72 + kk + lh * 8) * 2);
            }
#pragma unroll
            for (int ng = 0; ng < 4; ng++) {
                uint32_t b_h[4], b_l[4];
                ldm_x4_trans(b_h, bh_b + ((kk + lm) * 136 + wn * 64 + ng * 16 + lh * 8) * 2);
                ldm_x4_trans(b_l, bl_b + ((kk + lm) * 136 + wn * 64 + ng * 16 + lh * 8) * 2);
#pragma unroll
                for (int mt = 0; mt < 2; mt++) {
                    mma16816(acc[mt][ng * 2 + 0], a_h[mt], b_h[0], b_h[1]);
                    mma16816(acc[mt][ng * 2 + 0], a_h[mt], b_l[0], b_l[1]);
                    mma16816(acc[mt][ng * 2 + 0], a_l[mt], b_h[0], b_h[1]);
                    mma16816(acc[mt][ng * 2 + 1], a_h[mt], b_h[2], b_h[3]);
                    mma16816(acc[mt][ng * 2 + 1], a_h[mt], b_l[2], b_l[3]);
                    mma16816(acc[mt][ng * 2 + 1], a_l[mt], b_h[2], b_h[3]);
                }
            }
        }
        __syncthreads();
    }

    float* outF = (which == 0) ? g_q : (which == 1) ? g_k : g_v;
    __half* oh = (which == 0) ? g_qhh : g_khh;
    __half* ol = (which == 0) ? g_qll : g_kll;
#pragma unroll
    for (int mt = 0; mt < 2; mt++) {
        int r0 = row0 + wm * 32 + mt * 16 + (lane >> 2);
#pragma unroll
        for (int nt = 0; nt < 8; nt++) {
            int c = col0 + wn * 64 + nt * 8 + (lane & 3) * 2;
            int hh = c >> 6, dh = c & 63;
#pragma unroll
            for (int rr = 0; rr < 2; rr++) {
                int s = r0 + rr * 8;
                float v0 = acc[mt][nt][rr * 2 + 0], v1 = acc[mt][nt][rr * 2 + 1];
                size_t gi = ((size_t)hh * S + s) * DH + dh;
                *(float2*)&outF[gi] = make_float2(v0, v1);
                if (which < 2) {
                    __half h0 = __float2half(v0), h1 = __float2half(v1);
                    *(__half2*)&oh[gi] = __halves2half2(h0, h1);
                    *(__half2*)&ol[gi] = __halves2half2(
                        __float2half(v0 - __half2float(h0)),
                        __float2half(v1 - __half2float(h1)));
                }
            }
        }
    }
}

// ---------------- fused: row norms of q,k + diag_p (one 16MB pass) ----------------
__global__ void norms_diag(const float* __restrict__ diag_scale,
                           const float* __restrict__ reg_p,
                           const float* __restrict__ bw_p) {
    int gw = (blockIdx.x * blockDim.x + threadIdx.x) >> 5;
    int lane = threadIdx.x & 31;
    if (gw >= H * S) return;
    const float* qp = g_q + (size_t)gw * DH;
    const float* kp = g_k + (size_t)gw * DH;
    float qa = qp[lane], qb = qp[lane + 32];
    float ka = kp[lane], kb = kp[lane + 32];
    float qn = qa * qa + qb * qb;
    float kn = ka * ka + kb * kb;
    float da = qa - ka, db = qb - kb;
    float dd = da * da + db * db;
#pragma unroll
    for (int o = 16; o > 0; o >>= 1) {
        qn += __shfl_xor_sync(0xffffffffu, qn, o);
        kn += __shfl_xor_sync(0xffffffffu, kn, o);
        dd += __shfl_xor_sync(0xffffffffu, dd, o);
    }
    if (lane == 0) {
        g_qn[gw] = qn;
        g_kn[gw] = kn;
        float bw = softplusf(bw_p[0]) + 1e-6f;
        float inv = 1.0f / (2.0f * bw * bw);
        float kd = __expf(-dd * inv);
        g_diagp[gw] = softplusf(kd) * diag_scale[gw / S] + reg_p[0];
    }
}

// ---------------- transpose k hi/lo: [h][s][dh] -> [h][dh][s] ----------------------
__global__ void transpose_k() {
    __shared__ __half t0[32][33];
    __shared__ __half t1[32][33];
    int h = blockIdx.z;
    int s0 = blockIdx.x * 32, d0 = blockIdx.y * 32;
    int tx = threadIdx.x, ty = threadIdx.y;   // 32 x 8
#pragma unroll
    for (int i = 0; i < 32; i += 8) {
        t0[ty + i][tx] = g_khh[((size_t)h * S + s0 + ty + i) * DH + d0 + tx];
        t1[ty + i][tx] = g_kll[((size_t)h * S + s0 + ty + i) * DH + d0 + tx];
    }
    __syncthreads();
#pragma unroll
    for (int i = 0; i < 32; i += 8) {
        g_kTh[((size_t)h * DH + d0 + ty + i) * S + s0 + tx] = t0[tx][ty + i];
        g_kTl[((size_t)h * DH + d0 + ty + i) * S + s0 + tx] = t1[tx][ty + i];
    }
}

// ===== fused kmat (FULL phase1, cp.async double-buffered B tiles) =================
__global__ void __launch_bounds__(256) kmat_tc(const float* __restrict__ bw_p) {
    extern __shared__ __align__(16) char sm[];
    __half* Qh = (__half*)sm;                 // [128][72] 18432
    __half* Ql = (__half*)(sm + 18432);       // 18432
    float* qn_s = (float*)(sm + 106496);      // 512
    float* kn_p0 = (float*)(sm + 107008);     // 512
    float* kn_p1 = (float*)(sm + 107520);     // 512
    unsigned* minv = (unsigned*)(sm + 108032);// 512   -> total 108544

    uint32_t base = smem_u32(sm);
    uint32_t bhB[2] = {base + 36864u, base + 71680u};
    uint32_t blB[2] = {base + 54272u, base + 89088u};
    uint32_t knB[2] = {base + 107008u, base + 107520u};
    float* kn_p[2] = {kn_p0, kn_p1};

    int tid = threadIdx.x, lane = tid & 31, wid = tid >> 5;
    int h = blockIdx.y, i0 = blockIdx.x * 128;
    float bw = softplusf(bw_p[0]) + 1e-6f;
    float inv = 1.0f / (2.0f * bw * bw);

#pragma unroll
    for (int e = 0; e < 4; e++) {
        int idx = tid + 256 * e;
        int m = idx >> 3, c8 = idx & 7;
        *(uint4*)&Qh[m * 72 + c8 * 8] = *(const uint4*)&g_qhh[((size_t)h * S + i0 + m) * DH + c8 * 8];
        *(uint4*)&Ql[m * 72 + c8 * 8] = *(const uint4*)&g_qll[((size_t)h * S + i0 + m) * DH + c8 * 8];
    }
    if (tid < 128) {
        qn_s[tid] = g_qn[h * S + i0 + tid];
        minv[tid] = 0x7F800000u;
    }
    __syncthreads();

    uint32_t qh_b = smem_u32(Qh), ql_b = smem_u32(Ql);
    int lm = lane & 15, lh = lane >> 4;

    const __half* kThp = g_kTh + (size_t)h * DH * S;
    const __half* kTlp = g_kTl + (size_t)h * DH * S;

    float rmin[16];
#pragma unroll
    for (int i = 0; i < 16; i++) rmin[i] = 3.4e38f;

    // ---------------- phase 1: hi-only dist over ALL columns (pipelined) ----------
    {
#pragma unroll
        for (int e = 0; e < 4; e++) {
            int idx = tid + 256 * e;
            int kb = idx >> 4, c16 = idx & 15;
            cp_async16(bhB[0] + (uint32_t)(kb * 272 + c16 * 16),
                       kThp + (size_t)kb * S + c16 * 8);
        }
        if (tid < 32)
            cp_async16(knB[0] + (uint32_t)(tid * 16), &g_kn[h * S + tid * 4]);
        asm volatile("cp.async.commit_group;" ::: "memory");
    }

    for (int c = 0; c < 16; c++) {
        int st = c & 1;
        if (c < 15) {
            int j0n = (c + 1) * 128;
            int sn = st ^ 1;
#pragma unroll
            for (int e = 0; e < 4; e++) {
                int idx = tid + 256 * e;
                int kb = idx >> 4, c16 = idx & 15;
                cp_async16(bhB[sn] + (uint32_t)(kb * 272 + c16 * 16),
                           kThp + (size_t)kb * S + j0n + c16 * 8);
            }
            if (tid < 32)
                cp_async16(knB[sn] + (uint32_t)(tid * 16), &g_kn[h * S + j0n + tid * 4]);
            asm volatile("cp.async.commit_group;" ::: "memory");
            asm volatile("cp.async.wait_group 1;" ::: "memory");
        } else {
            asm volatile("cp.async.wait_group 0;" ::: "memory");
        }
        __syncthreads();

        uint32_t bf[4][4];
#pragma unroll
        for (int k4 = 0; k4 < 4; k4++)
            ldm_x4_trans(bf[k4], bhB[st] + (uint32_t)(((k4 * 16 + lm) * 136 + wid * 16 + lh * 8) * 2));

        const float* kns = kn_p[st];
#pragma unroll
        for (int mt = 0; mt < 8; mt++) {
            float a0[4] = {0.f, 0.f, 0.f, 0.f}, a1[4] = {0.f, 0.f, 0.f, 0.f};
#pragma unroll
            for (int k4 = 0; k4 < 4; k4++) {
                uint32_t a[4];
                ldm_x4(a, qh_b + ((mt * 16 + lm) * 72 + k4 * 16 + lh * 8) * 2);
                mma16816(a0, a, bf[k4][0], bf[k4][1]);
                mma16816(a1, a, bf[k4][2], bf[k4][3]);
            }
            int r = mt * 16 + (lane >> 2);
            float qn0 = qn_s[r], qn1 = qn_s[r + 8];
            int cb = wid * 16 + (lane & 3) * 2;
            float kn0 = kns[cb], kn1 = kns[cb + 1], kn8 = kns[cb + 8], kn9 = kns[cb + 9];
            float d0 = fminf(fminf(qn0 + kn0 - 2.f * a0[0], qn0 + kn1 - 2.f * a0[1]),
                             fminf(qn0 + kn8 - 2.f * a1[0], qn0 + kn9 - 2.f * a1[1]));
            float d1 = fminf(fminf(qn1 + kn0 - 2.f * a0[2], qn1 + kn1 - 2.f * a0[3]),
                             fminf(qn1 + kn8 - 2.f * a1[2], qn1 + kn9 - 2.f * a1[3]));
            rmin[mt * 2] = fminf(rmin[mt * 2], d0);
            rmin[mt * 2 + 1] = fminf(rmin[mt * 2 + 1], d1);
        }
        __syncthreads();
    }
#pragma unroll
    for (int i = 0; i < 16; i++) {
        rmin[i] = fminf(rmin[i], __shfl_xor_sync(0xffffffffu, rmin[i], 1));
        rmin[i] = fminf(rmin[i], __shfl_xor_sync(0xffffffffu, rmin[i], 2));
    }
    if ((lane & 3) == 0) {
#pragma unroll
        for (int mt = 0; mt < 8; mt++) {
            atomicMin(&minv[mt * 16 + (lane >> 2)], __float_as_uint(fmaxf(rmin[mt * 2], 0.f)));
            atomicMin(&minv[mt * 16 + (lane >> 2) + 8], __float_as_uint(fmaxf(rmin[mt * 2 + 1], 0.f)));
        }
    }
    __syncthreads();
    if (tid < 128)
        g_scale[h * S + i0 + tid] = __expf(-__uint_as_float(minv[tid]) * inv);

    // ---------------- phase 2: split dist, exp -> Kh fp16 (pipelined) -------------
    {
#pragma unroll
        for (int e = 0; e < 4; e++) {
            int idx = tid + 256 * e;
            int kb = idx >> 4, c16 = idx & 15;
            cp_async16(bhB[0] + (uint32_t)(kb * 272 + c16 * 16),
                       kThp + (size_t)kb * S + c16 * 8);
            cp_async16(blB[0] + (uint32_t)(kb * 272 + c16 * 16),
                       kTlp + (size_t)kb * S + c16 * 8);
        }
        if (tid < 32)
            cp_async16(knB[0] + (uint32_t)(tid * 16), &g_kn[h * S + tid * 4]);
        asm volatile("cp.async.commit_group;" ::: "memory");
    }

    for (int c = 0; c < 16; c++) {
        int st = c & 1;
        int j0 = c * 128;
        if (c < 15) {
            int j0n = (c + 1) * 128;
            int sn = st ^ 1;
#pragma unroll
            for (int e = 0; e < 4; e++) {
                int idx = tid + 256 * e;
                int kb = idx >> 4, c16 = idx & 15;
                cp_async16(bhB[sn] + (uint32_t)(kb * 272 + c16 * 16),
                           kThp + (size_t)kb * S + j0n + c16 * 8);
                cp_async16(blB[sn] + (uint32_t)(kb * 272 + c16 * 16),
                           kTlp + (size_t)kb * S + j0n + c16 * 8);
            }
            if (tid < 32)
                cp_async16(knB[sn] + (uint32_t)(tid * 16), &g_kn[h * S + j0n + tid * 4]);
            asm volatile("cp.async.commit_group;" ::: "memory");
            asm volatile("cp.async.wait_group 1;" ::: "memory");
        } else {
            asm volatile("cp.async.wait_group 0;" ::: "memory");
        }
        __syncthreads();

        uint32_t bfh[4][4], bfl[4][4];
#pragma unroll
        for (int k4 = 0; k4 < 4; k4++) {
            ldm_x4_trans(bfh[k4], bhB[st] + (uint32_t)(((k4 * 16 + lm) * 136 + wid * 16 + lh * 8) * 2));
            ldm_x4_trans(bfl[k4], blB[st] + (uint32_t)(((k4 * 16 + lm) * 136 + wid * 16 + lh * 8) * 2));
        }

        const float* kns = kn_p[st];
#pragma unroll
        for (int mt = 0; mt < 8; mt++) {
            float a0[4] = {0.f, 0.f, 0.f, 0.f}, a1[4] = {0.f, 0.f, 0.f, 0.f};
#pragma unroll
            for (int k4 = 0; k4 < 4; k4++) {
                uint32_t ah[4], al[4];
                ldm_x4(ah, qh_b + ((mt * 16 + lm) * 72 + k4 * 16 + lh * 8) * 2);
                ldm_x4(al, ql_b + ((mt * 16 + lm) * 72 + k4 * 16 + lh * 8) * 2);
                mma16816(a0, ah, bfh[k4][0], bfh[k4][1]);
                mma16816(a0, ah, bfl[k4][0], bfl[k4][1]);
                mma16816(a0, al, bfh[k4][0], bfh[k4][1]);
                mma16816(a1, ah, bfh[k4][2], bfh[k4][3]);
                mma16816(a1, ah, bfl[k4][2], bfl[k4][3]);
                mma16816(a1, al, bfh[k4][2], bfh[k4][3]);
            }
            int r = mt * 16 + (lane >> 2);
            float qn0 = qn_s[r], qn1 = qn_s[r + 8];
            float dm0 = __uint_as_float(minv[r]), dm1 = __uint_as_float(minv[r + 8]);
            int cb = wid * 16 + (lane & 3) * 2;
            float kn0 = kns[cb], kn1 = kns[cb + 1], kn8 = kns[cb + 8], kn9 = kns[cb + 9];
            float e00 = __expf((dm0 - fmaxf(qn0 + kn0 - 2.f * a0[0], 0.f)) * inv);
            float e01 = __expf((dm0 - fmaxf(qn0 + kn1 - 2.f * a0[1], 0.f)) * inv);
            float e10 = __expf((dm1 - fmaxf(qn1 + kn0 - 2.f * a0[2], 0.f)) * inv);
            float e11 = __expf((dm1 - fmaxf(qn1 + kn1 - 2.f * a0[3], 0.f)) * inv);
            float f00 = __expf((dm0 - fmaxf(qn0 + kn8 - 2.f * a1[0], 0.f)) * inv);
            float f01 = __expf((dm0 - fmaxf(qn0 + kn9 - 2.f * a1[1], 0.f)) * inv);
            float f10 = __expf((dm1 - fmaxf(qn1 + kn8 - 2.f * a1[2], 0.f)) * inv);
            float f11 = __expf((dm1 - fmaxf(qn1 + kn9 - 2.f * a1[3], 0.f)) * inv);
            __half* Kp0 = &g_Kh[((size_t)(h * S + i0 + r)) * S + j0 + cb];
            __half* Kp1 = Kp0 + (size_t)8 * S;
            *(__half2*)Kp0 = __halves2half2(__float2half(e00), __float2half(e01));
            *(__half2*)(Kp0 + 8) = __halves2half2(__float2half(f00), __float2half(f01));
            *(__half2*)Kp1 = __halves2half2(__float2half(e10), __float2half(e11));
            *(__half2*)(Kp1 + 8) = __halves2half2(__float2half(f10), __float2half(f11));
        }
        __syncthreads();
    }
}

// ---------------- U[h,s,r] = sum_rp pos[s,rp] * proj[h,rp,r] ----------------------
__global__ void u_kernel(const float* __restrict__ pos, const float* __restrict__ proj) {
    __shared__ float pr[RANK][RANK];
    int h = blockIdx.y;
    int tid = threadIdx.x;
    pr[tid >> 4][tid & 15] = proj[h * RANK * RANK + tid];
    __syncthreads();
    int s = blockIdx.x * 256 + tid;
    float pe[RANK];
#pragma unroll
    for (int r = 0; r < RANK; r++) pe[r] = pos[(size_t)s * RANK + r];
#pragma unroll
    for (int r = 0; r < RANK; r++) {
        float acc = 0.f;
#pragma unroll
        for (int rp = 0; rp < RANK; rp++) acc += pe[rp] * pr[rp][r];
        g_U[((size_t)h * S + s) * RANK + r] = acc;
    }
}

// == HMMA K@alpha, M=64 tiles (512 CTAs) + fused U^T r partial =====================
// mode0: r = v - scale*K'a - lam*a, writes g_r AND utr_part[blockIdx.x]
// mode1: store NORMALIZED K'a hi/lo
__global__ void __launch_bounds__(256) kapply_mma(int mode, const float* __restrict__ lam_p) {
    extern __shared__ __align__(16) char sm[];
    uint32_t base = smem_u32(sm);
    // buffers: Ks[2] @ 0 / 9216 (64x72 fp16), Al[2] @ 18432 / 27648 (64x72 fp16)
    uint32_t ksb0 = base, ksb1 = base + 9216;
    uint32_t alb0 = base + 18432, alb1 = base + 27648;

    int tid = threadIdx.x, wid = tid >> 5, lane = tid & 31;
    int wm = wid >> 1, wn = wid & 1;     // 4 M-subtiles x 2 N-halves
    int h = blockIdx.y;
    int s0 = blockIdx.x * 64;

    const __half* Kb = g_Kh + ((size_t)h * S + s0) * S;
    const __half* Ab = g_alphaH + (size_t)h * S * DH;

    float acc[4][4];
#pragma unroll
    for (int i = 0; i < 4; i++)
#pragma unroll
        for (int j = 0; j < 4; j++) acc[i][j] = 0.f;

    int lm = lane & 15, lh = lane >> 4;
    int mA = tid >> 3, c8A = tid & 7;    // 32 rows x 8 col-groups per pass

    // prefetch chunk 0 into buffer 0
    {
#pragma unroll
        for (int e = 0; e < 2; e++) {
            int m = mA + 32 * e;
            cp_async16(ksb0 + (uint32_t)(m * 144 + c8A * 16), Kb + (size_t)m * S + c8A * 8);
            cp_async16(alb0 + (uint32_t)(m * 144 + c8A * 16), Ab + (size_t)m * DH + c8A * 8);
        }
        asm volatile("cp.async.commit_group;" ::: "memory");
    }

    for (int c = 0; c < 32; c++) {
        uint32_t ks_cur = (c & 1) ? ksb1 : ksb0;
        uint32_t al_cur = (c & 1) ? alb1 : alb0;
        if (c < 31) {
            uint32_t ks_nxt = (c & 1) ? ksb0 : ksb1;
            uint32_t al_nxt = (c & 1) ? alb0 : alb1;
            int t0 = (c + 1) * 64;
#pragma unroll
            for (int e = 0; e < 2; e++) {
                int m = mA + 32 * e;
                cp_async16(ks_nxt + (uint32_t)(m * 144 + c8A * 16), Kb + (size_t)m * S + t0 + c8A * 8);
                cp_async16(al_nxt + (uint32_t)(m * 144 + c8A * 16), Ab + (size_t)(t0 + m) * DH + c8A * 8);
            }
            asm volatile("cp.async.commit_group;" ::: "memory");
            asm volatile("cp.async.wait_group 1;" ::: "memory");
        } else {
            asm volatile("cp.async.wait_group 0;" ::: "memory");
        }
        __syncthreads();

#pragma unroll
        for (int kk = 0; kk < 64; kk += 16) {
            uint32_t a[4];
            ldm_x4(a, ks_cur + (uint32_t)(((wm * 16 + lm) * 72 + kk + lh * 8) * 2));
#pragma unroll
            for (int nt = 0; nt < 2; nt++) {
                uint32_t b[4];
                ldm_x4_trans(b, al_cur + (uint32_t)(((kk + lm) * 72 + wn * 32 + nt * 16 + lh * 8) * 2));
                mma16816(acc[nt * 2 + 0], a, b[0], b[1]);
                mma16816(acc[nt * 2 + 1], a, b[2], b[3]);
            }
        }
        __syncthreads();
    }

    int rl0 = wm * 16 + (lane >> 2);     // local row in 0..63
    int rbase = s0 + rl0;
    float sc0 = g_scale[h * S + rbase];
    float sc1 = g_scale[h * S + rbase + 8];

    if (mode == 0) {
        float lam = softplusf(lam_p[0]);
        // stage r into smem for fused U^T r; pipeline buffers are dead
        float* rsm = (float*)sm;              // [64][65] = 16640 B
        float* Usm = (float*)(sm + 16640);    // [64][16] =  4096 B
#pragma unroll
        for (int e = 0; e < 4; e++) {
            int idx = tid + 256 * e;          // 0..1023
            int m = idx >> 4, rr = idx & 15;
            Usm[m * 16 + rr] = g_U[((size_t)h * S + s0 + m) * RANK + rr];
        }
#pragma unroll
        for (int nt = 0; nt < 4; nt++) {
            int col = wn * 32 + nt * 8 + (lane & 3) * 2;
            size_t g0 = ((size_t)h * S + rbase) * DH + col;
            size_t g1 = g0 + 8 * DH;
            float2 v0 = *(const float2*)&g_v[g0];
            float2 v1 = *(const float2*)&g_v[g1];
            float2 a0 = *(const float2*)&g_alpha[g0];
            float2 a1 = *(const float2*)&g_alpha[g1];
            float r00 = v0.x - sc0 * acc[nt][0] - lam * a0.x;
            float r01 = v0.y - sc0 * acc[nt][1] - lam * a0.y;
            float r10 = v1.x - sc1 * acc[nt][2] - lam * a1.x;
            float r11 = v1.y - sc1 * acc[nt][3] - lam * a1.y;
            *(float2*)&g_r[g0] = make_float2(r00, r01);
            *(float2*)&g_r[g1] = make_float2(r10, r11);
            rsm[rl0 * 65 + col] = r00;
            rsm[rl0 * 65 + col + 1] = r01;
            rsm[(rl0 + 8) * 65 + col] = r10;
            rsm[(rl0 + 8) * 65 + col + 1] = r11;
        }
        __syncthreads();

        // fused partial U^T r over this CTA's 64 rows
        int d = tid & 63, rg = tid >> 6;      // rg in 0..3
        float a4[4] = {0.f, 0.f, 0.f, 0.f};
        for (int s = 0; s < 64; s++) {
            float rv = rsm[s * 65 + d];
            a4[0] += Usm[s * 16 + rg] * rv;
            a4[1] += Usm[s * 16 + rg + 4] * rv;
            a4[2] += Usm[s * 16 + rg + 8] * rv;
            a4[3] += Usm[s * 16 + rg + 12] * rv;
        }
        int part = blockIdx.x;                // 0..31
#pragma unroll
        for (int i = 0; i < 4; i++)
            g_utr_part[(((size_t)part * H + h) * RANK + (rg + 4 * i)) * DH + d] = a4[i];
    } else {
#pragma unroll
        for (int nt = 0; nt < 4; nt++) {
            int col = wn * 32 + nt * 8 + (lane & 3) * 2;
            size_t g0 = ((size_t)h * S + rbase) * DH + col;
            size_t g1 = g0 + 8 * DH;
            float c00 = acc[nt][0], c01 = acc[nt][1];
            float c10 = acc[nt][2], c11 = acc[nt][3];
            __half h00 = __float2half(c00), h01 = __float2half(c01);
            __half h10 = __float2half(c10), h11 = __float2half(c11);
            *(__half2*)&g_ctxH[g0] = __halves2half2(h00, h01);
            *(__half2*)&g_ctxH[g1] = __halves2half2(h10, h11);
            *(__half2*)&g_ctxL[g0] = __halves2half2(__float2half(c00 - __half2float(h00)),
                                                    __float2half(c01 - __half2float(h01)));
            *(__half2*)&g_ctxL[g1] = __halves2half2(__float2half(c10 - __half2float(h10)),
                                                    __float2half(c11 - __half2float(h11)));
        }
    }
}

// ------- utr_part[p,h,r,d] = sum_{s in part} U[h,s,r] * v[h,s,d] (iter 1 only) ----
__global__ void utr_kernel() {
    int h = blockIdx.x;
    int part = blockIdx.y;     // 0..31
    int tid = threadIdx.x;
    int d = tid & 63, rr = tid >> 6;
    const float* Ub = g_U + (size_t)h * S * RANK;
    const float* rb = g_v + (size_t)h * S * DH;
    int s0 = part * (S / 32);
    float a0 = 0, a1 = 0, a2 = 0, a3 = 0;
    for (int s = s0; s < s0 + S / 32; s += 4) {
        a0 += Ub[(s + 0) * RANK + rr] * rb[(size_t)(s + 0) * DH + d];
        a1 += Ub[(s + 1) * RANK + rr] * rb[(size_t)(s + 1) * DH + d];
        a2 += Ub[(s + 2) * RANK + rr] * rb[(size_t)(s + 2) * DH + d];
        a3 += Ub[(s + 3) * RANK + rr] * rb[(size_t)(s + 3) * DH + d];
    }
    g_utr_part[((part * H + h) * RANK + rr) * DH + d] = (a0 + a1) + (a2 + a3);
}

// ---------------- alpha = prev + r*diag_p + U @ utr; emit fp16 mirror -------------
__global__ void update_kernel(int first) {
    __shared__ float ut[RANK][DH];
    __shared__ float Us[16][RANK];
    int h = blockIdx.y;
    int tid = threadIdx.x;
    {
        float sum = 0.f;
#pragma unroll
        for (int p = 0; p < 32; p++) sum += g_utr_part[(p * H + h) * RANK * DH + tid];
        ut[tid >> 6][tid & 63] = sum;
    }
    int s0 = blockIdx.x * 16;
    if (tid < 16 * RANK)
        Us[tid >> 4][tid & 15] = g_U[((size_t)h * S + s0 + (tid >> 4)) * RANK + (tid & 15)];
    __syncthreads();

    int sl = tid >> 6;
    int d = tid & 63;
    int s = s0 + sl;
    size_t idx = ((size_t)h * S + s) * DH + d;
    float acc = 0.f;
#pragma unroll
    for (int r2 = 0; r2 < RANK; r2++) acc += Us[sl][r2] * ut[r2][d];
    float rv = first ? g_v[idx] : g_r[idx];
    float prev = first ? 0.f : g_alpha[idx];
    float na = prev + rv * g_diagp[h * S + s] + acc;
    g_alpha[idx] = na;
    g_alphaH[idx] = __float2half(na);
}

// == output GEMM (128x64 tiles): out = (scale ⊙ ctxN)_flat @ Wo ====================
__global__ void __launch_bounds__(256) wo_tc(float* __restrict__ out) {
    extern __shared__ __align__(16) char sm[];
    __half* Ah = (__half*)sm;                 // [128][72]
    __half* Alo = (__half*)(sm + 18432);
    __half* Bh = (__half*)(sm + 36864);       // [64][72]
    __half* Bl = (__half*)(sm + 46080);
    float* scs = (float*)(sm + 55296);        // 128 row scales

    int tid = threadIdx.x, lane = tid & 31, wid = tid >> 5;
    int wm = wid >> 1, wn = wid & 1;
    int row0 = blockIdx.y * 128, col0 = blockIdx.x * 64;

    float acc[2][4][4];
#pragma unroll
    for (int i = 0; i < 2; i++)
#pragma unroll
        for (int j = 0; j < 4; j++)
#pragma unroll
            for (int l = 0; l < 4; l++) acc[i][j][l] = 0.f;

    uint32_t ah_b = smem_u32(Ah), al_b = smem_u32(Alo);
    uint32_t bh_b = smem_u32(Bh), bl_b = smem_u32(Bl);
    int lm = lane & 15, lh = lane >> 4;

    for (int ck = 0; ck < 16; ck++) {
        int k0 = ck * 64;
#pragma unroll
        for (int e = 0; e < 4; e++) {
            int idx = tid + 256 * e;
            int m = idx >> 3, c8 = idx & 7;
            *(uint4*)&Ah[m * 72 + c8 * 8]  = *(const uint4*)&g_ctxH[((size_t)ck * S + row0 + m) * DH + c8 * 8];
            *(uint4*)&Alo[m * 72 + c8 * 8] = *(const uint4*)&g_ctxL[((size_t)ck * S + row0 + m) * DH + c8 * 8];
        }
#pragma unroll
        for (int e = 0; e < 2; e++) {
            int idx = tid + 256 * e;
            int kb = idx >> 3, c8 = idx & 7;
            *(uint4*)&Bh[kb * 72 + c8 * 8] = *(const uint4*)&g_Woh[(size_t)(k0 + kb) * D + col0 + c8 * 8];
            *(uint4*)&Bl[kb * 72 + c8 * 8] = *(const uint4*)&g_Wol[(size_t)(k0 + kb) * D + col0 + c8 * 8];
        }
        if (tid < 128) scs[tid] = g_scale[ck * S + row0 + tid];
        __syncthreads();

        float accp[2][4][4];
#pragma unroll
        for (int i = 0; i < 2; i++)
#pragma unroll
            for (int j = 0; j < 4; j++)
#pragma unroll
                for (int l = 0; l < 4; l++) accp[i][j][l] = 0.f;

#pragma unroll
        for (int kk = 0; kk < 64; kk += 16) {
            uint32_t a_h[2][4], a_l[2][4];
#pragma unroll
            for (int mt = 0; mt < 2; mt++) {
                ldm_x4(a_h[mt], ah_b + ((wm * 32 + mt * 16 + lm) * 72 + kk + lh * 8) * 2);
                ldm_x4(a_l[mt], al_b + ((wm * 32 + mt * 16 + lm) * 72 + kk + lh * 8) * 2);
            }
#pragma unroll
            for (int ng = 0; ng < 2; ng++) {
                uint32_t b_h[4], b_l[4];
                ldm_x4_trans(b_h, bh_b + ((kk + lm) * 72 + wn * 32 + ng * 16 + lh * 8) * 2);
                ldm_x4_trans(b_l, bl_b + ((kk + lm) * 72 + wn * 32 + ng * 16 + lh * 8) * 2);
#pragma unroll
                for (int mt = 0; mt < 2; mt++) {
                    mma16816(accp[mt][ng * 2 + 0], a_h[mt], b_h[0], b_h[1]);
                    mma16816(accp[mt][ng * 2 + 0], a_h[mt], b_l[0], b_l[1]);
                    mma16816(accp[mt][ng * 2 + 0], a_l[mt], b_h[0], b_h[1]);
                    mma16816(accp[mt][ng * 2 + 1], a_h[mt], b_h[2], b_h[3]);
                    mma16816(accp[mt][ng * 2 + 1], a_h[mt], b_l[2], b_l[3]);
                    mma16816(accp[mt][ng * 2 + 1], a_l[mt], b_h[2], b_h[3]);
                }
            }
        }

#pragma unroll
        for (int mt = 0; mt < 2; mt++) {
            int rl = wm * 32 + mt * 16 + (lane >> 2);
            float sc0 = scs[rl], sc1 = scs[rl + 8];
#pragma unroll
            for (int nt = 0; nt < 4; nt++) {
                acc[mt][nt][0] += sc0 * accp[mt][nt][0];
                acc[mt][nt][1] += sc0 * accp[mt][nt][1];
                acc[mt][nt][2] += sc1 * accp[mt][nt][2];
                acc[mt][nt][3] += sc1 * accp[mt][nt][3];
            }
        }
        __syncthreads();
    }

#pragma unroll
    for (int mt = 0; mt < 2; mt++) {
        int r0 = row0 + wm * 32 + mt * 16 + (lane >> 2);
#pragma unroll
        for (int nt = 0; nt < 4; nt++) {
            int c = col0 + wn * 32 + nt * 8 + (lane & 3) * 2;
#pragma unroll
            for (int rr = 0; rr < 2; rr++) {
                int s = r0 + rr * 8;
                *(float2*)&out[(size_t)s * D + c] =
                    make_float2(acc[mt][nt][rr * 2 + 0], acc[mt][nt][rr * 2 + 1]);
            }
        }
    }
}

// ---------------- launch ----------------------------------------------------------
extern "C" void kernel_launch(void* const* d_in, const int* in_sizes, int n_in,
                              void* d_out, int out_size) {
    const float* x          = (const float*)d_in[0];
    const float* Wq         = (const float*)d_in[1];
    const float* Wk         = (const float*)d_in[2];
    const float* Wv         = (const float*)d_in[3];
    const float* Wo         = (const float*)d_in[4];
    const float* bandwidth  = (const float*)d_in[5];
    const float* diag_scale = (const float*)d_in[6];
    const float* pos        = (const float*)d_in[7];
    const float* proj       = (const float*)d_in[8];
    const float* reg        = (const float*)d_in[9];
    const float* lam        = (const float*)d_in[10];
    float* out = (float*)d_out;

    static bool attr_done = false;
    if (!attr_done) {
        cudaFuncSetAttribute(qkv_tc, cudaFuncAttributeMaxDynamicSharedMemorySize, 71680);
        cudaFuncSetAttribute(wo_tc, cudaFuncAttributeMaxDynamicSharedMemorySize, 55808);
        cudaFuncSetAttribute(kmat_tc, cudaFuncAttributeMaxDynamicSharedMemorySize, 108544);
        cudaFuncSetAttribute(kapply_mma, cudaFuncAttributeMaxDynamicSharedMemorySize, 36864);
        attr_done = true;
    }

    const int NTOT = S * D + 4 * D * D;
    cvt_all<<<(NTOT + 255) / 256, 256>>>(x, Wq, Wk, Wv, Wo);

    qkv_tc<<<dim3(D / 128, S / 128, 3), 256, 71680>>>();
    norms_diag<<<(H * S * 32 + 255) / 256, 256>>>(diag_scale, reg, bandwidth);
    transpose_k<<<dim3(S / 32, DH / 32, H), dim3(32, 8)>>>();
    kmat_tc<<<dim3(S / 128, H), 256, 108544>>>(bandwidth);
    u_kernel<<<dim3(S / 256, H), 256>>>(pos, proj);

    // Richardson iteration 1 (alpha = 0 => r = v)
    utr_kernel<<<dim3(H, 32), 1024>>>();
    update_kernel<<<dim3(S / 16, H), 1024>>>(1);

    // iterations 2..5: utr fused into kapply epilogue
    for (int it = 1; it < 5; it++) {
        kapply_mma<<<dim3(S / 64, H), 256, 36864>>>(0, lam);
        update_kernel<<<dim3(S / 16, H), 1024>>>(0);
    }

    kapply_mma<<<dim3(S / 64, H), 256, 36864>>>(1, lam);
    wo_tc<<<dim3(D / 64, S / 128), 256, 55808>>>(out);
}

// round 14
// speedup vs baseline: 1.0371x; 1.0371x over previous
#include <cuda_runtime.h>
#include <cuda_fp16.h>
#include <math.h>
#include <cstdint>

#define H 16
#define S 2048
#define D 1024
#define DH 64
#define RANK 16

// ---------------- scratch (device globals; no allocation allowed) ----------------
__device__ float g_q[H * S * DH];
__device__ float g_k[H * S * DH];
__device__ float g_v[H * S * DH];
__device__ float g_alpha[H * S * DH];
__device__ __half g_alphaH[H * S * DH];
__device__ float g_r[H * S * DH];
__device__ __half g_ctxH[H * S * DH];   // normalized ctx = K'@alpha (hi)
__device__ __half g_ctxL[H * S * DH];   // normalized ctx (lo)
__device__ __half g_Kh[(size_t)H * S * S];       // 128 MB fp16 row-normalized kernel
__device__ float g_scale[H * S];                 // per-row scale exp(-dmin*inv)
__device__ float g_qn[H * S];
__device__ float g_kn[H * S];
__device__ float g_diagp[H * S];
__device__ float g_U[H * S * RANK];
__device__ float g_utr_part[16 * H * RANK * DH];   // 16 partial blocks (one per M tile)

// split fp16 operands
__device__ __half g_xh[S * D],  g_xl[S * D];
__device__ __half g_Wh[3 * D * D], g_Wl[3 * D * D];   // Wq, Wk, Wv
__device__ __half g_Woh[D * D], g_Wol[D * D];
__device__ __half g_qhh[H * S * DH], g_qll[H * S * DH];
__device__ __half g_khh[H * S * DH], g_kll[H * S * DH];
__device__ __half g_kTh[H * DH * S], g_kTl[H * DH * S];  // transposed k

__device__ __forceinline__ float softplusf(float x) {
    return (x > 20.f) ? x : log1pf(expf(x));
}

// ======================= HMMA helpers (mma.sync + ldmatrix) =======================
__device__ __forceinline__ uint32_t smem_u32(const void* p) {
    uint32_t a;
    asm("{ .reg .u64 t; cvta.to.shared.u64 t, %1; cvt.u32.u64 %0, t; }" : "=r"(a) : "l"(p));
    return a;
}
__device__ __forceinline__ void ldm_x4(uint32_t* r, uint32_t addr) {
    asm volatile("ldmatrix.sync.aligned.m8n8.x4.shared.b16 {%0,%1,%2,%3}, [%4];"
                 : "=r"(r[0]), "=r"(r[1]), "=r"(r[2]), "=r"(r[3]) : "r"(addr));
}
__device__ __forceinline__ void ldm_x4_trans(uint32_t* r, uint32_t addr) {
    asm volatile("ldmatrix.sync.aligned.m8n8.x4.trans.shared.b16 {%0,%1,%2,%3}, [%4];"
                 : "=r"(r[0]), "=r"(r[1]), "=r"(r[2]), "=r"(r[3]) : "r"(addr));
}
__device__ __forceinline__ void mma16816(float* c, const uint32_t* a, uint32_t b0, uint32_t b1) {
    asm volatile(
        "mma.sync.aligned.m16n8k16.row.col.f32.f16.f16.f32 "
        "{%0,%1,%2,%3}, {%4,%5,%6,%7}, {%8,%9}, {%0,%1,%2,%3};"
        : "+f"(c[0]), "+f"(c[1]), "+f"(c[2]), "+f"(c[3])
        : "r"(a[0]), "r"(a[1]), "r"(a[2]), "r"(a[3]), "r"(b0), "r"(b1));
}
__device__ __forceinline__ void cp_async16(uint32_t saddr, const void* gaddr) {
    asm volatile("cp.async.cg.shared.global [%0], [%1], 16;" :: "r"(saddr), "l"(gaddr) : "memory");
}

// ---------------- fp32 -> (hi, lo) fp16 split conversion (merged) -----------------
__global__ void cvt_all(const float* __restrict__ x, const float* __restrict__ wq,
                        const float* __restrict__ wk, const float* __restrict__ wv,
                        const float* __restrict__ wo) {
    int i = blockIdx.x * blockDim.x + threadIdx.x;
    const int NX = S * D, NW = D * D;
    const float* src;
    __half *hi, *lo;
    int off;
    if (i < NX)               { src = x;  hi = g_xh;           lo = g_xl;           off = i; }
    else if (i < NX + NW)     { src = wq; hi = g_Wh;           lo = g_Wl;           off = i - NX; }
    else if (i < NX + 2 * NW) { src = wk; hi = g_Wh + NW;      lo = g_Wl + NW;      off = i - NX - NW; }
    else if (i < NX + 3 * NW) { src = wv; hi = g_Wh + 2 * NW;  lo = g_Wl + 2 * NW;  off = i - NX - 2 * NW; }
    else if (i < NX + 4 * NW) { src = wo; hi = g_Woh;          lo = g_Wol;          off = i - NX - 3 * NW; }
    else return;
    float v = src[off];
    __half h = __float2half(v);
    hi[off] = h;
    lo[off] = __float2half(v - __half2float(h));
}

// ===== QKV split-fp16 tensor GEMM: C = x @ W_z, output heads layout + hi/lo =======
__global__ void __launch_bounds__(256) qkv_tc() {
    extern __shared__ __align__(16) char sm[];
    __half* Ah = (__half*)sm;                 // [128][72]
    __half* Alo = (__half*)(sm + 18432);
    __half* Bh = (__half*)(sm + 36864);       // [64][136]
    __half* Bl = (__half*)(sm + 54272);

    int tid = threadIdx.x, lane = tid & 31, wid = tid >> 5;
    int wm = wid >> 1, wn = wid & 1;
    int row0 = blockIdx.y * 128, col0 = blockIdx.x * 128;
    int which = blockIdx.z;
    const __half* Whp = g_Wh + (size_t)which * D * D;
    const __half* Wlp = g_Wl + (size_t)which * D * D;

    float acc[2][8][4];
#pragma unroll
    for (int i = 0; i < 2; i++)
#pragma unroll
        for (int j = 0; j < 8; j++)
#pragma unroll
            for (int l = 0; l < 4; l++) acc[i][j][l] = 0.f;

    uint32_t ah_b = smem_u32(Ah), al_b = smem_u32(Alo);
    uint32_t bh_b = smem_u32(Bh), bl_b = smem_u32(Bl);
    int lm = lane & 15, lh = lane >> 4;

    for (int k0 = 0; k0 < D; k0 += 64) {
#pragma unroll
        for (int e = 0; e < 4; e++) {
            int idx = tid + 256 * e;           // 0..1023
            int m = idx >> 3, c8 = idx & 7;
            *(uint4*)&Ah[m * 72 + c8 * 8]  = *(const uint4*)&g_xh[(size_t)(row0 + m) * D + k0 + c8 * 8];
            *(uint4*)&Alo[m * 72 + c8 * 8] = *(const uint4*)&g_xl[(size_t)(row0 + m) * D + k0 + c8 * 8];
            int kb = idx >> 4, c16 = idx & 15;
            *(uint4*)&Bh[kb * 136 + c16 * 8] = *(const uint4*)&Whp[(size_t)(k0 + kb) * D + col0 + c16 * 8];
            *(uint4*)&Bl[kb * 136 + c16 * 8] = *(const uint4*)&Wlp[(size_t)(k0 + kb) * D + col0 + c16 * 8];
        }
        __syncthreads();
#pragma unroll
        for (int kk = 0; kk < 64; kk += 16) {
            uint32_t a_h[2][4], a_l[2][4];
#pragma unroll
            for (int mt = 0; mt < 2; mt++) {
                ldm_x4(a_h[mt], ah_b + ((wm * 32 + mt * 16 + lm) * 72 + kk + lh * 8) * 2);
                ldm_x4(a_l[mt], al_b + ((wm * 32 + mt * 16 + lm) * 72 + kk + lh * 8) * 2);
            }
#pragma unroll
            for (int ng = 0; ng < 4; ng++) {
                uint32_t b_h[4], b_l[4];
                ldm_x4_trans(b_h, bh_b + ((kk + lm) * 136 + wn * 64 + ng * 16 + lh * 8) * 2);
                ldm_x4_trans(b_l, bl_b + ((kk + lm) * 136 + wn * 64 + ng * 16 + lh * 8) * 2);
#pragma unroll
                for (int mt = 0; mt < 2; mt++) {
                    mma16816(acc[mt][ng * 2 + 0], a_h[mt], b_h[0], b_h[1]);
                    mma16816(acc[mt][ng * 2 + 0], a_h[mt], b_l[0], b_l[1]);
                    mma16816(acc[mt][ng * 2 + 0], a_l[mt], b_h[0], b_h[1]);
                    mma16816(acc[mt][ng * 2 + 1], a_h[mt], b_h[2], b_h[3]);
                    mma16816(acc[mt][ng * 2 + 1], a_h[mt], b_l[2], b_l[3]);
                    mma16816(acc[mt][ng * 2 + 1], a_l[mt], b_h[2], b_h[3]);
                }
            }
        }
        __syncthreads();
    }

    float* outF = (which == 0) ? g_q : (which == 1) ? g_k : g_v;
    __half* oh = (which == 0) ? g_qhh : g_khh;
    __half* ol = (which == 0) ? g_qll : g_kll;
#pragma unroll
    for (int mt = 0; mt < 2; mt++) {
        int r0 = row0 + wm * 32 + mt * 16 + (lane >> 2);
#pragma unroll
        for (int nt = 0; nt < 8; nt++) {
            int c = col0 + wn * 64 + nt * 8 + (lane & 3) * 2;
            int hh = c >> 6, dh = c & 63;
#pragma unroll
            for (int rr = 0; rr < 2; rr++) {
                int s = r0 + rr * 8;
                float v0 = acc[mt][nt][rr * 2 + 0], v1 = acc[mt][nt][rr * 2 + 1];
                size_t gi = ((size_t)hh * S + s) * DH + dh;
                *(float2*)&outF[gi] = make_float2(v0, v1);
                if (which < 2) {
                    __half h0 = __float2half(v0), h1 = __float2half(v1);
                    *(__half2*)&oh[gi] = __halves2half2(h0, h1);
                    *(__half2*)&ol[gi] = __halves2half2(
                        __float2half(v0 - __half2float(h0)),
                        __float2half(v1 - __half2float(h1)));
                }
            }
        }
    }
}

// ---------------- fused: row norms of q,k + diag_p (one 16MB pass) ----------------
__global__ void norms_diag(const float* __restrict__ diag_scale,
                           const float* __restrict__ reg_p,
                           const float* __restrict__ bw_p) {
    int gw = (blockIdx.x * blockDim.x + threadIdx.x) >> 5;
    int lane = threadIdx.x & 31;
    if (gw >= H * S) return;
    const float* qp = g_q + (size_t)gw * DH;
    const float* kp = g_k + (size_t)gw * DH;
    float qa = qp[lane], qb = qp[lane + 32];
    float ka = kp[lane], kb = kp[lane + 32];
    float qn = qa * qa + qb * qb;
    float kn = ka * ka + kb * kb;
    float da = qa - ka, db = qb - kb;
    float dd = da * da + db * db;
#pragma unroll
    for (int o = 16; o > 0; o >>= 1) {
        qn += __shfl_xor_sync(0xffffffffu, qn, o);
        kn += __shfl_xor_sync(0xffffffffu, kn, o);
        dd += __shfl_xor_sync(0xffffffffu, dd, o);
    }
    if (lane == 0) {
        g_qn[gw] = qn;
        g_kn[gw] = kn;
        float bw = softplusf(bw_p[0]) + 1e-6f;
        float inv = 1.0f / (2.0f * bw * bw);
        float kd = __expf(-dd * inv);
        g_diagp[gw] = softplusf(kd) * diag_scale[gw / S] + reg_p[0];
    }
}

// ---------------- transpose k hi/lo: [h][s][dh] -> [h][dh][s] ----------------------
__global__ void transpose_k() {
    __shared__ __half t0[32][33];
    __shared__ __half t1[32][33];
    int h = blockIdx.z;
    int s0 = blockIdx.x * 32, d0 = blockIdx.y * 32;
    int tx = threadIdx.x, ty = threadIdx.y;   // 32 x 8
#pragma unroll
    for (int i = 0; i < 32; i += 8) {
        t0[ty + i][tx] = g_khh[((size_t)h * S + s0 + ty + i) * DH + d0 + tx];
        t1[ty + i][tx] = g_kll[((size_t)h * S + s0 + ty + i) * DH + d0 + tx];
    }
    __syncthreads();
#pragma unroll
    for (int i = 0; i < 32; i += 8) {
        g_kTh[((size_t)h * DH + d0 + ty + i) * S + s0 + tx] = t0[tx][ty + i];
        g_kTl[((size_t)h * DH + d0 + ty + i) * S + s0 + tx] = t1[tx][ty + i];
    }
}

// ===== fused kmat (FULL phase1, cp.async double-buffered B tiles) =================
__global__ void __launch_bounds__(256) kmat_tc(const float* __restrict__ bw_p) {
    extern __shared__ __align__(16) char sm[];
    __half* Qh = (__half*)sm;                 // [128][72] 18432
    __half* Ql = (__half*)(sm + 18432);       // 18432
    float* qn_s = (float*)(sm + 106496);      // 512
    float* kn_p0 = (float*)(sm + 107008);     // 512
    float* kn_p1 = (float*)(sm + 107520);     // 512
    unsigned* minv = (unsigned*)(sm + 108032);// 512   -> total 108544

    uint32_t base = smem_u32(sm);
    uint32_t bhB[2] = {base + 36864u, base + 71680u};
    uint32_t blB[2] = {base + 54272u, base + 89088u};
    uint32_t knB[2] = {base + 107008u, base + 107520u};
    float* kn_p[2] = {kn_p0, kn_p1};

    int tid = threadIdx.x, lane = tid & 31, wid = tid >> 5;
    int h = blockIdx.y, i0 = blockIdx.x * 128;
    float bw = softplusf(bw_p[0]) + 1e-6f;
    float inv = 1.0f / (2.0f * bw * bw);

#pragma unroll
    for (int e = 0; e < 4; e++) {
        int idx = tid + 256 * e;
        int m = idx >> 3, c8 = idx & 7;
        *(uint4*)&Qh[m * 72 + c8 * 8] = *(const uint4*)&g_qhh[((size_t)h * S + i0 + m) * DH + c8 * 8];
        *(uint4*)&Ql[m * 72 + c8 * 8] = *(const uint4*)&g_qll[((size_t)h * S + i0 + m) * DH + c8 * 8];
    }
    if (tid < 128) {
        qn_s[tid] = g_qn[h * S + i0 + tid];
        minv[tid] = 0x7F800000u;
    }
    __syncthreads();

    uint32_t qh_b = smem_u32(Qh), ql_b = smem_u32(Ql);
    int lm = lane & 15, lh = lane >> 4;

    const __half* kThp = g_kTh + (size_t)h * DH * S;
    const __half* kTlp = g_kTl + (size_t)h * DH * S;

    float rmin[16];
#pragma unroll
    for (int i = 0; i < 16; i++) rmin[i] = 3.4e38f;

    // ---------------- phase 1: hi-only dist over ALL columns (pipelined) ----------
    {
#pragma unroll
        for (int e = 0; e < 4; e++) {
            int idx = tid + 256 * e;
            int kb = idx >> 4, c16 = idx & 15;
            cp_async16(bhB[0] + (uint32_t)(kb * 272 + c16 * 16),
                       kThp + (size_t)kb * S + c16 * 8);
        }
        if (tid < 32)
            cp_async16(knB[0] + (uint32_t)(tid * 16), &g_kn[h * S + tid * 4]);
        asm volatile("cp.async.commit_group;" ::: "memory");
    }

    for (int c = 0; c < 16; c++) {
        int st = c & 1;
        if (c < 15) {
            int j0n = (c + 1) * 128;
            int sn = st ^ 1;
#pragma unroll
            for (int e = 0; e < 4; e++) {
                int idx = tid + 256 * e;
                int kb = idx >> 4, c16 = idx & 15;
                cp_async16(bhB[sn] + (uint32_t)(kb * 272 + c16 * 16),
                           kThp + (size_t)kb * S + j0n + c16 * 8);
            }
            if (tid < 32)
                cp_async16(knB[sn] + (uint32_t)(tid * 16), &g_kn[h * S + j0n + tid * 4]);
            asm volatile("cp.async.commit_group;" ::: "memory");
            asm volatile("cp.async.wait_group 1;" ::: "memory");
        } else {
            asm volatile("cp.async.wait_group 0;" ::: "memory");
        }
        __syncthreads();

        uint32_t bf[4][4];
#pragma unroll
        for (int k4 = 0; k4 < 4; k4++)
            ldm_x4_trans(bf[k4], bhB[st] + (uint32_t)(((k4 * 16 + lm) * 136 + wid * 16 + lh * 8) * 2));

        const float* kns = kn_p[st];
#pragma unroll
        for (int mt = 0; mt < 8; mt++) {
            float a0[4] = {0.f, 0.f, 0.f, 0.f}, a1[4] = {0.f, 0.f, 0.f, 0.f};
#pragma unroll
            for (int k4 = 0; k4 < 4; k4++) {
                uint32_t a[4];
                ldm_x4(a, qh_b + ((mt * 16 + lm) * 72 + k4 * 16 + lh * 8) * 2);
                mma16816(a0, a, bf[k4][0], bf[k4][1]);
                mma16816(a1, a, bf[k4][2], bf[k4][3]);
            }
            int r = mt * 16 + (lane >> 2);
            float qn0 = qn_s[r], qn1 = qn_s[r + 8];
            int cb = wid * 16 + (lane & 3) * 2;
            float kn0 = kns[cb], kn1 = kns[cb + 1], kn8 = kns[cb + 8], kn9 = kns[cb + 9];
            float d0 = fminf(fminf(qn0 + kn0 - 2.f * a0[0], qn0 + kn1 - 2.f * a0[1]),
                             fminf(qn0 + kn8 - 2.f * a1[0], qn0 + kn9 - 2.f * a1[1]));
            float d1 = fminf(fminf(qn1 + kn0 - 2.f * a0[2], qn1 + kn1 - 2.f * a0[3]),
                             fminf(qn1 + kn8 - 2.f * a1[2], qn1 + kn9 - 2.f * a1[3]));
            rmin[mt * 2] = fminf(rmin[mt * 2], d0);
            rmin[mt * 2 + 1] = fminf(rmin[mt * 2 + 1], d1);
        }
        __syncthreads();
    }
#pragma unroll
    for (int i = 0; i < 16; i++) {
        rmin[i] = fminf(rmin[i], __shfl_xor_sync(0xffffffffu, rmin[i], 1));
        rmin[i] = fminf(rmin[i], __shfl_xor_sync(0xffffffffu, rmin[i], 2));
    }
    if ((lane & 3) == 0) {
#pragma unroll
        for (int mt = 0; mt < 8; mt++) {
            atomicMin(&minv[mt * 16 + (lane >> 2)], __float_as_uint(fmaxf(rmin[mt * 2], 0.f)));
            atomicMin(&minv[mt * 16 + (lane >> 2) + 8], __float_as_uint(fmaxf(rmin[mt * 2 + 1], 0.f)));
        }
    }
    __syncthreads();
    if (tid < 128)
        g_scale[h * S + i0 + tid] = __expf(-__uint_as_float(minv[tid]) * inv);

    // ---------------- phase 2: split dist, exp -> Kh fp16 (pipelined) -------------
    {
#pragma unroll
        for (int e = 0; e < 4; e++) {
            int idx = tid + 256 * e;
            int kb = idx >> 4, c16 = idx & 15;
            cp_async16(bhB[0] + (uint32_t)(kb * 272 + c16 * 16),
                       kThp + (size_t)kb * S + c16 * 8);
            cp_async16(blB[0] + (uint32_t)(kb * 272 + c16 * 16),
                       kTlp + (size_t)kb * S + c16 * 8);
        }
        if (tid < 32)
            cp_async16(knB[0] + (uint32_t)(tid * 16), &g_kn[h * S + tid * 4]);
        asm volatile("cp.async.commit_group;" ::: "memory");
    }

    for (int c = 0; c < 16; c++) {
        int st = c & 1;
        int j0 = c * 128;
        if (c < 15) {
            int j0n = (c + 1) * 128;
            int sn = st ^ 1;
#pragma unroll
            for (int e = 0; e < 4; e++) {
                int idx = tid + 256 * e;
                int kb = idx >> 4, c16 = idx & 15;
                cp_async16(bhB[sn] + (uint32_t)(kb * 272 + c16 * 16),
                           kThp + (size_t)kb * S + j0n + c16 * 8);
                cp_async16(blB[sn] + (uint32_t)(kb * 272 + c16 * 16),
                           kTlp + (size_t)kb * S + j0n + c16 * 8);
            }
            if (tid < 32)
                cp_async16(knB[sn] + (uint32_t)(tid * 16), &g_kn[h * S + j0n + tid * 4]);
            asm volatile("cp.async.commit_group;" ::: "memory");
            asm volatile("cp.async.wait_group 1;" ::: "memory");
        } else {
            asm volatile("cp.async.wait_group 0;" ::: "memory");
        }
        __syncthreads();

        uint32_t bfh[4][4], bfl[4][4];
#pragma unroll
        for (int k4 = 0; k4 < 4; k4++) {
            ldm_x4_trans(bfh[k4], bhB[st] + (uint32_t)(((k4 * 16 + lm) * 136 + wid * 16 + lh * 8) * 2));
            ldm_x4_trans(bfl[k4], blB[st] + (uint32_t)(((k4 * 16 + lm) * 136 + wid * 16 + lh * 8) * 2));
        }

        const float* kns = kn_p[st];
#pragma unroll
        for (int mt = 0; mt < 8; mt++) {
            float a0[4] = {0.f, 0.f, 0.f, 0.f}, a1[4] = {0.f, 0.f, 0.f, 0.f};
#pragma unroll
            for (int k4 = 0; k4 < 4; k4++) {
                uint32_t ah[4], al[4];
                ldm_x4(ah, qh_b + ((mt * 16 + lm) * 72 + k4 * 16 + lh * 8) * 2);
                ldm_x4(al, ql_b + ((mt * 16 + lm) * 72 + k4 * 16 + lh * 8) * 2);
                mma16816(a0, ah, bfh[k4][0], bfh[k4][1]);
                mma16816(a0, ah, bfl[k4][0], bfl[k4][1]);
                mma16816(a0, al, bfh[k4][0], bfh[k4][1]);
                mma16816(a1, ah, bfh[k4][2], bfh[k4][3]);
                mma16816(a1, ah, bfl[k4][2], bfl[k4][3]);
                mma16816(a1, al, bfh[k4][2], bfh[k4][3]);
            }
            int r = mt * 16 + (lane >> 2);
            float qn0 = qn_s[r], qn1 = qn_s[r + 8];
            float dm0 = __uint_as_float(minv[r]), dm1 = __uint_as_float(minv[r + 8]);
            int cb = wid * 16 + (lane & 3) * 2;
            float kn0 = kns[cb], kn1 = kns[cb + 1], kn8 = kns[cb + 8], kn9 = kns[cb + 9];
            float e00 = __expf((dm0 - fmaxf(qn0 + kn0 - 2.f * a0[0], 0.f)) * inv);
            float e01 = __expf((dm0 - fmaxf(qn0 + kn1 - 2.f * a0[1], 0.f)) * inv);
            float e10 = __expf((dm1 - fmaxf(qn1 + kn0 - 2.f * a0[2], 0.f)) * inv);
            float e11 = __expf((dm1 - fmaxf(qn1 + kn1 - 2.f * a0[3], 0.f)) * inv);
            float f00 = __expf((dm0 - fmaxf(qn0 + kn8 - 2.f * a1[0], 0.f)) * inv);
            float f01 = __expf((dm0 - fmaxf(qn0 + kn9 - 2.f * a1[1], 0.f)) * inv);
            float f10 = __expf((dm1 - fmaxf(qn1 + kn8 - 2.f * a1[2], 0.f)) * inv);
            float f11 = __expf((dm1 - fmaxf(qn1 + kn9 - 2.f * a1[3], 0.f)) * inv);
            __half* Kp0 = &g_Kh[((size_t)(h * S + i0 + r)) * S + j0 + cb];
            __half* Kp1 = Kp0 + (size_t)8 * S;
            *(__half2*)Kp0 = __halves2half2(__float2half(e00), __float2half(e01));
            *(__half2*)(Kp0 + 8) = __halves2half2(__float2half(f00), __float2half(f01));
            *(__half2*)Kp1 = __halves2half2(__float2half(e10), __float2half(e11));
            *(__half2*)(Kp1 + 8) = __halves2half2(__float2half(f10), __float2half(f11));
        }
        __syncthreads();
    }
}

// ---------------- U[h,s,r] = sum_rp pos[s,rp] * proj[h,rp,r] ----------------------
__global__ void u_kernel(const float* __restrict__ pos, const float* __restrict__ proj) {
    __shared__ float pr[RANK][RANK];
    int h = blockIdx.y;
    int tid = threadIdx.x;
    pr[tid >> 4][tid & 15] = proj[h * RANK * RANK + tid];
    __syncthreads();
    int s = blockIdx.x * 256 + tid;
    float pe[RANK];
#pragma unroll
    for (int r = 0; r < RANK; r++) pe[r] = pos[(size_t)s * RANK + r];
#pragma unroll
    for (int r = 0; r < RANK; r++) {
        float acc = 0.f;
#pragma unroll
        for (int rp = 0; rp < RANK; rp++) acc += pe[rp] * pr[rp][r];
        g_U[((size_t)h * S + s) * RANK + r] = acc;
    }
}

// == HMMA K@alpha (2-stage cp.async) + FUSED U^T r partial reduction ===============
// mode0: r = v - scale*K'a - lam*a, writes g_r AND utr_part[blockIdx.x]
// mode1: store NORMALIZED K'a hi/lo
__global__ void __launch_bounds__(256) kapply_mma(int mode, const float* __restrict__ lam_p) {
    extern __shared__ __align__(16) char sm[];
    uint32_t base = smem_u32(sm);
    uint32_t ksb0 = base, ksb1 = base + 18432;
    uint32_t alb0 = base + 36864, alb1 = base + 46080;

    int tid = threadIdx.x, wid = tid >> 5, lane = tid & 31;
    int h = blockIdx.y;
    int s0 = blockIdx.x * 128;

    const __half* Kb = g_Kh + ((size_t)h * S + s0) * S;
    const __half* Ab = g_alphaH + (size_t)h * S * DH;

    float acc[8][4];
#pragma unroll
    for (int i = 0; i < 8; i++)
#pragma unroll
        for (int j = 0; j < 4; j++) acc[i][j] = 0.f;

    int lm = lane & 15, lh = lane >> 4;
    int mA = tid >> 3, c8A = tid & 7;

    {
        int t0 = 0;
#pragma unroll
        for (int e = 0; e < 4; e++) {
            int m = mA + 32 * e;
            cp_async16(ksb0 + (uint32_t)(m * 144 + c8A * 16), Kb + (size_t)m * S + t0 + c8A * 8);
        }
#pragma unroll
        for (int e = 0; e < 2; e++) {
            int t = mA + 32 * e;
            cp_async16(alb0 + (uint32_t)(t * 144 + c8A * 16), Ab + (size_t)(t0 + t) * DH + c8A * 8);
        }
        asm volatile("cp.async.commit_group;" ::: "memory");
    }

    for (int c = 0; c < 32; c++) {
        uint32_t ks_cur = (c & 1) ? ksb1 : ksb0;
        uint32_t al_cur = (c & 1) ? alb1 : alb0;
        if (c < 31) {
            uint32_t ks_nxt = (c & 1) ? ksb0 : ksb1;
            uint32_t al_nxt = (c & 1) ? alb0 : alb1;
            int t0 = (c + 1) * 64;
#pragma unroll
            for (int e = 0; e < 4; e++) {
                int m = mA + 32 * e;
                cp_async16(ks_nxt + (uint32_t)(m * 144 + c8A * 16), Kb + (size_t)m * S + t0 + c8A * 8);
            }
#pragma unroll
            for (int e = 0; e < 2; e++) {
                int t = mA + 32 * e;
                cp_async16(al_nxt + (uint32_t)(t * 144 + c8A * 16), Ab + (size_t)(t0 + t) * DH + c8A * 8);
            }
            asm volatile("cp.async.commit_group;" ::: "memory");
            asm volatile("cp.async.wait_group 1;" ::: "memory");
        } else {
            asm volatile("cp.async.wait_group 0;" ::: "memory");
        }
        __syncthreads();

#pragma unroll
        for (int kk = 0; kk < 64; kk += 16) {
            uint32_t a[4];
            ldm_x4(a, ks_cur + (uint32_t)(((wid * 16 + lm) * 72 + kk + lh * 8) * 2));
#pragma unroll
            for (int nt = 0; nt < 4; nt++) {
                uint32_t b[4];
                ldm_x4_trans(b, al_cur + (uint32_t)(((kk + lm) * 72 + nt * 16 + lh * 8) * 2));
                mma16816(acc[nt * 2 + 0], a, b[0], b[1]);
                mma16816(acc[nt * 2 + 1], a, b[2], b[3]);
            }
        }
        __syncthreads();
    }

    int rbase = s0 + wid * 16 + (lane >> 2);
    float sc0 = g_scale[h * S + rbase];
    float sc1 = g_scale[h * S + rbase + 8];

    if (mode == 0) {
        float lam = softplusf(lam_p[0]);
        // stage r into smem for fused U^T r; buffers are dead after the loop
        float* rsm = (float*)sm;              // [128][65] = 33280 B
        float* Usm = (float*)(sm + 33280);    // [128][16] =  8192 B
#pragma unroll
        for (int e = 0; e < 8; e++) {
            int idx = tid + 256 * e;          // 0..2047
            int m = idx >> 4, rr = idx & 15;
            Usm[m * 16 + rr] = g_U[((size_t)h * S + s0 + m) * RANK + rr];
        }
        int rl0 = wid * 16 + (lane >> 2);
#pragma unroll
        for (int nt = 0; nt < 8; nt++) {
            int col = nt * 8 + (lane & 3) * 2;
            size_t g0 = ((size_t)h * S + rbase) * DH + col;
            size_t g1 = g0 + 8 * DH;
            float2 v0 = *(const float2*)&g_v[g0];
            float2 v1 = *(const float2*)&g_v[g1];
            float2 a0 = *(const float2*)&g_alpha[g0];
            float2 a1 = *(const float2*)&g_alpha[g1];
            float r00 = v0.x - sc0 * acc[nt][0] - lam * a0.x;
            float r01 = v0.y - sc0 * acc[nt][1] - lam * a0.y;
            float r10 = v1.x - sc1 * acc[nt][2] - lam * a1.x;
            float r11 = v1.y - sc1 * acc[nt][3] - lam * a1.y;
            *(float2*)&g_r[g0] = make_float2(r00, r01);
            *(float2*)&g_r[g1] = make_float2(r10, r11);
            rsm[rl0 * 65 + col] = r00;
            rsm[rl0 * 65 + col + 1] = r01;
            rsm[(rl0 + 8) * 65 + col] = r10;
            rsm[(rl0 + 8) * 65 + col + 1] = r11;
        }
        __syncthreads();

        // fused partial U^T r over this CTA's 128 rows
        int d = tid & 63, rg = tid >> 6;      // rg in 0..3
        float a4[4] = {0.f, 0.f, 0.f, 0.f};
        for (int s = 0; s < 128; s++) {
            float rv = rsm[s * 65 + d];
            a4[0] += Usm[s * 16 + rg] * rv;
            a4[1] += Usm[s * 16 + rg + 4] * rv;
            a4[2] += Usm[s * 16 + rg + 8] * rv;
            a4[3] += Usm[s * 16 + rg + 12] * rv;
        }
        int part = blockIdx.x;
#pragma unroll
        for (int i = 0; i < 4; i++)
            g_utr_part[(((size_t)part * H + h) * RANK + (rg + 4 * i)) * DH + d] = a4[i];
    } else {
#pragma unroll
        for (int nt = 0; nt < 8; nt++) {
            int col = nt * 8 + (lane & 3) * 2;
            size_t g0 = ((size_t)h * S + rbase) * DH + col;
            size_t g1 = g0 + 8 * DH;
            float c00 = acc[nt][0], c01 = acc[nt][1];
            float c10 = acc[nt][2], c11 = acc[nt][3];
            __half h00 = __float2half(c00), h01 = __float2half(c01);
            __half h10 = __float2half(c10), h11 = __float2half(c11);
            *(__half2*)&g_ctxH[g0] = __halves2half2(h00, h01);
            *(__half2*)&g_ctxH[g1] = __halves2half2(h10, h11);
            *(__half2*)&g_ctxL[g0] = __halves2half2(__float2half(c00 - __half2float(h00)),
                                                    __float2half(c01 - __half2float(h01)));
            *(__half2*)&g_ctxL[g1] = __halves2half2(__float2half(c10 - __half2float(h10)),
                                                    __float2half(c11 - __half2float(h11)));
        }
    }
}

// ------- utr_part[p,h,r,d] = sum_{s in part} U[h,s,r] * v[h,s,d] (iter 1 only) ----
__global__ void utr_kernel() {
    int h = blockIdx.x;
    int part = blockIdx.y;     // 0..15
    int tid = threadIdx.x;
    int d = tid & 63, rr = tid >> 6;
    const float* Ub = g_U + (size_t)h * S * RANK;
    const float* rb = g_v + (size_t)h * S * DH;
    int s0 = part * (S / 16);
    float a0 = 0, a1 = 0, a2 = 0, a3 = 0;
    for (int s = s0; s < s0 + S / 16; s += 4) {
        a0 += Ub[(s + 0) * RANK + rr] * rb[(size_t)(s + 0) * DH + d];
        a1 += Ub[(s + 1) * RANK + rr] * rb[(size_t)(s + 1) * DH + d];
        a2 += Ub[(s + 2) * RANK + rr] * rb[(size_t)(s + 2) * DH + d];
        a3 += Ub[(s + 3) * RANK + rr] * rb[(size_t)(s + 3) * DH + d];
    }
    g_utr_part[((part * H + h) * RANK + rr) * DH + d] = (a0 + a1) + (a2 + a3);
}

// ---------------- alpha = prev + r*diag_p + U @ utr; emit fp16 mirror -------------
__global__ void update_kernel(int first) {
    __shared__ float ut[RANK][DH];
    __shared__ float Us[16][RANK];
    int h = blockIdx.y;
    int tid = threadIdx.x;
    {
        float sum = 0.f;
#pragma unroll
        for (int p = 0; p < 16; p++) sum += g_utr_part[(p * H + h) * RANK * DH + tid];
        ut[tid >> 6][tid & 63] = sum;
    }
    int s0 = blockIdx.x * 16;
    if (tid < 16 * RANK)
        Us[tid >> 4][tid & 15] = g_U[((size_t)h * S + s0 + (tid >> 4)) * RANK + (tid & 15)];
    __syncthreads();

    int sl = tid >> 6;
    int d = tid & 63;
    int s = s0 + sl;
    size_t idx = ((size_t)h * S + s) * DH + d;
    float acc = 0.f;
#pragma unroll
    for (int r2 = 0; r2 < RANK; r2++) acc += Us[sl][r2] * ut[r2][d];
    float rv = first ? g_v[idx] : g_r[idx];
    float prev = first ? 0.f : g_alpha[idx];
    float na = prev + rv * g_diagp[h * S + s] + acc;
    g_alpha[idx] = na;
    g_alphaH[idx] = __float2half(na);
}

// == output GEMM (128x64 tiles): out = (scale ⊙ ctxN)_flat @ Wo ====================
__global__ void __launch_bounds__(256) wo_tc(float* __restrict__ out) {
    extern __shared__ __align__(16) char sm[];
    __half* Ah = (__half*)sm;                 // [128][72]
    __half* Alo = (__half*)(sm + 18432);
    __half* Bh = (__half*)(sm + 36864);       // [64][72]
    __half* Bl = (__half*)(sm + 46080);
    float* scs = (float*)(sm + 55296);        // 128 row scales

    int tid = threadIdx.x, lane = tid & 31, wid = tid >> 5;
    int wm = wid >> 1, wn = wid & 1;
    int row0 = blockIdx.y * 128, col0 = blockIdx.x * 64;

    float acc[2][4][4];
#pragma unroll
    for (int i = 0; i < 2; i++)
#pragma unroll
        for (int j = 0; j < 4; j++)
#pragma unroll
            for (int l = 0; l < 4; l++) acc[i][j][l] = 0.f;

    uint32_t ah_b = smem_u32(Ah), al_b = smem_u32(Alo);
    uint32_t bh_b = smem_u32(Bh), bl_b = smem_u32(Bl);
    int lm = lane & 15, lh = lane >> 4;

    for (int ck = 0; ck < 16; ck++) {
        int k0 = ck * 64;
#pragma unroll
        for (int e = 0; e < 4; e++) {
            int idx = tid + 256 * e;
            int m = idx >> 3, c8 = idx & 7;
            *(uint4*)&Ah[m * 72 + c8 * 8]  = *(const uint4*)&g_ctxH[((size_t)ck * S + row0 + m) * DH + c8 * 8];
            *(uint4*)&Alo[m * 72 + c8 * 8] = *(const uint4*)&g_ctxL[((size_t)ck * S + row0 + m) * DH + c8 * 8];
        }
#pragma unroll
        for (int e = 0; e < 2; e++) {
            int idx = tid + 256 * e;
            int kb = idx >> 3, c8 = idx & 7;
            *(uint4*)&Bh[kb * 72 + c8 * 8] = *(const uint4*)&g_Woh[(size_t)(k0 + kb) * D + col0 + c8 * 8];
            *(uint4*)&Bl[kb * 72 + c8 * 8] = *(const uint4*)&g_Wol[(size_t)(k0 + kb) * D + col0 + c8 * 8];
        }
        if (tid < 128) scs[tid] = g_scale[ck * S + row0 + tid];
        __syncthreads();

        float accp[2][4][4];
#pragma unroll
        for (int i = 0; i < 2; i++)
#pragma unroll
            for (int j = 0; j < 4; j++)
#pragma unroll
                for (int l = 0; l < 4; l++) accp[i][j][l] = 0.f;

#pragma unroll
        for (int kk = 0; kk < 64; kk += 16) {
            uint32_t a_h[2][4], a_l[2][4];
#pragma unroll
            for (int mt = 0; mt < 2; mt++) {
                ldm_x4(a_h[mt], ah_b + ((wm * 32 + mt * 16 + lm) * 72 + kk + lh * 8) * 2);
                ldm_x4(a_l[mt], al_b + ((wm * 32 + mt * 16 + lm) * 72 + kk + lh * 8) * 2);
            }
#pragma unroll
            for (int ng = 0; ng < 2; ng++) {
                uint32_t b_h[4], b_l[4];
                ldm_x4_trans(b_h, bh_b + ((kk + lm) * 72 + wn * 32 + ng * 16 + lh * 8) * 2);
                ldm_x4_trans(b_l, bl_b + ((kk + lm) * 72 + wn * 32 + ng * 16 + lh * 8) * 2);
#pragma unroll
                for (int mt = 0; mt < 2; mt++) {
                    mma16816(accp[mt][ng * 2 + 0], a_h[mt], b_h[0], b_h[1]);
                    mma16816(accp[mt][ng * 2 + 0], a_h[mt], b_l[0], b_l[1]);
                    mma16816(accp[mt][ng * 2 + 0], a_l[mt], b_h[0], b_h[1]);
                    mma16816(accp[mt][ng * 2 + 1], a_h[mt], b_h[2], b_h[3]);
                    mma16816(accp[mt][ng * 2 + 1], a_h[mt], b_l[2], b_l[3]);
                    mma16816(accp[mt][ng * 2 + 1], a_l[mt], b_h[2], b_h[3]);
                }
            }
        }

#pragma unroll
        for (int mt = 0; mt < 2; mt++) {
            int rl = wm * 32 + mt * 16 + (lane >> 2);
            float sc0 = scs[rl], sc1 = scs[rl + 8];
#pragma unroll
            for (int nt = 0; nt < 4; nt++) {
                acc[mt][nt][0] += sc0 * accp[mt][nt][0];
                acc[mt][nt][1] += sc0 * accp[mt][nt][1];
                acc[mt][nt][2] += sc1 * accp[mt][nt][2];
                acc[mt][nt][3] += sc1 * accp[mt][nt][3];
            }
        }
        __syncthreads();
    }

#pragma unroll
    for (int mt = 0; mt < 2; mt++) {
        int r0 = row0 + wm * 32 + mt * 16 + (lane >> 2);
#pragma unroll
        for (int nt = 0; nt < 4; nt++) {
            int c = col0 + wn * 32 + nt * 8 + (lane & 3) * 2;
#pragma unroll
            for (int rr = 0; rr < 2; rr++) {
                int s = r0 + rr * 8;
                *(float2*)&out[(size_t)s * D + c] =
                    make_float2(acc[mt][nt][rr * 2 + 0], acc[mt][nt][rr * 2 + 1]);
            }
        }
    }
}

// ---------------- launch ----------------------------------------------------------
extern "C" void kernel_launch(void* const* d_in, const int* in_sizes, int n_in,
                              void* d_out, int out_size) {
    const float* x          = (const float*)d_in[0];
    const float* Wq         = (const float*)d_in[1];
    const float* Wk         = (const float*)d_in[2];
    const float* Wv         = (const float*)d_in[3];
    const float* Wo         = (const float*)d_in[4];
    const float* bandwidth  = (const float*)d_in[5];
    const float* diag_scale = (const float*)d_in[6];
    const float* pos        = (const float*)d_in[7];
    const float* proj       = (const float*)d_in[8];
    const float* reg        = (const float*)d_in[9];
    const float* lam        = (const float*)d_in[10];
    float* out = (float*)d_out;

    static bool attr_done = false;
    if (!attr_done) {
        cudaFuncSetAttribute(qkv_tc, cudaFuncAttributeMaxDynamicSharedMemorySize, 71680);
        cudaFuncSetAttribute(wo_tc, cudaFuncAttributeMaxDynamicSharedMemorySize, 55808);
        cudaFuncSetAttribute(kmat_tc, cudaFuncAttributeMaxDynamicSharedMemorySize, 108544);
        cudaFuncSetAttribute(kapply_mma, cudaFuncAttributeMaxDynamicSharedMemorySize, 55296);
        attr_done = true;
    }

    const int NTOT = S * D + 4 * D * D;
    cvt_all<<<(NTOT + 255) / 256, 256>>>(x, Wq, Wk, Wv, Wo);

    qkv_tc<<<dim3(D / 128, S / 128, 3), 256, 71680>>>();
    norms_diag<<<(H * S * 32 + 255) / 256, 256>>>(diag_scale, reg, bandwidth);
    transpose_k<<<dim3(S / 32, DH / 32, H), dim3(32, 8)>>>();
    kmat_tc<<<dim3(S / 128, H), 256, 108544>>>(bandwidth);
    u_kernel<<<dim3(S / 256, H), 256>>>(pos, proj);

    // Richardson iteration 1 (alpha = 0 => r = v)
    utr_kernel<<<dim3(H, 16), 1024>>>();
    update_kernel<<<dim3(S / 16, H), 1024>>>(1);

    // iterations 2..5: utr fused into kapply epilogue
    for (int it = 1; it < 5; it++) {
        kapply_mma<<<dim3(S / 128, H), 256, 55296>>>(0, lam);
        update_kernel<<<dim3(S / 16, H), 1024>>>(0);
    }

    kapply_mma<<<dim3(S / 128, H), 256, 55296>>>(1, lam);
    wo_tc<<<dim3(D / 64, S / 128), 256, 55808>>>(out);
}

// round 15
// speedup vs baseline: 1.0508x; 1.0132x over previous
#include <cuda_runtime.h>
#include <cuda_fp16.h>
#include <math.h>
#include <cstdint>

#define H 16
#define S 2048
#define D 1024
#define DH 64
#define RANK 16

// ---- tcgen05 availability: only in arch-specific (sm_103a/sm_100a) device passes
#if defined(__CUDA_ARCH__) && (defined(__CUDA_ARCH_FEAT_SM103_ALL) || \
    defined(__CUDA_ARCH_FEAT_SM100_ALL) || defined(__CUDA_ARCH_FEAT_SM101_ALL) || \
    (defined(__CUDA_ARCH_SPECIFIC__) && (__CUDA_ARCH_SPECIFIC__ >= 1000)))
#define HAS_TC 1
#else
#define HAS_TC 0
#endif

// ---------------- scratch (device globals; no allocation allowed) ----------------
__device__ float g_q[H * S * DH];
__device__ float g_k[H * S * DH];
__device__ float g_v[H * S * DH];
__device__ float g_alpha[H * S * DH];
__device__ __half g_alphaH[H * S * DH];
__device__ __half g_alphaT[H * DH * S];          // transposed fp16 alpha (tcgen05 B op)
__device__ float g_r[H * S * DH];
__device__ __half g_ctxH[H * S * DH];   // normalized ctx = K'@alpha (hi)
__device__ __half g_ctxL[H * S * DH];   // normalized ctx (lo)
__device__ __half g_Kh[(size_t)H * S * S];       // 128 MB fp16 row-normalized kernel
__device__ float g_scale[H * S];                 // per-row scale exp(-dmin*inv)
__device__ float g_qn[H * S];
__device__ float g_kn[H * S];
__device__ float g_diagp[H * S];
__device__ float g_U[H * S * RANK];
__device__ float g_utr_part[16 * H * RANK * DH];   // 16 partial blocks (one per M tile)

// split fp16 operands
__device__ __half g_xh[S * D],  g_xl[S * D];
__device__ __half g_Wh[3 * D * D], g_Wl[3 * D * D];   // Wq, Wk, Wv
__device__ __half g_Woh[D * D], g_Wol[D * D];
__device__ __half g_qhh[H * S * DH], g_qll[H * S * DH];
__device__ __half g_khh[H * S * DH], g_kll[H * S * DH];
__device__ __half g_kTh[H * DH * S], g_kTl[H * DH * S];  // transposed k

__device__ __forceinline__ float softplusf(float x) {
    return (x > 20.f) ? x : log1pf(expf(x));
}

// ======================= HMMA helpers (mma.sync + ldmatrix) =======================
__device__ __forceinline__ uint32_t smem_u32(const void* p) {
    uint32_t a;
    asm("{ .reg .u64 t; cvta.to.shared.u64 t, %1; cvt.u32.u64 %0, t; }" : "=r"(a) : "l"(p));
    return a;
}
__device__ __forceinline__ void ldm_x4(uint32_t* r, uint32_t addr) {
    asm volatile("ldmatrix.sync.aligned.m8n8.x4.shared.b16 {%0,%1,%2,%3}, [%4];"
                 : "=r"(r[0]), "=r"(r[1]), "=r"(r[2]), "=r"(r[3]) : "r"(addr));
}
__device__ __forceinline__ void ldm_x4_trans(uint32_t* r, uint32_t addr) {
    asm volatile("ldmatrix.sync.aligned.m8n8.x4.trans.shared.b16 {%0,%1,%2,%3}, [%4];"
                 : "=r"(r[0]), "=r"(r[1]), "=r"(r[2]), "=r"(r[3]) : "r"(addr));
}
__device__ __forceinline__ void mma16816(float* c, const uint32_t* a, uint32_t b0, uint32_t b1) {
    asm volatile(
        "mma.sync.aligned.m16n8k16.row.col.f32.f16.f16.f32 "
        "{%0,%1,%2,%3}, {%4,%5,%6,%7}, {%8,%9}, {%0,%1,%2,%3};"
        : "+f"(c[0]), "+f"(c[1]), "+f"(c[2]), "+f"(c[3])
        : "r"(a[0]), "r"(a[1]), "r"(a[2]), "r"(a[3]), "r"(b0), "r"(b1));
}
__device__ __forceinline__ void cp_async16(uint32_t saddr, const void* gaddr) {
    asm volatile("cp.async.cg.shared.global [%0], [%1], 16;" :: "r"(saddr), "l"(gaddr) : "memory");
}

#if HAS_TC
// ======================= tcgen05 helpers (sm_103a cubin pass only) ================
#define SW128(o) ((o) ^ (((o) >> 3) & 0x70))
static constexpr uint64_t DESC_BASE_SW128 =
    (uint64_t(2) << 61) | (uint64_t(1) << 46) | (uint64_t(64) << 32) | (uint64_t(1) << 16);
__device__ __forceinline__ uint64_t make_desc(uint32_t addr) {
    return DESC_BASE_SW128 | ((uint64_t)(addr >> 4) & 0x3FFF);
}
// idesc kind::f16: dtype F32, atype=btype=FP16, N=64, M=128
#define IDESC_KA ((1u << 4) | ((64u / 8u) << 17) | ((128u / 16u) << 24))
__device__ __forceinline__ uint32_t elect_one() {
    uint32_t p;
    asm volatile("{ .reg .pred p; elect.sync _|p, 0xFFFFFFFF; selp.b32 %0, 1, 0, p; }" : "=r"(p));
    return p;
}
__device__ __forceinline__ void mbar_wait(uint32_t mb, uint32_t parity) {
    asm volatile(
        "{\n\t.reg .pred P1;\n\t"
        "W_%=:\n\t"
        "mbarrier.try_wait.parity.acquire.cta.shared::cta.b64 P1, [%0], %1, 0x989680;\n\t"
        "@P1 bra.uni D_%=;\n\t"
        "bra.uni W_%=;\n\t"
        "D_%=:\n\t}"
        :: "r"(mb), "r"(parity) : "memory");
}
__device__ __forceinline__ void mma_f16_ss(uint32_t d, uint64_t a, uint64_t b,
                                           uint32_t idesc, uint32_t en) {
    asm volatile(
        "{\n\t.reg .pred p;\n\t"
        "setp.ne.u32 p, %4, 0;\n\t"
        "tcgen05.mma.cta_group::1.kind::f16 [%0], %1, %2, %3, {%5, %5, %5, %5}, p;\n\t}"
        :: "r"(d), "l"(a), "l"(b), "r"(idesc), "r"(en), "r"(0u) : "memory");
}
__device__ __forceinline__ void ldtm_x32(uint32_t* r, uint32_t tm) {
    asm volatile(
        "tcgen05.ld.sync.aligned.32x32b.x32.b32 "
        "{%0,%1,%2,%3,%4,%5,%6,%7,%8,%9,%10,%11,%12,%13,%14,%15,"
        "%16,%17,%18,%19,%20,%21,%22,%23,%24,%25,%26,%27,%28,%29,%30,%31}, [%32];"
        : "=r"(r[0]), "=r"(r[1]), "=r"(r[2]), "=r"(r[3]), "=r"(r[4]), "=r"(r[5]), "=r"(r[6]), "=r"(r[7]),
          "=r"(r[8]), "=r"(r[9]), "=r"(r[10]), "=r"(r[11]), "=r"(r[12]), "=r"(r[13]), "=r"(r[14]), "=r"(r[15]),
          "=r"(r[16]), "=r"(r[17]), "=r"(r[18]), "=r"(r[19]), "=r"(r[20]), "=r"(r[21]), "=r"(r[22]), "=r"(r[23]),
          "=r"(r[24]), "=r"(r[25]), "=r"(r[26]), "=r"(r[27]), "=r"(r[28]), "=r"(r[29]), "=r"(r[30]), "=r"(r[31])
        : "r"(tm));
}
#define TC_ALLOC(smaddr, n)  asm volatile("tcgen05.alloc.cta_group::1.sync.aligned.shared::cta.b32 [%0], %1;" :: "r"(smaddr), "r"(n) : "memory")
#define TC_DEALLOC(tm, n)    asm volatile("tcgen05.dealloc.cta_group::1.sync.aligned.b32 %0, %1;" :: "r"(tm), "r"(n))
#define TC_RELINQ()          asm volatile("tcgen05.relinquish_alloc_permit.cta_group::1.sync.aligned;")
#define TC_COMMIT(mb)        asm volatile("tcgen05.commit.cta_group::1.mbarrier::arrive::one.shared::cluster.b64 [%0];" :: "r"(mb) : "memory")
#define TC_FENCE_AFTER()     asm volatile("tcgen05.fence::after_thread_sync;" ::: "memory")
#define TC_FENCE_BEFORE()    asm volatile("tcgen05.fence::before_thread_sync;" ::: "memory")
#define TC_WAIT_LD()         asm volatile("tcgen05.wait::ld.sync.aligned;" ::: "memory")
#define MBAR_INIT(mb, cnt)   asm volatile("mbarrier.init.shared.b64 [%0], %1;" :: "r"(mb), "r"(cnt) : "memory")
#define FENCE_ASYNC_SHARED() asm volatile("fence.proxy.async.shared::cta;" ::: "memory")
#endif

// ---------------- fp32 -> (hi, lo) fp16 split conversion (merged) -----------------
__global__ void cvt_all(const float* __restrict__ x, const float* __restrict__ wq,
                        const float* __restrict__ wk, const float* __restrict__ wv,
                        const float* __restrict__ wo) {
    int i = blockIdx.x * blockDim.x + threadIdx.x;
    const int NX = S * D, NW = D * D;
    const float* src;
    __half *hi, *lo;
    int off;
    if (i < NX)               { src = x;  hi = g_xh;           lo = g_xl;           off = i; }
    else if (i < NX + NW)     { src = wq; hi = g_Wh;           lo = g_Wl;           off = i - NX; }
    else if (i < NX + 2 * NW) { src = wk; hi = g_Wh + NW;      lo = g_Wl + NW;      off = i - NX - NW; }
    else if (i < NX + 3 * NW) { src = wv; hi = g_Wh + 2 * NW;  lo = g_Wl + 2 * NW;  off = i - NX - 2 * NW; }
    else if (i < NX + 4 * NW) { src = wo; hi = g_Woh;          lo = g_Wol;          off = i - NX - 3 * NW; }
    else return;
    float v = src[off];
    __half h = __float2half(v);
    hi[off] = h;
    lo[off] = __float2half(v - __half2float(h));
}

// ===== QKV split-fp16 tensor GEMM: C = x @ W_z, output heads layout + hi/lo =======
__global__ void __launch_bounds__(256) qkv_tc() {
    extern __shared__ __align__(16) char sm[];
    __half* Ah = (__half*)sm;                 // [128][72]
    __half* Alo = (__half*)(sm + 18432);
    __half* Bh = (__half*)(sm + 36864);       // [64][136]
    __half* Bl = (__half*)(sm + 54272);

    int tid = threadIdx.x, lane = tid & 31, wid = tid >> 5;
    int wm = wid >> 1, wn = wid & 1;
    int row0 = blockIdx.y * 128, col0 = blockIdx.x * 128;
    int which = blockIdx.z;
    const __half* Whp = g_Wh + (size_t)which * D * D;
    const __half* Wlp = g_Wl + (size_t)which * D * D;

    float acc[2][8][4];
#pragma unroll
    for (int i = 0; i < 2; i++)
#pragma unroll
        for (int j = 0; j < 8; j++)
#pragma unroll
            for (int l = 0; l < 4; l++) acc[i][j][l] = 0.f;

    uint32_t ah_b = smem_u32(Ah), al_b = smem_u32(Alo);
    uint32_t bh_b = smem_u32(Bh), bl_b = smem_u32(Bl);
    int lm = lane & 15, lh = lane >> 4;

    for (int k0 = 0; k0 < D; k0 += 64) {
#pragma unroll
        for (int e = 0; e < 4; e++) {
            int idx = tid + 256 * e;           // 0..1023
            int m = idx >> 3, c8 = idx & 7;
            *(uint4*)&Ah[m * 72 + c8 * 8]  = *(const uint4*)&g_xh[(size_t)(row0 + m) * D + k0 + c8 * 8];
            *(uint4*)&Alo[m * 72 + c8 * 8] = *(const uint4*)&g_xl[(size_t)(row0 + m) * D + k0 + c8 * 8];
            int kb = idx >> 4, c16 = idx & 15;
            *(uint4*)&Bh[kb * 136 + c16 * 8] = *(const uint4*)&Whp[(size_t)(k0 + kb) * D + col0 + c16 * 8];
            *(uint4*)&Bl[kb * 136 + c16 * 8] = *(const uint4*)&Wlp[(size_t)(k0 + kb) * D + col0 + c16 * 8];
        }
        __syncthreads();
#pragma unroll
        for (int kk = 0; kk < 64; kk += 16) {
            uint32_t a_h[2][4], a_l[2][4];
#pragma unroll
            for (int mt = 0; mt < 2; mt++) {
                ldm_x4(a_h[mt], ah_b + ((wm * 32 + mt * 16 + lm) * 72 + kk + lh * 8) * 2);
                ldm_x4(a_l[mt], al_b + ((wm * 32 + mt * 16 + lm) * 72 + kk + lh * 8) * 2);
            }
#pragma unroll
            for (int ng = 0; ng < 4; ng++) {
                uint32_t b_h[4], b_l[4];
                ldm_x4_trans(b_h, bh_b + ((kk + lm) * 136 + wn * 64 + ng * 16 + lh * 8) * 2);
                ldm_x4_trans(b_l, bl_b + ((kk + lm) * 136 + wn * 64 + ng * 16 + lh * 8) * 2);
#pragma unroll
                for (int mt = 0; mt < 2; mt++) {
                    mma16816(acc[mt][ng * 2 + 0], a_h[mt], b_h[0], b_h[1]);
                    mma16816(acc[mt][ng * 2 + 0], a_h[mt], b_l[0], b_l[1]);
                    mma16816(acc[mt][ng * 2 + 0], a_l[mt], b_h[0], b_h[1]);
                    mma16816(acc[mt][ng * 2 + 1], a_h[mt], b_h[2], b_h[3]);
                    mma16816(acc[mt][ng * 2 + 1], a_h[mt], b_l[2], b_l[3]);
                    mma16816(acc[mt][ng * 2 + 1], a_l[mt], b_h[2], b_h[3]);
                }
            }
        }
        __syncthreads();
    }

    float* outF = (which == 0) ? g_q : (which == 1) ? g_k : g_v;
    __half* oh = (which == 0) ? g_qhh : g_khh;
    __half* ol = (which == 0) ? g_qll : g_kll;
#pragma unroll
    for (int mt = 0; mt < 2; mt++) {
        int r0 = row0 + wm * 32 + mt * 16 + (lane >> 2);
#pragma unroll
        for (int nt = 0; nt < 8; nt++) {
            int c = col0 + wn * 64 + nt * 8 + (lane & 3) * 2;
            int hh = c >> 6, dh = c & 63;
#pragma unroll
            for (int rr = 0; rr < 2; rr++) {
                int s = r0 + rr * 8;
                float v0 = acc[mt][nt][rr * 2 + 0], v1 = acc[mt][nt][rr * 2 + 1];
                size_t gi = ((size_t)hh * S + s) * DH + dh;
                *(float2*)&outF[gi] = make_float2(v0, v1);
                if (which < 2) {
                    __half h0 = __float2half(v0), h1 = __float2half(v1);
                    *(__half2*)&oh[gi] = __halves2half2(h0, h1);
                    *(__half2*)&ol[gi] = __halves2half2(
                        __float2half(v0 - __half2float(h0)),
                        __float2half(v1 - __half2float(h1)));
                }
            }
        }
    }
}

// ---------------- fused: row norms of q,k + diag_p (one 16MB pass) ----------------
__global__ void norms_diag(const float* __restrict__ diag_scale,
                           const float* __restrict__ reg_p,
                           const float* __restrict__ bw_p) {
    int gw = (blockIdx.x * blockDim.x + threadIdx.x) >> 5;
    int lane = threadIdx.x & 31;
    if (gw >= H * S) return;
    const float* qp = g_q + (size_t)gw * DH;
    const float* kp = g_k + (size_t)gw * DH;
    float qa = qp[lane], qb = qp[lane + 32];
    float ka = kp[lane], kb = kp[lane + 32];
    float qn = qa * qa + qb * qb;
    float kn = ka * ka + kb * kb;
    float da = qa - ka, db = qb - kb;
    float dd = da * da + db * db;
#pragma unroll
    for (int o = 16; o > 0; o >>= 1) {
        qn += __shfl_xor_sync(0xffffffffu, qn, o);
        kn += __shfl_xor_sync(0xffffffffu, kn, o);
        dd += __shfl_xor_sync(0xffffffffu, dd, o);
    }
    if (lane == 0) {
        g_qn[gw] = qn;
        g_kn[gw] = kn;
        float bw = softplusf(bw_p[0]) + 1e-6f;
        float inv = 1.0f / (2.0f * bw * bw);
        float kd = __expf(-dd * inv);
        g_diagp[gw] = softplusf(kd) * diag_scale[gw / S] + reg_p[0];
    }
}

// ---------------- transpose k hi/lo: [h][s][dh] -> [h][dh][s] ----------------------
__global__ void transpose_k() {
    __shared__ __half t0[32][33];
    __shared__ __half t1[32][33];
    int h = blockIdx.z;
    int s0 = blockIdx.x * 32, d0 = blockIdx.y * 32;
    int tx = threadIdx.x, ty = threadIdx.y;   // 32 x 8
#pragma unroll
    for (int i = 0; i < 32; i += 8) {
        t0[ty + i][tx] = g_khh[((size_t)h * S + s0 + ty + i) * DH + d0 + tx];
        t1[ty + i][tx] = g_kll[((size_t)h * S + s0 + ty + i) * DH + d0 + tx];
    }
    __syncthreads();
#pragma unroll
    for (int i = 0; i < 32; i += 8) {
        g_kTh[((size_t)h * DH + d0 + ty + i) * S + s0 + tx] = t0[tx][ty + i];
        g_kTl[((size_t)h * DH + d0 + ty + i) * S + s0 + tx] = t1[tx][ty + i];
    }
}

// ===== fused kmat (FULL phase1, cp.async double-buffered B tiles) =================
__global__ void __launch_bounds__(256) kmat_tc(const float* __restrict__ bw_p) {
    extern __shared__ __align__(16) char sm[];
    __half* Qh = (__half*)sm;                 // [128][72] 18432
    __half* Ql = (__half*)(sm + 18432);       // 18432
    float* qn_s = (float*)(sm + 106496);      // 512
    float* kn_p0 = (float*)(sm + 107008);     // 512
    float* kn_p1 = (float*)(sm + 107520);     // 512
    unsigned* minv = (unsigned*)(sm + 108032);// 512   -> total 108544

    uint32_t base = smem_u32(sm);
    uint32_t bhB[2] = {base + 36864u, base + 71680u};
    uint32_t blB[2] = {base + 54272u, base + 89088u};
    uint32_t knB[2] = {base + 107008u, base + 107520u};
    float* kn_p[2] = {kn_p0, kn_p1};

    int tid = threadIdx.x, lane = tid & 31, wid = tid >> 5;
    int h = blockIdx.y, i0 = blockIdx.x * 128;
    float bw = softplusf(bw_p[0]) + 1e-6f;
    float inv = 1.0f / (2.0f * bw * bw);

#pragma unroll
    for (int e = 0; e < 4; e++) {
        int idx = tid + 256 * e;
        int m = idx >> 3, c8 = idx & 7;
        *(uint4*)&Qh[m * 72 + c8 * 8] = *(const uint4*)&g_qhh[((size_t)h * S + i0 + m) * DH + c8 * 8];
        *(uint4*)&Ql[m * 72 + c8 * 8] = *(const uint4*)&g_qll[((size_t)h * S + i0 + m) * DH + c8 * 8];
    }
    if (tid < 128) {
        qn_s[tid] = g_qn[h * S + i0 + tid];
        minv[tid] = 0x7F800000u;
    }
    __syncthreads();

    uint32_t qh_b = smem_u32(Qh), ql_b = smem_u32(Ql);
    int lm = lane & 15, lh = lane >> 4;

    const __half* kThp = g_kTh + (size_t)h * DH * S;
    const __half* kTlp = g_kTl + (size_t)h * DH * S;

    float rmin[16];
#pragma unroll
    for (int i = 0; i < 16; i++) rmin[i] = 3.4e38f;

    // ---------------- phase 1: hi-only dist over ALL columns (pipelined) ----------
    {
#pragma unroll
        for (int e = 0; e < 4; e++) {
            int idx = tid + 256 * e;
            int kb = idx >> 4, c16 = idx & 15;
            cp_async16(bhB[0] + (uint32_t)(kb * 272 + c16 * 16),
                       kThp + (size_t)kb * S + c16 * 8);
        }
        if (tid < 32)
            cp_async16(knB[0] + (uint32_t)(tid * 16), &g_kn[h * S + tid * 4]);
        asm volatile("cp.async.commit_group;" ::: "memory");
    }

    for (int c = 0; c < 16; c++) {
        int st = c & 1;
        if (c < 15) {
            int j0n = (c + 1) * 128;
            int sn = st ^ 1;
#pragma unroll
            for (int e = 0; e < 4; e++) {
                int idx = tid + 256 * e;
                int kb = idx >> 4, c16 = idx & 15;
                cp_async16(bhB[sn] + (uint32_t)(kb * 272 + c16 * 16),
                           kThp + (size_t)kb * S + j0n + c16 * 8);
            }
            if (tid < 32)
                cp_async16(knB[sn] + (uint32_t)(tid * 16), &g_kn[h * S + j0n + tid * 4]);
            asm volatile("cp.async.commit_group;" ::: "memory");
            asm volatile("cp.async.wait_group 1;" ::: "memory");
        } else {
            asm volatile("cp.async.wait_group 0;" ::: "memory");
        }
        __syncthreads();

        uint32_t bf[4][4];
#pragma unroll
        for (int k4 = 0; k4 < 4; k4++)
            ldm_x4_trans(bf[k4], bhB[st] + (uint32_t)(((k4 * 16 + lm) * 136 + wid * 16 + lh * 8) * 2));

        const float* kns = kn_p[st];
#pragma unroll
        for (int mt = 0; mt < 8; mt++) {
            float a0[4] = {0.f, 0.f, 0.f, 0.f}, a1[4] = {0.f, 0.f, 0.f, 0.f};
#pragma unroll
            for (int k4 = 0; k4 < 4; k4++) {
                uint32_t a[4];
                ldm_x4(a, qh_b + ((mt * 16 + lm) * 72 + k4 * 16 + lh * 8) * 2);
                mma16816(a0, a, bf[k4][0], bf[k4][1]);
                mma16816(a1, a, bf[k4][2], bf[k4][3]);
            }
            int r = mt * 16 + (lane >> 2);
            float qn0 = qn_s[r], qn1 = qn_s[r + 8];
            int cb = wid * 16 + (lane & 3) * 2;
            float kn0 = kns[cb], kn1 = kns[cb + 1], kn8 = kns[cb + 8], kn9 = kns[cb + 9];
            float d0 = fminf(fminf(qn0 + kn0 - 2.f * a0[0], qn0 + kn1 - 2.f * a0[1]),
                             fminf(qn0 + kn8 - 2.f * a1[0], qn0 + kn9 - 2.f * a1[1]));
            float d1 = fminf(fminf(qn1 + kn0 - 2.f * a0[2], qn1 + kn1 - 2.f * a0[3]),
                             fminf(qn1 + kn8 - 2.f * a1[2], qn1 + kn9 - 2.f * a1[3]));
            rmin[mt * 2] = fminf(rmin[mt * 2], d0);
            rmin[mt * 2 + 1] = fminf(rmin[mt * 2 + 1], d1);
        }
        __syncthreads();
    }
#pragma unroll
    for (int i = 0; i < 16; i++) {
        rmin[i] = fminf(rmin[i], __shfl_xor_sync(0xffffffffu, rmin[i], 1));
        rmin[i] = fminf(rmin[i], __shfl_xor_sync(0xffffffffu, rmin[i], 2));
    }
    if ((lane & 3) == 0) {
#pragma unroll
        for (int mt = 0; mt < 8; mt++) {
            atomicMin(&minv[mt * 16 + (lane >> 2)], __float_as_uint(fmaxf(rmin[mt * 2], 0.f)));
            atomicMin(&minv[mt * 16 + (lane >> 2) + 8], __float_as_uint(fmaxf(rmin[mt * 2 + 1], 0.f)));
        }
    }
    __syncthreads();
    if (tid < 128)
        g_scale[h * S + i0 + tid] = __expf(-__uint_as_float(minv[tid]) * inv);

    // ---------------- phase 2: split dist, exp -> Kh fp16 (pipelined) -------------
    {
#pragma unroll
        for (int e = 0; e < 4; e++) {
            int idx = tid + 256 * e;
            int kb = idx >> 4, c16 = idx & 15;
            cp_async16(bhB[0] + (uint32_t)(kb * 272 + c16 * 16),
                       kThp + (size_t)kb * S + c16 * 8);
            cp_async16(blB[0] + (uint32_t)(kb * 272 + c16 * 16),
                       kTlp + (size_t)kb * S + c16 * 8);
        }
        if (tid < 32)
            cp_async16(knB[0] + (uint32_t)(tid * 16), &g_kn[h * S + tid * 4]);
        asm volatile("cp.async.commit_group;" ::: "memory");
    }

    for (int c = 0; c < 16; c++) {
        int st = c & 1;
        int j0 = c * 128;
        if (c < 15) {
            int j0n = (c + 1) * 128;
            int sn = st ^ 1;
#pragma unroll
            for (int e = 0; e < 4; e++) {
                int idx = tid + 256 * e;
                int kb = idx >> 4, c16 = idx & 15;
                cp_async16(bhB[sn] + (uint32_t)(kb * 272 + c16 * 16),
                           kThp + (size_t)kb * S + j0n + c16 * 8);
                cp_async16(blB[sn] + (uint32_t)(kb * 272 + c16 * 16),
                           kTlp + (size_t)kb * S + j0n + c16 * 8);
            }
            if (tid < 32)
                cp_async16(knB[sn] + (uint32_t)(tid * 16), &g_kn[h * S + j0n + tid * 4]);
            asm volatile("cp.async.commit_group;" ::: "memory");
            asm volatile("cp.async.wait_group 1;" ::: "memory");
        } else {
            asm volatile("cp.async.wait_group 0;" ::: "memory");
        }
        __syncthreads();

        uint32_t bfh[4][4], bfl[4][4];
#pragma unroll
        for (int k4 = 0; k4 < 4; k4++) {
            ldm_x4_trans(bfh[k4], bhB[st] + (uint32_t)(((k4 * 16 + lm) * 136 + wid * 16 + lh * 8) * 2));
            ldm_x4_trans(bfl[k4], blB[st] + (uint32_t)(((k4 * 16 + lm) * 136 + wid * 16 + lh * 8) * 2));
        }

        const float* kns = kn_p[st];
#pragma unroll
        for (int mt = 0; mt < 8; mt++) {
            float a0[4] = {0.f, 0.f, 0.f, 0.f}, a1[4] = {0.f, 0.f, 0.f, 0.f};
#pragma unroll
            for (int k4 = 0; k4 < 4; k4++) {
                uint32_t ah[4], al[4];
                ldm_x4(ah, qh_b + ((mt * 16 + lm) * 72 + k4 * 16 + lh * 8) * 2);
                ldm_x4(al, ql_b + ((mt * 16 + lm) * 72 + k4 * 16 + lh * 8) * 2);
                mma16816(a0, ah, bfh[k4][0], bfh[k4][1]);
                mma16816(a0, ah, bfl[k4][0], bfl[k4][1]);
                mma16816(a0, al, bfh[k4][0], bfh[k4][1]);
                mma16816(a1, ah, bfh[k4][2], bfh[k4][3]);
                mma16816(a1, ah, bfl[k4][2], bfl[k4][3]);
                mma16816(a1, al, bfh[k4][2], bfh[k4][3]);
            }
            int r = mt * 16 + (lane >> 2);
            float qn0 = qn_s[r], qn1 = qn_s[r + 8];
            float dm0 = __uint_as_float(minv[r]), dm1 = __uint_as_float(minv[r + 8]);
            int cb = wid * 16 + (lane & 3) * 2;
            float kn0 = kns[cb], kn1 = kns[cb + 1], kn8 = kns[cb + 8], kn9 = kns[cb + 9];
            float e00 = __expf((dm0 - fmaxf(qn0 + kn0 - 2.f * a0[0], 0.f)) * inv);
            float e01 = __expf((dm0 - fmaxf(qn0 + kn1 - 2.f * a0[1], 0.f)) * inv);
            float e10 = __expf((dm1 - fmaxf(qn1 + kn0 - 2.f * a0[2], 0.f)) * inv);
            float e11 = __expf((dm1 - fmaxf(qn1 + kn1 - 2.f * a0[3], 0.f)) * inv);
            float f00 = __expf((dm0 - fmaxf(qn0 + kn8 - 2.f * a1[0], 0.f)) * inv);
            float f01 = __expf((dm0 - fmaxf(qn0 + kn9 - 2.f * a1[1], 0.f)) * inv);
            float f10 = __expf((dm1 - fmaxf(qn1 + kn8 - 2.f * a1[2], 0.f)) * inv);
            float f11 = __expf((dm1 - fmaxf(qn1 + kn9 - 2.f * a1[3], 0.f)) * inv);
            __half* Kp0 = &g_Kh[((size_t)(h * S + i0 + r)) * S + j0 + cb];
            __half* Kp1 = Kp0 + (size_t)8 * S;
            *(__half2*)Kp0 = __halves2half2(__float2half(e00), __float2half(e01));
            *(__half2*)(Kp0 + 8) = __halves2half2(__float2half(f00), __float2half(f01));
            *(__half2*)Kp1 = __halves2half2(__float2half(e10), __float2half(e11));
            *(__half2*)(Kp1 + 8) = __halves2half2(__float2half(f10), __float2half(f11));
        }
        __syncthreads();
    }
}

// ---------------- U[h,s,r] = sum_rp pos[s,rp] * proj[h,rp,r] ----------------------
__global__ void u_kernel(const float* __restrict__ pos, const float* __restrict__ proj) {
    __shared__ float pr[RANK][RANK];
    int h = blockIdx.y;
    int tid = threadIdx.x;
    pr[tid >> 4][tid & 15] = proj[h * RANK * RANK + tid];
    __syncthreads();
    int s = blockIdx.x * 256 + tid;
    float pe[RANK];
#pragma unroll
    for (int r = 0; r < RANK; r++) pe[r] = pos[(size_t)s * RANK + r];
#pragma unroll
    for (int r = 0; r < RANK; r++) {
        float acc = 0.f;
#pragma unroll
        for (int rp = 0; rp < RANK; rp++) acc += pe[rp] * pr[rp][r];
        g_U[((size_t)h * S + s) * RANK + r] = acc;
    }
}

// == K@alpha: tcgen05 (sm_103a cubin) or HMMA fallback; fused U^T r partials =======
// mode0: r = v - scale*K'a - lam*a, writes g_r AND utr_part[blockIdx.x]
// mode1: store NORMALIZED K'a hi/lo
__global__ void __launch_bounds__(256) kapply_mma(int mode, const float* __restrict__ lam_p) {
#if HAS_TC
    extern __shared__ __align__(16) char smraw[];
    uint32_t rawb = smem_u32(smraw);
    uint32_t abase = (rawb + 1023u) & ~1023u;
    char* smA = smraw + (abase - rawb);
    uint32_t A0 = abase, A1 = abase + 16384;
    uint32_t B0 = abase + 32768, B1 = abase + 40960;
    uint32_t ctrl = abase + 49152, mbar = abase + 49160;

    int tid = threadIdx.x, wid = tid >> 5, lane = tid & 31;
    int h = blockIdx.y;
    int s0 = blockIdx.x * 128;

    if (wid == 0) { TC_ALLOC(ctrl, 64); TC_RELINQ(); }
    if (tid == 0) MBAR_INIT(mbar, 1);
    __syncthreads();
    uint32_t tmem;
    asm volatile("ld.shared.b32 %0, [%1];" : "=r"(tmem) : "r"(ctrl));

    const __half* Kb = g_Kh + ((size_t)h * S + s0) * S;
    const __half* Tb = g_alphaT + (size_t)h * DH * S;

    // prefetch chunk 0 into buffer 0 (SW128-swizzled tiles)
    {
#pragma unroll
        for (int e = 0; e < 4; e++) {
            int idx = tid + 256 * e;
            int m = idx >> 3, c16 = idx & 7;
            cp_async16(A0 + SW128((uint32_t)(m * 128 + c16 * 16)), Kb + (size_t)m * S + c16 * 8);
        }
#pragma unroll
        for (int e = 0; e < 2; e++) {
            int idx = tid + 256 * e;
            int m = idx >> 3, c16 = idx & 7;
            cp_async16(B0 + SW128((uint32_t)(m * 128 + c16 * 16)), Tb + (size_t)m * S + c16 * 8);
        }
        asm volatile("cp.async.commit_group;" ::: "memory");
    }

    for (int c = 0; c < 32; c++) {
        uint32_t Ac = (c & 1) ? A1 : A0, Bc = (c & 1) ? B1 : B0;
        if (c >= 1) mbar_wait(mbar, (uint32_t)((c - 1) & 1));  // MMA c-1 done -> its buffers free
        if (c + 1 < 32) {
            uint32_t An = (c & 1) ? A0 : A1, Bn = (c & 1) ? B0 : B1;
            int t0 = (c + 1) * 64;
#pragma unroll
            for (int e = 0; e < 4; e++) {
                int idx = tid + 256 * e;
                int m = idx >> 3, c16 = idx & 7;
                cp_async16(An + SW128((uint32_t)(m * 128 + c16 * 16)), Kb + (size_t)m * S + t0 + c16 * 8);
            }
#pragma unroll
            for (int e = 0; e < 2; e++) {
                int idx = tid + 256 * e;
                int m = idx >> 3, c16 = idx & 7;
                cp_async16(Bn + SW128((uint32_t)(m * 128 + c16 * 16)), Tb + (size_t)m * S + t0 + c16 * 8);
            }
            asm volatile("cp.async.commit_group;" ::: "memory");
            asm volatile("cp.async.wait_group 1;" ::: "memory");
        } else {
            asm volatile("cp.async.wait_group 0;" ::: "memory");
        }
        __syncthreads();
        FENCE_ASYNC_SHARED();
        if (wid == 0 && elect_one()) {
            uint64_t ad = make_desc(Ac), bd = make_desc(Bc);
            mma_f16_ss(tmem, ad + 0, bd + 0, IDESC_KA, (c > 0) ? 1u : 0u);
            mma_f16_ss(tmem, ad + 2, bd + 2, IDESC_KA, 1u);
            mma_f16_ss(tmem, ad + 4, bd + 4, IDESC_KA, 1u);
            mma_f16_ss(tmem, ad + 6, bd + 6, IDESC_KA, 1u);
            TC_COMMIT(mbar);
        }
    }

    mbar_wait(mbar, 1u);   // chunk 31 commit
    TC_FENCE_AFTER();

    float* rsm = (float*)smA;             // [128][65] = 33280 B (buffers dead)
    float* Usm = (float*)(smA + 33280);   // [128][16] =  8192 B
    if (wid < 4) {
        uint32_t dr[64];
        ldtm_x32(dr, tmem);
        ldtm_x32(dr + 32, tmem + 32);
        TC_WAIT_LD();
        TC_FENCE_BEFORE();
        int m = wid * 32 + lane;
#pragma unroll
        for (int cc = 0; cc < 64; cc++) rsm[m * 65 + cc] = __uint_as_float(dr[cc]);
    }
    __syncthreads();
    if (wid == 0) TC_DEALLOC(tmem, 64);

    if (mode == 0) {
        float lam = softplusf(lam_p[0]);
#pragma unroll
        for (int e = 0; e < 8; e++) {
            int idx = tid + 256 * e;
            int m2 = idx >> 4, rr = idx & 15;
            Usm[m2 * 16 + rr] = g_U[((size_t)h * S + s0 + m2) * RANK + rr];
        }
        for (int e = 0; e < 32; e++) {
            int idx = tid + 256 * e;       // 0..8191
            int m = idx >> 6, d0 = idx & 63;
            int s = s0 + m;
            size_t gi = ((size_t)h * S + s) * DH + d0;
            float Dv = rsm[m * 65 + d0];
            float rv = g_v[gi] - g_scale[h * S + s] * Dv - lam * g_alpha[gi];
            g_r[gi] = rv;
            rsm[m * 65 + d0] = rv;
        }
        __syncthreads();

        int d = tid & 63, rg = tid >> 6;
        float a4[4] = {0.f, 0.f, 0.f, 0.f};
        for (int s2 = 0; s2 < 128; s2++) {
            float rv = rsm[s2 * 65 + d];
            a4[0] += Usm[s2 * 16 + rg] * rv;
            a4[1] += Usm[s2 * 16 + rg + 4] * rv;
            a4[2] += Usm[s2 * 16 + rg + 8] * rv;
            a4[3] += Usm[s2 * 16 + rg + 12] * rv;
        }
        int part = blockIdx.x;
#pragma unroll
        for (int i = 0; i < 4; i++)
            g_utr_part[(((size_t)part * H + h) * RANK + (rg + 4 * i)) * DH + d] = a4[i];
    } else {
        for (int e = 0; e < 32; e++) {
            int idx = tid + 256 * e;
            int m = idx >> 6, d0 = idx & 63;
            size_t gi = ((size_t)h * S + s0 + m) * DH + d0;
            float cN = rsm[m * 65 + d0];
            __half hh = __float2half(cN);
            g_ctxH[gi] = hh;
            g_ctxL[gi] = __float2half(cN - __half2float(hh));
        }
    }
#else
    // ===== HMMA fallback (R14-proven) =====
    extern __shared__ __align__(16) char sm[];
    uint32_t base = smem_u32(sm);
    uint32_t ksb0 = base, ksb1 = base + 18432;
    uint32_t alb0 = base + 36864, alb1 = base + 46080;

    int tid = threadIdx.x, wid = tid >> 5, lane = tid & 31;
    int h = blockIdx.y;
    int s0 = blockIdx.x * 128;

    const __half* Kb = g_Kh + ((size_t)h * S + s0) * S;
    const __half* Ab = g_alphaH + (size_t)h * S * DH;

    float acc[8][4];
#pragma unroll
    for (int i = 0; i < 8; i++)
#pragma unroll
        for (int j = 0; j < 4; j++) acc[i][j] = 0.f;

    int lm = lane & 15, lh = lane >> 4;
    int mA = tid >> 3, c8A = tid & 7;

    {
        int t0 = 0;
#pragma unroll
        for (int e = 0; e < 4; e++) {
            int m = mA + 32 * e;
            cp_async16(ksb0 + (uint32_t)(m * 144 + c8A * 16), Kb + (size_t)m * S + t0 + c8A * 8);
        }
#pragma unroll
        for (int e = 0; e < 2; e++) {
            int t = mA + 32 * e;
            cp_async16(alb0 + (uint32_t)(t * 144 + c8A * 16), Ab + (size_t)(t0 + t) * DH + c8A * 8);
        }
        asm volatile("cp.async.commit_group;" ::: "memory");
    }

    for (int c = 0; c < 32; c++) {
        uint32_t ks_cur = (c & 1) ? ksb1 : ksb0;
        uint32_t al_cur = (c & 1) ? alb1 : alb0;
        if (c < 31) {
            uint32_t ks_nxt = (c & 1) ? ksb0 : ksb1;
            uint32_t al_nxt = (c & 1) ? alb0 : alb1;
            int t0 = (c + 1) * 64;
#pragma unroll
            for (int e = 0; e < 4; e++) {
                int m = mA + 32 * e;
                cp_async16(ks_nxt + (uint32_t)(m * 144 + c8A * 16), Kb + (size_t)m * S + t0 + c8A * 8);
            }
#pragma unroll
            for (int e = 0; e < 2; e++) {
                int t = mA + 32 * e;
                cp_async16(al_nxt + (uint32_t)(t * 144 + c8A * 16), Ab + (size_t)(t0 + t) * DH + c8A * 8);
            }
            asm volatile("cp.async.commit_group;" ::: "memory");
            asm volatile("cp.async.wait_group 1;" ::: "memory");
        } else {
            asm volatile("cp.async.wait_group 0;" ::: "memory");
        }
        __syncthreads();

#pragma unroll
        for (int kk = 0; kk < 64; kk += 16) {
            uint32_t a[4];
            ldm_x4(a, ks_cur + (uint32_t)(((wid * 16 + lm) * 72 + kk + lh * 8) * 2));
#pragma unroll
            for (int nt = 0; nt < 4; nt++) {
                uint32_t b[4];
                ldm_x4_trans(b, al_cur + (uint32_t)(((kk + lm) * 72 + nt * 16 + lh * 8) * 2));
                mma16816(acc[nt * 2 + 0], a, b[0], b[1]);
                mma16816(acc[nt * 2 + 1], a, b[2], b[3]);
            }
        }
        __syncthreads();
    }

    int rbase = s0 + wid * 16 + (lane >> 2);
    float sc0 = g_scale[h * S + rbase];
    float sc1 = g_scale[h * S + rbase + 8];

    if (mode == 0) {
        float lam = softplusf(lam_p[0]);
        float* rsm = (float*)sm;
        float* Usm = (float*)(sm + 33280);
#pragma unroll
        for (int e = 0; e < 8; e++) {
            int idx = tid + 256 * e;
            int m = idx >> 4, rr = idx & 15;
            Usm[m * 16 + rr] = g_U[((size_t)h * S + s0 + m) * RANK + rr];
        }
        int rl0 = wid * 16 + (lane >> 2);
#pragma unroll
        for (int nt = 0; nt < 8; nt++) {
            int col = nt * 8 + (lane & 3) * 2;
            size_t g0 = ((size_t)h * S + rbase) * DH + col;
            size_t g1 = g0 + 8 * DH;
            float2 v0 = *(const float2*)&g_v[g0];
            float2 v1 = *(const float2*)&g_v[g1];
            float2 a0 = *(const float2*)&g_alpha[g0];
            float2 a1 = *(const float2*)&g_alpha[g1];
            float r00 = v0.x - sc0 * acc[nt][0] - lam * a0.x;
            float r01 = v0.y - sc0 * acc[nt][1] - lam * a0.y;
            float r10 = v1.x - sc1 * acc[nt][2] - lam * a1.x;
            float r11 = v1.y - sc1 * acc[nt][3] - lam * a1.y;
            *(float2*)&g_r[g0] = make_float2(r00, r01);
            *(float2*)&g_r[g1] = make_float2(r10, r11);
            rsm[rl0 * 65 + col] = r00;
            rsm[rl0 * 65 + col + 1] = r01;
            rsm[(rl0 + 8) * 65 + col] = r10;
            rsm[(rl0 + 8) * 65 + col + 1] = r11;
        }
        __syncthreads();

        int d = tid & 63, rg = tid >> 6;
        float a4[4] = {0.f, 0.f, 0.f, 0.f};
        for (int s = 0; s < 128; s++) {
            float rv = rsm[s * 65 + d];
            a4[0] += Usm[s * 16 + rg] * rv;
            a4[1] += Usm[s * 16 + rg + 4] * rv;
            a4[2] += Usm[s * 16 + rg + 8] * rv;
            a4[3] += Usm[s * 16 + rg + 12] * rv;
        }
        int part = blockIdx.x;
#pragma unroll
        for (int i = 0; i < 4; i++)
            g_utr_part[(((size_t)part * H + h) * RANK + (rg + 4 * i)) * DH + d] = a4[i];
    } else {
#pragma unroll
        for (int nt = 0; nt < 8; nt++) {
            int col = nt * 8 + (lane & 3) * 2;
            size_t g0 = ((size_t)h * S + rbase) * DH + col;
            size_t g1 = g0 + 8 * DH;
            float c00 = acc[nt][0], c01 = acc[nt][1];
            float c10 = acc[nt][2], c11 = acc[nt][3];
            __half h00 = __float2half(c00), h01 = __float2half(c01);
            __half h10 = __float2half(c10), h11 = __float2half(c11);
            *(__half2*)&g_ctxH[g0] = __halves2half2(h00, h01);
            *(__half2*)&g_ctxH[g1] = __halves2half2(h10, h11);
            *(__half2*)&g_ctxL[g0] = __halves2half2(__float2half(c00 - __half2float(h00)),
                                                    __float2half(c01 - __half2float(h01)));
            *(__half2*)&g_ctxL[g1] = __halves2half2(__float2half(c10 - __half2float(h10)),
                                                    __float2half(c11 - __half2float(h11)));
        }
    }
#endif
}

// ------- utr_part[p,h,r,d] = sum_{s in part} U[h,s,r] * v[h,s,d] (iter 1 only) ----
__global__ void utr_kernel() {
    int h = blockIdx.x;
    int part = blockIdx.y;     // 0..15
    int tid = threadIdx.x;
    int d = tid & 63, rr = tid >> 6;
    const float* Ub = g_U + (size_t)h * S * RANK;
    const float* rb = g_v + (size_t)h * S * DH;
    int s0 = part * (S / 16);
    float a0 = 0, a1 = 0, a2 = 0, a3 = 0;
    for (int s = s0; s < s0 + S / 16; s += 4) {
        a0 += Ub[(s + 0) * RANK + rr] * rb[(size_t)(s + 0) * DH + d];
        a1 += Ub[(s + 1) * RANK + rr] * rb[(size_t)(s + 1) * DH + d];
        a2 += Ub[(s + 2) * RANK + rr] * rb[(size_t)(s + 2) * DH + d];
        a3 += Ub[(s + 3) * RANK + rr] * rb[(size_t)(s + 3) * DH + d];
    }
    g_utr_part[((part * H + h) * RANK + rr) * DH + d] = (a0 + a1) + (a2 + a3);
}

// -------- alpha = prev + r*diag_p + U @ utr; emit fp16 mirror + transposed --------
__global__ void update_kernel(int first) {
    __shared__ float ut[RANK][DH];
    __shared__ float Us[16][RANK];
    __shared__ __half aT[64][18];
    int h = blockIdx.y;
    int tid = threadIdx.x;
    {
        float sum = 0.f;
#pragma unroll
        for (int p = 0; p < 16; p++) sum += g_utr_part[(p * H + h) * RANK * DH + tid];
        ut[tid >> 6][tid & 63] = sum;
    }
    int s0 = blockIdx.x * 16;
    if (tid < 16 * RANK)
        Us[tid >> 4][tid & 15] = g_U[((size_t)h * S + s0 + (tid >> 4)) * RANK + (tid & 15)];
    __syncthreads();

    int sl = tid >> 6;
    int d = tid & 63;
    int s = s0 + sl;
    size_t idx = ((size_t)h * S + s) * DH + d;
    float acc = 0.f;
#pragma unroll
    for (int r2 = 0; r2 < RANK; r2++) acc += Us[sl][r2] * ut[r2][d];
    float rv = first ? g_v[idx] : g_r[idx];
    float prev = first ? 0.f : g_alpha[idx];
    float na = prev + rv * g_diagp[h * S + s] + acc;
    g_alpha[idx] = na;
    __half nah = __float2half(na);
    g_alphaH[idx] = nah;
    aT[d][sl] = nah;
    __syncthreads();
    if (tid < 512) {
        int dd = tid >> 3, i = tid & 7;
        __half2 v2 = __halves2half2(aT[dd][i * 2], aT[dd][i * 2 + 1]);
        *(__half2*)&g_alphaT[((size_t)h * DH + dd) * S + s0 + i * 2] = v2;
    }
}

// == output GEMM (128x64 tiles): out = (scale ⊙ ctxN)_flat @ Wo ====================
__global__ void __launch_bounds__(256) wo_tc(float* __restrict__ out) {
    extern __shared__ __align__(16) char sm[];
    __half* Ah = (__half*)sm;                 // [128][72]
    __half* Alo = (__half*)(sm + 18432);
    __half* Bh = (__half*)(sm + 36864);       // [64][72]
    __half* Bl = (__half*)(sm + 46080);
    float* scs = (float*)(sm + 55296);        // 128 row scales

    int tid = threadIdx.x, lane = tid & 31, wid = tid >> 5;
    int wm = wid >> 1, wn = wid & 1;
    int row0 = blockIdx.y * 128, col0 = blockIdx.x * 64;

    float acc[2][4][4];
#pragma unroll
    for (int i = 0; i < 2; i++)
#pragma unroll
        for (int j = 0; j < 4; j++)
#pragma unroll
            for (int l = 0; l < 4; l++) acc[i][j][l] = 0.f;

    uint32_t ah_b = smem_u32(Ah), al_b = smem_u32(Alo);
    uint32_t bh_b = smem_u32(Bh), bl_b = smem_u32(Bl);
    int lm = lane & 15, lh = lane >> 4;

    for (int ck = 0; ck < 16; ck++) {
        int k0 = ck * 64;
#pragma unroll
        for (int e = 0; e < 4; e++) {
            int idx = tid + 256 * e;
            int m = idx >> 3, c8 = idx & 7;
            *(uint4*)&Ah[m * 72 + c8 * 8]  = *(const uint4*)&g_ctxH[((size_t)ck * S + row0 + m) * DH + c8 * 8];
            *(uint4*)&Alo[m * 72 + c8 * 8] = *(const uint4*)&g_ctxL[((size_t)ck * S + row0 + m) * DH + c8 * 8];
        }
#pragma unroll
        for (int e = 0; e < 2; e++) {
            int idx = tid + 256 * e;
            int kb = idx >> 3, c8 = idx & 7;
            *(uint4*)&Bh[kb * 72 + c8 * 8] = *(const uint4*)&g_Woh[(size_t)(k0 + kb) * D + col0 + c8 * 8];
            *(uint4*)&Bl[kb * 72 + c8 * 8] = *(const uint4*)&g_Wol[(size_t)(k0 + kb) * D + col0 + c8 * 8];
        }
        if (tid < 128) scs[tid] = g_scale[ck * S + row0 + tid];
        __syncthreads();

        float accp[2][4][4];
#pragma unroll
        for (int i = 0; i < 2; i++)
#pragma unroll
            for (int j = 0; j < 4; j++)
#pragma unroll
                for (int l = 0; l < 4; l++) accp[i][j][l] = 0.f;

#pragma unroll
        for (int kk = 0; kk < 64; kk += 16) {
            uint32_t a_h[2][4], a_l[2][4];
#pragma unroll
            for (int mt = 0; mt < 2; mt++) {
                ldm_x4(a_h[mt], ah_b + ((wm * 32 + mt * 16 + lm) * 72 + kk + lh * 8) * 2);
                ldm_x4(a_l[mt], al_b + ((wm * 32 + mt * 16 + lm) * 72 + kk + lh * 8) * 2);
            }
#pragma unroll
            for (int ng = 0; ng < 2; ng++) {
                uint32_t b_h[4], b_l[4];
                ldm_x4_trans(b_h, bh_b + ((kk + lm) * 72 + wn * 32 + ng * 16 + lh * 8) * 2);
                ldm_x4_trans(b_l, bl_b + ((kk + lm) * 72 + wn * 32 + ng * 16 + lh * 8) * 2);
#pragma unroll
                for (int mt = 0; mt < 2; mt++) {
                    mma16816(accp[mt][ng * 2 + 0], a_h[mt], b_h[0], b_h[1]);
                    mma16816(accp[mt][ng * 2 + 0], a_h[mt], b_l[0], b_l[1]);
                    mma16816(accp[mt][ng * 2 + 0], a_l[mt], b_h[0], b_h[1]);
                    mma16816(accp[mt][ng * 2 + 1], a_h[mt], b_h[2], b_h[3]);
                    mma16816(accp[mt][ng * 2 + 1], a_h[mt], b_l[2], b_l[3]);
                    mma16816(accp[mt][ng * 2 + 1], a_l[mt], b_h[2], b_h[3]);
                }
            }
        }

#pragma unroll
        for (int mt = 0; mt < 2; mt++) {
            int rl = wm * 32 + mt * 16 + (lane >> 2);
            float sc0 = scs[rl], sc1 = scs[rl + 8];
#pragma unroll
            for (int nt = 0; nt < 4; nt++) {
                acc[mt][nt][0] += sc0 * accp[mt][nt][0];
                acc[mt][nt][1] += sc0 * accp[mt][nt][1];
                acc[mt][nt][2] += sc1 * accp[mt][nt][2];
                acc[mt][nt][3] += sc1 * accp[mt][nt][3];
            }
        }
        __syncthreads();
    }

#pragma unroll
    for (int mt = 0; mt < 2; mt++) {
        int r0 = row0 + wm * 32 + mt * 16 + (lane >> 2);
#pragma unroll
        for (int nt = 0; nt < 4; nt++) {
            int c = col0 + wn * 32 + nt * 8 + (lane & 3) * 2;
#pragma unroll
            for (int rr = 0; rr < 2; rr++) {
                int s = r0 + rr * 8;
                *(float2*)&out[(size_t)s * D + c] =
                    make_float2(acc[mt][nt][rr * 2 + 0], acc[mt][nt][rr * 2 + 1]);
            }
        }
    }
}

// ---------------- launch ----------------------------------------------------------
extern "C" void kernel_launch(void* const* d_in, const int* in_sizes, int n_in,
                              void* d_out, int out_size) {
    const float* x          = (const float*)d_in[0];
    const float* Wq         = (const float*)d_in[1];
    const float* Wk         = (const float*)d_in[2];
    const float* Wv         = (const float*)d_in[3];
    const float* Wo         = (const float*)d_in[4];
    const float* bandwidth  = (const float*)d_in[5];
    const float* diag_scale = (const float*)d_in[6];
    const float* pos        = (const float*)d_in[7];
    const float* proj       = (const float*)d_in[8];
    const float* reg        = (const float*)d_in[9];
    const float* lam        = (const float*)d_in[10];
    float* out = (float*)d_out;

    static bool attr_done = false;
    if (!attr_done) {
        cudaFuncSetAttribute(qkv_tc, cudaFuncAttributeMaxDynamicSharedMemorySize, 71680);
        cudaFuncSetAttribute(wo_tc, cudaFuncAttributeMaxDynamicSharedMemorySize, 55808);
        cudaFuncSetAttribute(kmat_tc, cudaFuncAttributeMaxDynamicSharedMemorySize, 108544);
        cudaFuncSetAttribute(kapply_mma, cudaFuncAttributeMaxDynamicSharedMemorySize, 55296);
        attr_done = true;
    }

    const int NTOT = S * D + 4 * D * D;
    cvt_all<<<(NTOT + 255) / 256, 256>>>(x, Wq, Wk, Wv, Wo);

    qkv_tc<<<dim3(D / 128, S / 128, 3), 256, 71680>>>();
    norms_diag<<<(H * S * 32 + 255) / 256, 256>>>(diag_scale, reg, bandwidth);
    transpose_k<<<dim3(S / 32, DH / 32, H), dim3(32, 8)>>>();
    kmat_tc<<<dim3(S / 128, H), 256, 108544>>>(bandwidth);
    u_kernel<<<dim3(S / 256, H), 256>>>(pos, proj);

    // Richardson iteration 1 (alpha = 0 => r = v)
    utr_kernel<<<dim3(H, 16), 1024>>>();
    update_kernel<<<dim3(S / 16, H), 1024>>>(1);

    // iterations 2..5: utr fused into kapply epilogue
    for (int it = 1; it < 5; it++) {
        kapply_mma<<<dim3(S / 128, H), 256, 55296>>>(0, lam);
        update_kernel<<<dim3(S / 16, H), 1024>>>(0);
    }

    kapply_mma<<<dim3(S / 128, H), 256, 55296>>>(1, lam);
    wo_tc<<<dim3(D / 64, S / 128), 256, 55808>>>(out);
}

// round 16
// speedup vs baseline: 1.0523x; 1.0015x over previous
#include <cuda_runtime.h>
#include <cuda_fp16.h>
#include <math.h>
#include <cstdint>

#define H 16
#define S 2048
#define D 1024
#define DH 64
#define RANK 16

// ---- tcgen05 availability: only in arch-specific (sm_103a/sm_100a) device passes
#if defined(__CUDA_ARCH__) && (defined(__CUDA_ARCH_FEAT_SM103_ALL) || \
    defined(__CUDA_ARCH_FEAT_SM100_ALL) || defined(__CUDA_ARCH_FEAT_SM101_ALL) || \
    (defined(__CUDA_ARCH_SPECIFIC__) && (__CUDA_ARCH_SPECIFIC__ >= 1000)))
#define HAS_TC 1
#else
#define HAS_TC 0
#endif

// ---------------- scratch (device globals; no allocation allowed) ----------------
__device__ float g_q[H * S * DH];
__device__ float g_k[H * S * DH];
__device__ float g_v[H * S * DH];
__device__ float g_alpha[H * S * DH];
__device__ __half g_alphaH[H * S * DH];
__device__ __half g_alphaT[H * DH * S];          // transposed fp16 alpha (tcgen05 B op)
__device__ float g_r[H * S * DH];
__device__ __half g_ctxH[H * S * DH];   // normalized ctx = K'@alpha (hi)
__device__ __half g_ctxL[H * S * DH];   // normalized ctx (lo)
__device__ __half g_Kh[(size_t)H * S * S];       // 128 MB fp16 row-normalized kernel
__device__ float g_scale[H * S];                 // per-row scale exp(-dmin*inv)
__device__ float g_qn[H * S];
__device__ float g_kn[H * S];
__device__ float g_diagp[H * S];
__device__ float g_U[H * S * RANK];
__device__ float g_utr_part[16 * H * RANK * DH];   // 16 partial blocks (one per M tile)

// split fp16 operands
__device__ __half g_xh[S * D],  g_xl[S * D];
__device__ __half g_Wh[3 * D * D], g_Wl[3 * D * D];   // Wq, Wk, Wv
__device__ __half g_Woh[D * D], g_Wol[D * D];
__device__ __half g_qhh[H * S * DH], g_qll[H * S * DH];
__device__ __half g_khh[H * S * DH], g_kll[H * S * DH];
__device__ __half g_kTh[H * DH * S], g_kTl[H * DH * S];  // transposed k

__device__ __forceinline__ float softplusf(float x) {
    return (x > 20.f) ? x : log1pf(expf(x));
}

// ======================= HMMA helpers (mma.sync + ldmatrix) =======================
__device__ __forceinline__ uint32_t smem_u32(const void* p) {
    uint32_t a;
    asm("{ .reg .u64 t; cvta.to.shared.u64 t, %1; cvt.u32.u64 %0, t; }" : "=r"(a) : "l"(p));
    return a;
}
__device__ __forceinline__ void ldm_x4(uint32_t* r, uint32_t addr) {
    asm volatile("ldmatrix.sync.aligned.m8n8.x4.shared.b16 {%0,%1,%2,%3}, [%4];"
                 : "=r"(r[0]), "=r"(r[1]), "=r"(r[2]), "=r"(r[3]) : "r"(addr));
}
__device__ __forceinline__ void ldm_x4_trans(uint32_t* r, uint32_t addr) {
    asm volatile("ldmatrix.sync.aligned.m8n8.x4.trans.shared.b16 {%0,%1,%2,%3}, [%4];"
                 : "=r"(r[0]), "=r"(r[1]), "=r"(r[2]), "=r"(r[3]) : "r"(addr));
}
__device__ __forceinline__ void mma16816(float* c, const uint32_t* a, uint32_t b0, uint32_t b1) {
    asm volatile(
        "mma.sync.aligned.m16n8k16.row.col.f32.f16.f16.f32 "
        "{%0,%1,%2,%3}, {%4,%5,%6,%7}, {%8,%9}, {%0,%1,%2,%3};"
        : "+f"(c[0]), "+f"(c[1]), "+f"(c[2]), "+f"(c[3])
        : "r"(a[0]), "r"(a[1]), "r"(a[2]), "r"(a[3]), "r"(b0), "r"(b1));
}
__device__ __forceinline__ void cp_async16(uint32_t saddr, const void* gaddr) {
    asm volatile("cp.async.cg.shared.global [%0], [%1], 16;" :: "r"(saddr), "l"(gaddr) : "memory");
}

#if HAS_TC
// ======================= tcgen05 helpers (sm_103a cubin pass only) ================
#define SW128(o) ((o) ^ (((o) >> 3) & 0x70))
static constexpr uint64_t DESC_BASE_SW128 =
    (uint64_t(2) << 61) | (uint64_t(1) << 46) | (uint64_t(64) << 32) | (uint64_t(1) << 16);
__device__ __forceinline__ uint64_t make_desc(uint32_t addr) {
    return DESC_BASE_SW128 | ((uint64_t)(addr >> 4) & 0x3FFF);
}
// idesc kind::f16: dtype F32, atype=btype=FP16, N=64, M=128
#define IDESC_KA ((1u << 4) | ((64u / 8u) << 17) | ((128u / 16u) << 24))
__device__ __forceinline__ uint32_t elect_one() {
    uint32_t p;
    asm volatile("{ .reg .pred p; elect.sync _|p, 0xFFFFFFFF; selp.b32 %0, 1, 0, p; }" : "=r"(p));
    return p;
}
__device__ __forceinline__ void mbar_wait(uint32_t mb, uint32_t parity) {
    asm volatile(
        "{\n\t.reg .pred P1;\n\t"
        "W_%=:\n\t"
        "mbarrier.try_wait.parity.acquire.cta.shared::cta.b64 P1, [%0], %1, 0x989680;\n\t"
        "@P1 bra.uni D_%=;\n\t"
        "bra.uni W_%=;\n\t"
        "D_%=:\n\t}"
        :: "r"(mb), "r"(parity) : "memory");
}
__device__ __forceinline__ void mma_f16_ss(uint32_t d, uint64_t a, uint64_t b,
                                           uint32_t idesc, uint32_t en) {
    asm volatile(
        "{\n\t.reg .pred p;\n\t"
        "setp.ne.u32 p, %4, 0;\n\t"
        "tcgen05.mma.cta_group::1.kind::f16 [%0], %1, %2, %3, {%5, %5, %5, %5}, p;\n\t}"
        :: "r"(d), "l"(a), "l"(b), "r"(idesc), "r"(en), "r"(0u) : "memory");
}
__device__ __forceinline__ void ldtm_x32(uint32_t* r, uint32_t tm) {
    asm volatile(
        "tcgen05.ld.sync.aligned.32x32b.x32.b32 "
        "{%0,%1,%2,%3,%4,%5,%6,%7,%8,%9,%10,%11,%12,%13,%14,%15,"
        "%16,%17,%18,%19,%20,%21,%22,%23,%24,%25,%26,%27,%28,%29,%30,%31}, [%32];"
        : "=r"(r[0]), "=r"(r[1]), "=r"(r[2]), "=r"(r[3]), "=r"(r[4]), "=r"(r[5]), "=r"(r[6]), "=r"(r[7]),
          "=r"(r[8]), "=r"(r[9]), "=r"(r[10]), "=r"(r[11]), "=r"(r[12]), "=r"(r[13]), "=r"(r[14]), "=r"(r[15]),
          "=r"(r[16]), "=r"(r[17]), "=r"(r[18]), "=r"(r[19]), "=r"(r[20]), "=r"(r[21]), "=r"(r[22]), "=r"(r[23]),
          "=r"(r[24]), "=r"(r[25]), "=r"(r[26]), "=r"(r[27]), "=r"(r[28]), "=r"(r[29]), "=r"(r[30]), "=r"(r[31])
        : "r"(tm));
}
#define TC_ALLOC(smaddr, n)  asm volatile("tcgen05.alloc.cta_group::1.sync.aligned.shared::cta.b32 [%0], %1;" :: "r"(smaddr), "r"(n) : "memory")
#define TC_DEALLOC(tm, n)    asm volatile("tcgen05.dealloc.cta_group::1.sync.aligned.b32 %0, %1;" :: "r"(tm), "r"(n))
#define TC_RELINQ()          asm volatile("tcgen05.relinquish_alloc_permit.cta_group::1.sync.aligned;")
#define TC_COMMIT(mb)        asm volatile("tcgen05.commit.cta_group::1.mbarrier::arrive::one.shared::cluster.b64 [%0];" :: "r"(mb) : "memory")
#define TC_FENCE_AFTER()     asm volatile("tcgen05.fence::after_thread_sync;" ::: "memory")
#define TC_FENCE_BEFORE()    asm volatile("tcgen05.fence::before_thread_sync;" ::: "memory")
#define TC_WAIT_LD()         asm volatile("tcgen05.wait::ld.sync.aligned;" ::: "memory")
#define MBAR_INIT(mb, cnt)   asm volatile("mbarrier.init.shared.b64 [%0], %1;" :: "r"(mb), "r"(cnt) : "memory")
#define FENCE_ASYNC_SHARED() asm volatile("fence.proxy.async.shared::cta;" ::: "memory")
#endif

// ---------------- fp32 -> (hi, lo) fp16 split conversion (merged) -----------------
__global__ void cvt_all(const float* __restrict__ x, const float* __restrict__ wq,
                        const float* __restrict__ wk, const float* __restrict__ wv,
                        const float* __restrict__ wo) {
    int i = blockIdx.x * blockDim.x + threadIdx.x;
    const int NX = S * D, NW = D * D;
    const float* src;
    __half *hi, *lo;
    int off;
    if (i < NX)               { src = x;  hi = g_xh;           lo = g_xl;           off = i; }
    else if (i < NX + NW)     { src = wq; hi = g_Wh;           lo = g_Wl;           off = i - NX; }
    else if (i < NX + 2 * NW) { src = wk; hi = g_Wh + NW;      lo = g_Wl + NW;      off = i - NX - NW; }
    else if (i < NX + 3 * NW) { src = wv; hi = g_Wh + 2 * NW;  lo = g_Wl + 2 * NW;  off = i - NX - 2 * NW; }
    else if (i < NX + 4 * NW) { src = wo; hi = g_Woh;          lo = g_Wol;          off = i - NX - 3 * NW; }
    else return;
    float v = src[off];
    __half h = __float2half(v);
    hi[off] = h;
    lo[off] = __float2half(v - __half2float(h));
}

// ===== QKV split-fp16 tensor GEMM: C = x @ W_z, output heads layout + hi/lo =======
__global__ void __launch_bounds__(256) qkv_tc() {
    extern __shared__ __align__(16) char sm[];
    __half* Ah = (__half*)sm;                 // [128][72]
    __half* Alo = (__half*)(sm + 18432);
    __half* Bh = (__half*)(sm + 36864);       // [64][136]
    __half* Bl = (__half*)(sm + 54272);

    int tid = threadIdx.x, lane = tid & 31, wid = tid >> 5;
    int wm = wid >> 1, wn = wid & 1;
    int row0 = blockIdx.y * 128, col0 = blockIdx.x * 128;
    int which = blockIdx.z;
    const __half* Whp = g_Wh + (size_t)which * D * D;
    const __half* Wlp = g_Wl + (size_t)which * D * D;

    float acc[2][8][4];
#pragma unroll
    for (int i = 0; i < 2; i++)
#pragma unroll
        for (int j = 0; j < 8; j++)
#pragma unroll
            for (int l = 0; l < 4; l++) acc[i][j][l] = 0.f;

    uint32_t ah_b = smem_u32(Ah), al_b = smem_u32(Alo);
    uint32_t bh_b = smem_u32(Bh), bl_b = smem_u32(Bl);
    int lm = lane & 15, lh = lane >> 4;

    for (int k0 = 0; k0 < D; k0 += 64) {
#pragma unroll
        for (int e = 0; e < 4; e++) {
            int idx = tid + 256 * e;           // 0..1023
            int m = idx >> 3, c8 = idx & 7;
            *(uint4*)&Ah[m * 72 + c8 * 8]  = *(const uint4*)&g_xh[(size_t)(row0 + m) * D + k0 + c8 * 8];
            *(uint4*)&Alo[m * 72 + c8 * 8] = *(const uint4*)&g_xl[(size_t)(row0 + m) * D + k0 + c8 * 8];
            int kb = idx >> 4, c16 = idx & 15;
            *(uint4*)&Bh[kb * 136 + c16 * 8] = *(const uint4*)&Whp[(size_t)(k0 + kb) * D + col0 + c16 * 8];
            *(uint4*)&Bl[kb * 136 + c16 * 8] = *(const uint4*)&Wlp[(size_t)(k0 + kb) * D + col0 + c16 * 8];
        }
        __syncthreads();
#pragma unroll
        for (int kk = 0; kk < 64; kk += 16) {
            uint32_t a_h[2][4], a_l[2][4];
#pragma unroll
            for (int mt = 0; mt < 2; mt++) {
                ldm_x4(a_h[mt], ah_b + ((wm * 32 + mt * 16 + lm) * 72 + kk + lh * 8) * 2);
                ldm_x4(a_l[mt], al_b + ((wm * 32 + mt * 16 + lm) * 72 + kk + lh * 8) * 2);
            }
#pragma unroll
            for (int ng = 0; ng < 4; ng++) {
                uint32_t b_h[4], b_l[4];
                ldm_x4_trans(b_h, bh_b + ((kk + lm) * 136 + wn * 64 + ng * 16 + lh * 8) * 2);
                ldm_x4_trans(b_l, bl_b + ((kk + lm) * 136 + wn * 64 + ng * 16 + lh * 8) * 2);
#pragma unroll
                for (int mt = 0; mt < 2; mt++) {
                    mma16816(acc[mt][ng * 2 + 0], a_h[mt], b_h[0], b_h[1]);
                    mma16816(acc[mt][ng * 2 + 0], a_h[mt], b_l[0], b_l[1]);
                    mma16816(acc[mt][ng * 2 + 0], a_l[mt], b_h[0], b_h[1]);
                    mma16816(acc[mt][ng * 2 + 1], a_h[mt], b_h[2], b_h[3]);
                    mma16816(acc[mt][ng * 2 + 1], a_h[mt], b_l[2], b_l[3]);
                    mma16816(acc[mt][ng * 2 + 1], a_l[mt], b_h[2], b_h[3]);
                }
            }
        }
        __syncthreads();
    }

    float* outF = (which == 0) ? g_q : (which == 1) ? g_k : g_v;
    __half* oh = (which == 0) ? g_qhh : g_khh;
    __half* ol = (which == 0) ? g_qll : g_kll;
#pragma unroll
    for (int mt = 0; mt < 2; mt++) {
        int r0 = row0 + wm * 32 + mt * 16 + (lane >> 2);
#pragma unroll
        for (int nt = 0; nt < 8; nt++) {
            int c = col0 + wn * 64 + nt * 8 + (lane & 3) * 2;
            int hh = c >> 6, dh = c & 63;
#pragma unroll
            for (int rr = 0; rr < 2; rr++) {
                int s = r0 + rr * 8;
                float v0 = acc[mt][nt][rr * 2 + 0], v1 = acc[mt][nt][rr * 2 + 1];
                size_t gi = ((size_t)hh * S + s) * DH + dh;
                *(float2*)&outF[gi] = make_float2(v0, v1);
                if (which < 2) {
                    __half h0 = __float2half(v0), h1 = __float2half(v1);
                    *(__half2*)&oh[gi] = __halves2half2(h0, h1);
                    *(__half2*)&ol[gi] = __halves2half2(
                        __float2half(v0 - __half2float(h0)),
                        __float2half(v1 - __half2float(h1)));
                }
            }
        }
    }
}

// ---------------- fused: row norms of q,k + diag_p (one 16MB pass) ----------------
__global__ void norms_diag(const float* __restrict__ diag_scale,
                           const float* __restrict__ reg_p,
                           const float* __restrict__ bw_p) {
    int gw = (blockIdx.x * blockDim.x + threadIdx.x) >> 5;
    int lane = threadIdx.x & 31;
    if (gw >= H * S) return;
    const float* qp = g_q + (size_t)gw * DH;
    const float* kp = g_k + (size_t)gw * DH;
    float qa = qp[lane], qb = qp[lane + 32];
    float ka = kp[lane], kb = kp[lane + 32];
    float qn = qa * qa + qb * qb;
    float kn = ka * ka + kb * kb;
    float da = qa - ka, db = qb - kb;
    float dd = da * da + db * db;
#pragma unroll
    for (int o = 16; o > 0; o >>= 1) {
        qn += __shfl_xor_sync(0xffffffffu, qn, o);
        kn += __shfl_xor_sync(0xffffffffu, kn, o);
        dd += __shfl_xor_sync(0xffffffffu, dd, o);
    }
    if (lane == 0) {
        g_qn[gw] = qn;
        g_kn[gw] = kn;
        float bw = softplusf(bw_p[0]) + 1e-6f;
        float inv = 1.0f / (2.0f * bw * bw);
        float kd = __expf(-dd * inv);
        g_diagp[gw] = softplusf(kd) * diag_scale[gw / S] + reg_p[0];
    }
}

// ---------------- transpose k hi/lo: [h][s][dh] -> [h][dh][s] ----------------------
__global__ void transpose_k() {
    __shared__ __half t0[32][33];
    __shared__ __half t1[32][33];
    int h = blockIdx.z;
    int s0 = blockIdx.x * 32, d0 = blockIdx.y * 32;
    int tx = threadIdx.x, ty = threadIdx.y;   // 32 x 8
#pragma unroll
    for (int i = 0; i < 32; i += 8) {
        t0[ty + i][tx] = g_khh[((size_t)h * S + s0 + ty + i) * DH + d0 + tx];
        t1[ty + i][tx] = g_kll[((size_t)h * S + s0 + ty + i) * DH + d0 + tx];
    }
    __syncthreads();
#pragma unroll
    for (int i = 0; i < 32; i += 8) {
        g_kTh[((size_t)h * DH + d0 + ty + i) * S + s0 + tx] = t0[tx][ty + i];
        g_kTl[((size_t)h * DH + d0 + ty + i) * S + s0 + tx] = t1[tx][ty + i];
    }
}

// ===== fused kmat (FULL phase1, cp.async double-buffered B tiles) =================
__global__ void __launch_bounds__(256) kmat_tc(const float* __restrict__ bw_p) {
    extern __shared__ __align__(16) char sm[];
    __half* Qh = (__half*)sm;                 // [128][72] 18432
    __half* Ql = (__half*)(sm + 18432);       // 18432
    float* qn_s = (float*)(sm + 106496);      // 512
    float* kn_p0 = (float*)(sm + 107008);     // 512
    float* kn_p1 = (float*)(sm + 107520);     // 512
    unsigned* minv = (unsigned*)(sm + 108032);// 512   -> total 108544

    uint32_t base = smem_u32(sm);
    uint32_t bhB[2] = {base + 36864u, base + 71680u};
    uint32_t blB[2] = {base + 54272u, base + 89088u};
    uint32_t knB[2] = {base + 107008u, base + 107520u};
    float* kn_p[2] = {kn_p0, kn_p1};

    int tid = threadIdx.x, lane = tid & 31, wid = tid >> 5;
    int h = blockIdx.y, i0 = blockIdx.x * 128;
    float bw = softplusf(bw_p[0]) + 1e-6f;
    float inv = 1.0f / (2.0f * bw * bw);

#pragma unroll
    for (int e = 0; e < 4; e++) {
        int idx = tid + 256 * e;
        int m = idx >> 3, c8 = idx & 7;
        *(uint4*)&Qh[m * 72 + c8 * 8] = *(const uint4*)&g_qhh[((size_t)h * S + i0 + m) * DH + c8 * 8];
        *(uint4*)&Ql[m * 72 + c8 * 8] = *(const uint4*)&g_qll[((size_t)h * S + i0 + m) * DH + c8 * 8];
    }
    if (tid < 128) {
        qn_s[tid] = g_qn[h * S + i0 + tid];
        minv[tid] = 0x7F800000u;
    }
    __syncthreads();

    uint32_t qh_b = smem_u32(Qh), ql_b = smem_u32(Ql);
    int lm = lane & 15, lh = lane >> 4;

    const __half* kThp = g_kTh + (size_t)h * DH * S;
    const __half* kTlp = g_kTl + (size_t)h * DH * S;

    float rmin[16];
#pragma unroll
    for (int i = 0; i < 16; i++) rmin[i] = 3.4e38f;

    // ---------------- phase 1: hi-only dist over ALL columns (pipelined) ----------
    {
#pragma unroll
        for (int e = 0; e < 4; e++) {
            int idx = tid + 256 * e;
            int kb = idx >> 4, c16 = idx & 15;
            cp_async16(bhB[0] + (uint32_t)(kb * 272 + c16 * 16),
                       kThp + (size_t)kb * S + c16 * 8);
        }
        if (tid < 32)
            cp_async16(knB[0] + (uint32_t)(tid * 16), &g_kn[h * S + tid * 4]);
        asm volatile("cp.async.commit_group;" ::: "memory");
    }

    for (int c = 0; c < 16; c++) {
        int st = c & 1;
        if (c < 15) {
            int j0n = (c + 1) * 128;
            int sn = st ^ 1;
#pragma unroll
            for (int e = 0; e < 4; e++) {
                int idx = tid + 256 * e;
                int kb = idx >> 4, c16 = idx & 15;
                cp_async16(bhB[sn] + (uint32_t)(kb * 272 + c16 * 16),
                           kThp + (size_t)kb * S + j0n + c16 * 8);
            }
            if (tid < 32)
                cp_async16(knB[sn] + (uint32_t)(tid * 16), &g_kn[h * S + j0n + tid * 4]);
            asm volatile("cp.async.commit_group;" ::: "memory");
            asm volatile("cp.async.wait_group 1;" ::: "memory");
        } else {
            asm volatile("cp.async.wait_group 0;" ::: "memory");
        }
        __syncthreads();

        uint32_t bf[4][4];
#pragma unroll
        for (int k4 = 0; k4 < 4; k4++)
            ldm_x4_trans(bf[k4], bhB[st] + (uint32_t)(((k4 * 16 + lm) * 136 + wid * 16 + lh * 8) * 2));

        const float* kns = kn_p[st];
#pragma unroll
        for (int mt = 0; mt < 8; mt++) {
            float a0[4] = {0.f, 0.f, 0.f, 0.f}, a1[4] = {0.f, 0.f, 0.f, 0.f};
#pragma unroll
            for (int k4 = 0; k4 < 4; k4++) {
                uint32_t a[4];
                ldm_x4(a, qh_b + ((mt * 16 + lm) * 72 + k4 * 16 + lh * 8) * 2);
                mma16816(a0, a, bf[k4][0], bf[k4][1]);
                mma16816(a1, a, bf[k4][2], bf[k4][3]);
            }
            int r = mt * 16 + (lane >> 2);
            float qn0 = qn_s[r], qn1 = qn_s[r + 8];
            int cb = wid * 16 + (lane & 3) * 2;
            float kn0 = kns[cb], kn1 = kns[cb + 1], kn8 = kns[cb + 8], kn9 = kns[cb + 9];
            float d0 = fminf(fminf(qn0 + kn0 - 2.f * a0[0], qn0 + kn1 - 2.f * a0[1]),
                             fminf(qn0 + kn8 - 2.f * a1[0], qn0 + kn9 - 2.f * a1[1]));
            float d1 = fminf(fminf(qn1 + kn0 - 2.f * a0[2], qn1 + kn1 - 2.f * a0[3]),
                             fminf(qn1 + kn8 - 2.f * a1[2], qn1 + kn9 - 2.f * a1[3]));
            rmin[mt * 2] = fminf(rmin[mt * 2], d0);
            rmin[mt * 2 + 1] = fminf(rmin[mt * 2 + 1], d1);
        }
        __syncthreads();
    }
#pragma unroll
    for (int i = 0; i < 16; i++) {
        rmin[i] = fminf(rmin[i], __shfl_xor_sync(0xffffffffu, rmin[i], 1));
        rmin[i] = fminf(rmin[i], __shfl_xor_sync(0xffffffffu, rmin[i], 2));
    }
    if ((lane & 3) == 0) {
#pragma unroll
        for (int mt = 0; mt < 8; mt++) {
            atomicMin(&minv[mt * 16 + (lane >> 2)], __float_as_uint(fmaxf(rmin[mt * 2], 0.f)));
            atomicMin(&minv[mt * 16 + (lane >> 2) + 8], __float_as_uint(fmaxf(rmin[mt * 2 + 1], 0.f)));
        }
    }
    __syncthreads();
    if (tid < 128)
        g_scale[h * S + i0 + tid] = __expf(-__uint_as_float(minv[tid]) * inv);

    // ---------------- phase 2: split dist, exp -> Kh fp16 (pipelined) -------------
    {
#pragma unroll
        for (int e = 0; e < 4; e++) {
            int idx = tid + 256 * e;
            int kb = idx >> 4, c16 = idx & 15;
            cp_async16(bhB[0] + (uint32_t)(kb * 272 + c16 * 16),
                       kThp + (size_t)kb * S + c16 * 8);
            cp_async16(blB[0] + (uint32_t)(kb * 272 + c16 * 16),
                       kTlp + (size_t)kb * S + c16 * 8);
        }
        if (tid < 32)
            cp_async16(knB[0] + (uint32_t)(tid * 16), &g_kn[h * S + tid * 4]);
        asm volatile("cp.async.commit_group;" ::: "memory");
    }

    for (int c = 0; c < 16; c++) {
        int st = c & 1;
        int j0 = c * 128;
        if (c < 15) {
            int j0n = (c + 1) * 128;
            int sn = st ^ 1;
#pragma unroll
            for (int e = 0; e < 4; e++) {
                int idx = tid + 256 * e;
                int kb = idx >> 4, c16 = idx & 15;
                cp_async16(bhB[sn] + (uint32_t)(kb * 272 + c16 * 16),
                           kThp + (size_t)kb * S + j0n + c16 * 8);
                cp_async16(blB[sn] + (uint32_t)(kb * 272 + c16 * 16),
                           kTlp + (size_t)kb * S + j0n + c16 * 8);
            }
            if (tid < 32)
                cp_async16(knB[sn] + (uint32_t)(tid * 16), &g_kn[h * S + j0n + tid * 4]);
            asm volatile("cp.async.commit_group;" ::: "memory");
            asm volatile("cp.async.wait_group 1;" ::: "memory");
        } else {
            asm volatile("cp.async.wait_group 0;" ::: "memory");
        }
        __syncthreads();

        uint32_t bfh[4][4], bfl[4][4];
#pragma unroll
        for (int k4 = 0; k4 < 4; k4++) {
            ldm_x4_trans(bfh[k4], bhB[st] + (uint32_t)(((k4 * 16 + lm) * 136 + wid * 16 + lh * 8) * 2));
            ldm_x4_trans(bfl[k4], blB[st] + (uint32_t)(((k4 * 16 + lm) * 136 + wid * 16 + lh * 8) * 2));
        }

        const float* kns = kn_p[st];
#pragma unroll
        for (int mt = 0; mt < 8; mt++) {
            float a0[4] = {0.f, 0.f, 0.f, 0.f}, a1[4] = {0.f, 0.f, 0.f, 0.f};
#pragma unroll
            for (int k4 = 0; k4 < 4; k4++) {
                uint32_t ah[4], al[4];
                ldm_x4(ah, qh_b + ((mt * 16 + lm) * 72 + k4 * 16 + lh * 8) * 2);
                ldm_x4(al, ql_b + ((mt * 16 + lm) * 72 + k4 * 16 + lh * 8) * 2);
                mma16816(a0, ah, bfh[k4][0], bfh[k4][1]);
                mma16816(a0, ah, bfl[k4][0], bfl[k4][1]);
                mma16816(a0, al, bfh[k4][0], bfh[k4][1]);
                mma16816(a1, ah, bfh[k4][2], bfh[k4][3]);
                mma16816(a1, ah, bfl[k4][2], bfl[k4][3]);
                mma16816(a1, al, bfh[k4][2], bfh[k4][3]);
            }
            int r = mt * 16 + (lane >> 2);
            float qn0 = qn_s[r], qn1 = qn_s[r + 8];
            float dm0 = __uint_as_float(minv[r]), dm1 = __uint_as_float(minv[r + 8]);
            int cb = wid * 16 + (lane & 3) * 2;
            float kn0 = kns[cb], kn1 = kns[cb + 1], kn8 = kns[cb + 8], kn9 = kns[cb + 9];
            float e00 = __expf((dm0 - fmaxf(qn0 + kn0 - 2.f * a0[0], 0.f)) * inv);
            float e01 = __expf((dm0 - fmaxf(qn0 + kn1 - 2.f * a0[1], 0.f)) * inv);
            float e10 = __expf((dm1 - fmaxf(qn1 + kn0 - 2.f * a0[2], 0.f)) * inv);
            float e11 = __expf((dm1 - fmaxf(qn1 + kn1 - 2.f * a0[3], 0.f)) * inv);
            float f00 = __expf((dm0 - fmaxf(qn0 + kn8 - 2.f * a1[0], 0.f)) * inv);
            float f01 = __expf((dm0 - fmaxf(qn0 + kn9 - 2.f * a1[1], 0.f)) * inv);
            float f10 = __expf((dm1 - fmaxf(qn1 + kn8 - 2.f * a1[2], 0.f)) * inv);
            float f11 = __expf((dm1 - fmaxf(qn1 + kn9 - 2.f * a1[3], 0.f)) * inv);
            __half* Kp0 = &g_Kh[((size_t)(h * S + i0 + r)) * S + j0 + cb];
            __half* Kp1 = Kp0 + (size_t)8 * S;
            *(__half2*)Kp0 = __halves2half2(__float2half(e00), __float2half(e01));
            *(__half2*)(Kp0 + 8) = __halves2half2(__float2half(f00), __float2half(f01));
            *(__half2*)Kp1 = __halves2half2(__float2half(e10), __float2half(e11));
            *(__half2*)(Kp1 + 8) = __halves2half2(__float2half(f10), __float2half(f11));
        }
        __syncthreads();
    }
}

// ---------------- U[h,s,r] = sum_rp pos[s,rp] * proj[h,rp,r] ----------------------
__global__ void u_kernel(const float* __restrict__ pos, const float* __restrict__ proj) {
    __shared__ float pr[RANK][RANK];
    int h = blockIdx.y;
    int tid = threadIdx.x;
    pr[tid >> 4][tid & 15] = proj[h * RANK * RANK + tid];
    __syncthreads();
    int s = blockIdx.x * 256 + tid;
    float pe[RANK];
#pragma unroll
    for (int r = 0; r < RANK; r++) pe[r] = pos[(size_t)s * RANK + r];
#pragma unroll
    for (int r = 0; r < RANK; r++) {
        float acc = 0.f;
#pragma unroll
        for (int rp = 0; rp < RANK; rp++) acc += pe[rp] * pr[rp][r];
        g_U[((size_t)h * S + s) * RANK + r] = acc;
    }
}

// == K@alpha: tcgen05 (arch-specific pass) or HMMA fallback; fused U^T r partials ==
// mode0: r = v - scale*K'a - lam*a, writes g_r AND utr_part[blockIdx.x]
// mode1: store NORMALIZED K'a hi/lo
__global__ void __launch_bounds__(256) kapply_mma(int mode, const float* __restrict__ lam_p) {
#if HAS_TC
    extern __shared__ __align__(16) char smraw[];
    uint32_t rawb = smem_u32(smraw);
    uint32_t abase = (rawb + 1023u) & ~1023u;
    char* smA = smraw + (abase - rawb);
    uint32_t A0 = abase, A1 = abase + 16384;
    uint32_t B0 = abase + 32768, B1 = abase + 40960;
    uint32_t ctrl = abase + 49152, mbar = abase + 49160;

    int tid = threadIdx.x, wid = tid >> 5, lane = tid & 31;
    int h = blockIdx.y;
    int s0 = blockIdx.x * 128;

    if (wid == 0) { TC_ALLOC(ctrl, 64); TC_RELINQ(); }
    if (tid == 0) MBAR_INIT(mbar, 1);
    __syncthreads();
    uint32_t tmem;
    asm volatile("ld.shared.b32 %0, [%1];" : "=r"(tmem) : "r"(ctrl));

    const __half* Kb = g_Kh + ((size_t)h * S + s0) * S;
    const __half* Tb = g_alphaT + (size_t)h * DH * S;

    {
#pragma unroll
        for (int e = 0; e < 4; e++) {
            int idx = tid + 256 * e;
            int m = idx >> 3, c16 = idx & 7;
            cp_async16(A0 + SW128((uint32_t)(m * 128 + c16 * 16)), Kb + (size_t)m * S + c16 * 8);
        }
#pragma unroll
        for (int e = 0; e < 2; e++) {
            int idx = tid + 256 * e;
            int m = idx >> 3, c16 = idx & 7;
            cp_async16(B0 + SW128((uint32_t)(m * 128 + c16 * 16)), Tb + (size_t)m * S + c16 * 8);
        }
        asm volatile("cp.async.commit_group;" ::: "memory");
    }

    for (int c = 0; c < 32; c++) {
        uint32_t Ac = (c & 1) ? A1 : A0, Bc = (c & 1) ? B1 : B0;
        if (c >= 1) mbar_wait(mbar, (uint32_t)((c - 1) & 1));
        if (c + 1 < 32) {
            uint32_t An = (c & 1) ? A0 : A1, Bn = (c & 1) ? B0 : B1;
            int t0 = (c + 1) * 64;
#pragma unroll
            for (int e = 0; e < 4; e++) {
                int idx = tid + 256 * e;
                int m = idx >> 3, c16 = idx & 7;
                cp_async16(An + SW128((uint32_t)(m * 128 + c16 * 16)), Kb + (size_t)m * S + t0 + c16 * 8);
            }
#pragma unroll
            for (int e = 0; e < 2; e++) {
                int idx = tid + 256 * e;
                int m = idx >> 3, c16 = idx & 7;
                cp_async16(Bn + SW128((uint32_t)(m * 128 + c16 * 16)), Tb + (size_t)m * S + t0 + c16 * 8);
            }
            asm volatile("cp.async.commit_group;" ::: "memory");
            asm volatile("cp.async.wait_group 1;" ::: "memory");
        } else {
            asm volatile("cp.async.wait_group 0;" ::: "memory");
        }
        __syncthreads();
        FENCE_ASYNC_SHARED();
        if (wid == 0 && elect_one()) {
            uint64_t ad = make_desc(Ac), bd = make_desc(Bc);
            mma_f16_ss(tmem, ad + 0, bd + 0, IDESC_KA, (c > 0) ? 1u : 0u);
            mma_f16_ss(tmem, ad + 2, bd + 2, IDESC_KA, 1u);
            mma_f16_ss(tmem, ad + 4, bd + 4, IDESC_KA, 1u);
            mma_f16_ss(tmem, ad + 6, bd + 6, IDESC_KA, 1u);
            TC_COMMIT(mbar);
        }
    }

    mbar_wait(mbar, 1u);
    TC_FENCE_AFTER();

    float* rsm = (float*)smA;
    float* Usm = (float*)(smA + 33280);
    if (wid < 4) {
        uint32_t dr[64];
        ldtm_x32(dr, tmem);
        ldtm_x32(dr + 32, tmem + 32);
        TC_WAIT_LD();
        TC_FENCE_BEFORE();
        int m = wid * 32 + lane;
#pragma unroll
        for (int cc = 0; cc < 64; cc++) rsm[m * 65 + cc] = __uint_as_float(dr[cc]);
    }
    __syncthreads();
    if (wid == 0) TC_DEALLOC(tmem, 64);

    if (mode == 0) {
        float lam = softplusf(lam_p[0]);
#pragma unroll
        for (int e = 0; e < 8; e++) {
            int idx = tid + 256 * e;
            int m2 = idx >> 4, rr = idx & 15;
            Usm[m2 * 16 + rr] = g_U[((size_t)h * S + s0 + m2) * RANK + rr];
        }
        for (int e = 0; e < 32; e++) {
            int idx = tid + 256 * e;
            int m = idx >> 6, d0 = idx & 63;
            int s = s0 + m;
            size_t gi = ((size_t)h * S + s) * DH + d0;
            float Dv = rsm[m * 65 + d0];
            float rv = g_v[gi] - g_scale[h * S + s] * Dv - lam * g_alpha[gi];
            g_r[gi] = rv;
            rsm[m * 65 + d0] = rv;
        }
        __syncthreads();

        int d = tid & 63, rg = tid >> 6;
        float a4[4] = {0.f, 0.f, 0.f, 0.f};
        for (int s2 = 0; s2 < 128; s2++) {
            float rv = rsm[s2 * 65 + d];
            a4[0] += Usm[s2 * 16 + rg] * rv;
            a4[1] += Usm[s2 * 16 + rg + 4] * rv;
            a4[2] += Usm[s2 * 16 + rg + 8] * rv;
            a4[3] += Usm[s2 * 16 + rg + 12] * rv;
        }
        int part = blockIdx.x;
#pragma unroll
        for (int i = 0; i < 4; i++)
            g_utr_part[(((size_t)part * H + h) * RANK + (rg + 4 * i)) * DH + d] = a4[i];
    } else {
        for (int e = 0; e < 32; e++) {
            int idx = tid + 256 * e;
            int m = idx >> 6, d0 = idx & 63;
            size_t gi = ((size_t)h * S + s0 + m) * DH + d0;
            float cN = rsm[m * 65 + d0];
            __half hh = __float2half(cN);
            g_ctxH[gi] = hh;
            g_ctxL[gi] = __float2half(cN - __half2float(hh));
        }
    }
#else
    // ===== HMMA fallback: 4x2 warp layout (wo_tc-proven fragment structure) =======
    extern __shared__ __align__(16) char sm[];
    uint32_t base = smem_u32(sm);
    uint32_t ksb0 = base, ksb1 = base + 18432;
    uint32_t alb0 = base + 36864, alb1 = base + 46080;

    int tid = threadIdx.x, wid = tid >> 5, lane = tid & 31;
    int wm = wid >> 1, wn = wid & 1;      // 4 M-quarters x 2 N-halves
    int h = blockIdx.y;
    int s0 = blockIdx.x * 128;

    const __half* Kb = g_Kh + ((size_t)h * S + s0) * S;
    const __half* Ab = g_alphaH + (size_t)h * S * DH;

    float acc[2][4][4];
#pragma unroll
    for (int i = 0; i < 2; i++)
#pragma unroll
        for (int j = 0; j < 4; j++)
#pragma unroll
            for (int l = 0; l < 4; l++) acc[i][j][l] = 0.f;

    int lm = lane & 15, lh = lane >> 4;
    int mA = tid >> 3, c8A = tid & 7;

    {
        int t0 = 0;
#pragma unroll
        for (int e = 0; e < 4; e++) {
            int m = mA + 32 * e;
            cp_async16(ksb0 + (uint32_t)(m * 144 + c8A * 16), Kb + (size_t)m * S + t0 + c8A * 8);
        }
#pragma unroll
        for (int e = 0; e < 2; e++) {
            int t = mA + 32 * e;
            cp_async16(alb0 + (uint32_t)(t * 144 + c8A * 16), Ab + (size_t)(t0 + t) * DH + c8A * 8);
        }
        asm volatile("cp.async.commit_group;" ::: "memory");
    }

    for (int c = 0; c < 32; c++) {
        uint32_t ks_cur = (c & 1) ? ksb1 : ksb0;
        uint32_t al_cur = (c & 1) ? alb1 : alb0;
        if (c < 31) {
            uint32_t ks_nxt = (c & 1) ? ksb0 : ksb1;
            uint32_t al_nxt = (c & 1) ? alb0 : alb1;
            int t0 = (c + 1) * 64;
#pragma unroll
            for (int e = 0; e < 4; e++) {
                int m = mA + 32 * e;
                cp_async16(ks_nxt + (uint32_t)(m * 144 + c8A * 16), Kb + (size_t)m * S + t0 + c8A * 8);
            }
#pragma unroll
            for (int e = 0; e < 2; e++) {
                int t = mA + 32 * e;
                cp_async16(al_nxt + (uint32_t)(t * 144 + c8A * 16), Ab + (size_t)(t0 + t) * DH + c8A * 8);
            }
            asm volatile("cp.async.commit_group;" ::: "memory");
            asm volatile("cp.async.wait_group 1;" ::: "memory");
        } else {
            asm volatile("cp.async.wait_group 0;" ::: "memory");
        }
        __syncthreads();

#pragma unroll
        for (int kk = 0; kk < 64; kk += 16) {
            uint32_t a[2][4];
#pragma unroll
            for (int mt = 0; mt < 2; mt++)
                ldm_x4(a[mt], ks_cur + (uint32_t)(((wm * 32 + mt * 16 + lm) * 72 + kk + lh * 8) * 2));
#pragma unroll
            for (int ng = 0; ng < 2; ng++) {
                uint32_t b[4];
                ldm_x4_trans(b, al_cur + (uint32_t)(((kk + lm) * 72 + wn * 32 + ng * 16 + lh * 8) * 2));
#pragma unroll
                for (int mt = 0; mt < 2; mt++) {
                    mma16816(acc[mt][ng * 2 + 0], a[mt], b[0], b[1]);
                    mma16816(acc[mt][ng * 2 + 1], a[mt], b[2], b[3]);
                }
            }
        }
        __syncthreads();
    }

    if (mode == 0) {
        float lam = softplusf(lam_p[0]);
        float* rsm = (float*)sm;              // [128][65] = 33280 B (buffers dead)
        float* Usm = (float*)(sm + 33280);    // [128][16] =  8192 B
#pragma unroll
        for (int e = 0; e < 8; e++) {
            int idx = tid + 256 * e;
            int m = idx >> 4, rr = idx & 15;
            Usm[m * 16 + rr] = g_U[((size_t)h * S + s0 + m) * RANK + rr];
        }
#pragma unroll
        for (int mt = 0; mt < 2; mt++) {
            int rl = wm * 32 + mt * 16 + (lane >> 2);
            int rbase = s0 + rl;
            float sc0 = g_scale[h * S + rbase];
            float sc1 = g_scale[h * S + rbase + 8];
#pragma unroll
            for (int nt = 0; nt < 4; nt++) {
                int col = wn * 32 + nt * 8 + (lane & 3) * 2;
                size_t g0 = ((size_t)h * S + rbase) * DH + col;
                size_t g1 = g0 + 8 * DH;
                float2 v0 = *(const float2*)&g_v[g0];
                float2 v1 = *(const float2*)&g_v[g1];
                float2 a0 = *(const float2*)&g_alpha[g0];
                float2 a1 = *(const float2*)&g_alpha[g1];
                float r00 = v0.x - sc0 * acc[mt][nt][0] - lam * a0.x;
                float r01 = v0.y - sc0 * acc[mt][nt][1] - lam * a0.y;
                float r10 = v1.x - sc1 * acc[mt][nt][2] - lam * a1.x;
                float r11 = v1.y - sc1 * acc[mt][nt][3] - lam * a1.y;
                *(float2*)&g_r[g0] = make_float2(r00, r01);
                *(float2*)&g_r[g1] = make_float2(r10, r11);
                rsm[rl * 65 + col] = r00;
                rsm[rl * 65 + col + 1] = r01;
                rsm[(rl + 8) * 65 + col] = r10;
                rsm[(rl + 8) * 65 + col + 1] = r11;
            }
        }
        __syncthreads();

        int d = tid & 63, rg = tid >> 6;
        float a4[4] = {0.f, 0.f, 0.f, 0.f};
        for (int s = 0; s < 128; s++) {
            float rv = rsm[s * 65 + d];
            a4[0] += Usm[s * 16 + rg] * rv;
            a4[1] += Usm[s * 16 + rg + 4] * rv;
            a4[2] += Usm[s * 16 + rg + 8] * rv;
            a4[3] += Usm[s * 16 + rg + 12] * rv;
        }
        int part = blockIdx.x;
#pragma unroll
        for (int i = 0; i < 4; i++)
            g_utr_part[(((size_t)part * H + h) * RANK + (rg + 4 * i)) * DH + d] = a4[i];
    } else {
#pragma unroll
        for (int mt = 0; mt < 2; mt++) {
            int rl = wm * 32 + mt * 16 + (lane >> 2);
            int rbase = s0 + rl;
#pragma unroll
            for (int nt = 0; nt < 4; nt++) {
                int col = wn * 32 + nt * 8 + (lane & 3) * 2;
                size_t g0 = ((size_t)h * S + rbase) * DH + col;
                size_t g1 = g0 + 8 * DH;
                float c00 = acc[mt][nt][0], c01 = acc[mt][nt][1];
                float c10 = acc[mt][nt][2], c11 = acc[mt][nt][3];
                __half h00 = __float2half(c00), h01 = __float2half(c01);
                __half h10 = __float2half(c10), h11 = __float2half(c11);
                *(__half2*)&g_ctxH[g0] = __halves2half2(h00, h01);
                *(__half2*)&g_ctxH[g1] = __halves2half2(h10, h11);
                *(__half2*)&g_ctxL[g0] = __halves2half2(__float2half(c00 - __half2float(h00)),
                                                        __float2half(c01 - __half2float(h01)));
                *(__half2*)&g_ctxL[g1] = __halves2half2(__float2half(c10 - __half2float(h10)),
                                                        __float2half(c11 - __half2float(h11)));
            }
        }
    }
#endif
}

// ------- utr_part[p,h,r,d] = sum_{s in part} U[h,s,r] * v[h,s,d] (iter 1 only) ----
__global__ void utr_kernel() {
    int h = blockIdx.x;
    int part = blockIdx.y;     // 0..15
    int tid = threadIdx.x;
    int d = tid & 63, rr = tid >> 6;
    const float* Ub = g_U + (size_t)h * S * RANK;
    const float* rb = g_v + (size_t)h * S * DH;
    int s0 = part * (S / 16);
    float a0 = 0, a1 = 0, a2 = 0, a3 = 0;
    for (int s = s0; s < s0 + S / 16; s += 4) {
        a0 += Ub[(s + 0) * RANK + rr] * rb[(size_t)(s + 0) * DH + d];
        a1 += Ub[(s + 1) * RANK + rr] * rb[(size_t)(s + 1) * DH + d];
        a2 += Ub[(s + 2) * RANK + rr] * rb[(size_t)(s + 2) * DH + d];
        a3 += Ub[(s + 3) * RANK + rr] * rb[(size_t)(s + 3) * DH + d];
    }
    g_utr_part[((part * H + h) * RANK + rr) * DH + d] = (a0 + a1) + (a2 + a3);
}

// -------- alpha = prev + r*diag_p + U @ utr; emit fp16 mirror + transposed --------
__global__ void update_kernel(int first) {
    __shared__ float ut[RANK][DH];
    __shared__ float Us[16][RANK];
    __shared__ __half aT[64][18];
    int h = blockIdx.y;
    int tid = threadIdx.x;
    {
        float sum = 0.f;
#pragma unroll
        for (int p = 0; p < 16; p++) sum += g_utr_part[(p * H + h) * RANK * DH + tid];
        ut[tid >> 6][tid & 63] = sum;
    }
    int s0 = blockIdx.x * 16;
    if (tid < 16 * RANK)
        Us[tid >> 4][tid & 15] = g_U[((size_t)h * S + s0 + (tid >> 4)) * RANK + (tid & 15)];
    __syncthreads();

    int sl = tid >> 6;
    int d = tid & 63;
    int s = s0 + sl;
    size_t idx = ((size_t)h * S + s) * DH + d;
    float acc = 0.f;
#pragma unroll
    for (int r2 = 0; r2 < RANK; r2++) acc += Us[sl][r2] * ut[r2][d];
    float rv = first ? g_v[idx] : g_r[idx];
    float prev = first ? 0.f : g_alpha[idx];
    float na = prev + rv * g_diagp[h * S + s] + acc;
    g_alpha[idx] = na;
    __half nah = __float2half(na);
    g_alphaH[idx] = nah;
    aT[d][sl] = nah;
    __syncthreads();
    if (tid < 512) {
        int dd = tid >> 3, i = tid & 7;
        __half2 v2 = __halves2half2(aT[dd][i * 2], aT[dd][i * 2 + 1]);
        *(__half2*)&g_alphaT[((size_t)h * DH + dd) * S + s0 + i * 2] = v2;
    }
}

// == output GEMM (128x64 tiles): out = (scale ⊙ ctxN)_flat @ Wo ====================
__global__ void __launch_bounds__(256) wo_tc(float* __restrict__ out) {
    extern __shared__ __align__(16) char sm[];
    __half* Ah = (__half*)sm;                 // [128][72]
    __half* Alo = (__half*)(sm + 18432);
    __half* Bh = (__half*)(sm + 36864);       // [64][72]
    __half* Bl = (__half*)(sm + 46080);
    float* scs = (float*)(sm + 55296);        // 128 row scales

    int tid = threadIdx.x, lane = tid & 31, wid = tid >> 5;
    int wm = wid >> 1, wn = wid & 1;
    int row0 = blockIdx.y * 128, col0 = blockIdx.x * 64;

    float acc[2][4][4];
#pragma unroll
    for (int i = 0; i < 2; i++)
#pragma unroll
        for (int j = 0; j < 4; j++)
#pragma unroll
            for (int l = 0; l < 4; l++) acc[i][j][l] = 0.f;

    uint32_t ah_b = smem_u32(Ah), al_b = smem_u32(Alo);
    uint32_t bh_b = smem_u32(Bh), bl_b = smem_u32(Bl);
    int lm = lane & 15, lh = lane >> 4;

    for (int ck = 0; ck < 16; ck++) {
        int k0 = ck * 64;
#pragma unroll
        for (int e = 0; e < 4; e++) {
            int idx = tid + 256 * e;
            int m = idx >> 3, c8 = idx & 7;
            *(uint4*)&Ah[m * 72 + c8 * 8]  = *(const uint4*)&g_ctxH[((size_t)ck * S + row0 + m) * DH + c8 * 8];
            *(uint4*)&Alo[m * 72 + c8 * 8] = *(const uint4*)&g_ctxL[((size_t)ck * S + row0 + m) * DH + c8 * 8];
        }
#pragma unroll
        for (int e = 0; e < 2; e++) {
            int idx = tid + 256 * e;
            int kb = idx >> 3, c8 = idx & 7;
            *(uint4*)&Bh[kb * 72 + c8 * 8] = *(const uint4*)&g_Woh[(size_t)(k0 + kb) * D + col0 + c8 * 8];
            *(uint4*)&Bl[kb * 72 + c8 * 8] = *(const uint4*)&g_Wol[(size_t)(k0 + kb) * D + col0 + c8 * 8];
        }
        if (tid < 128) scs[tid] = g_scale[ck * S + row0 + tid];
        __syncthreads();

        float accp[2][4][4];
#pragma unroll
        for (int i = 0; i < 2; i++)
#pragma unroll
            for (int j = 0; j < 4; j++)
#pragma unroll
                for (int l = 0; l < 4; l++) accp[i][j][l] = 0.f;

#pragma unroll
        for (int kk = 0; kk < 64; kk += 16) {
            uint32_t a_h[2][4], a_l[2][4];
#pragma unroll
            for (int mt = 0; mt < 2; mt++) {
                ldm_x4(a_h[mt], ah_b + ((wm * 32 + mt * 16 + lm) * 72 + kk + lh * 8) * 2);
                ldm_x4(a_l[mt], al_b + ((wm * 32 + mt * 16 + lm) * 72 + kk + lh * 8) * 2);
            }
#pragma unroll
            for (int ng = 0; ng < 2; ng++) {
                uint32_t b_h[4], b_l[4];
                ldm_x4_trans(b_h, bh_b + ((kk + lm) * 72 + wn * 32 + ng * 16 + lh * 8) * 2);
                ldm_x4_trans(b_l, bl_b + ((kk + lm) * 72 + wn * 32 + ng * 16 + lh * 8) * 2);
#pragma unroll
                for (int mt = 0; mt < 2; mt++) {
                    mma16816(accp[mt][ng * 2 + 0], a_h[mt], b_h[0], b_h[1]);
                    mma16816(accp[mt][ng * 2 + 0], a_h[mt], b_l[0], b_l[1]);
                    mma16816(accp[mt][ng * 2 + 0], a_l[mt], b_h[0], b_h[1]);
                    mma16816(accp[mt][ng * 2 + 1], a_h[mt], b_h[2], b_h[3]);
                    mma16816(accp[mt][ng * 2 + 1], a_h[mt], b_l[2], b_l[3]);
                    mma16816(accp[mt][ng * 2 + 1], a_l[mt], b_h[2], b_h[3]);
                }
            }
        }

#pragma unroll
        for (int mt = 0; mt < 2; mt++) {
            int rl = wm * 32 + mt * 16 + (lane >> 2);
            float sc0 = scs[rl], sc1 = scs[rl + 8];
#pragma unroll
            for (int nt = 0; nt < 4; nt++) {
                acc[mt][nt][0] += sc0 * accp[mt][nt][0];
                acc[mt][nt][1] += sc0 * accp[mt][nt][1];
                acc[mt][nt][2] += sc1 * accp[mt][nt][2];
                acc[mt][nt][3] += sc1 * accp[mt][nt][3];
            }
        }
        __syncthreads();
    }

#pragma unroll
    for (int mt = 0; mt < 2; mt++) {
        int r0 = row0 + wm * 32 + mt * 16 + (lane >> 2);
#pragma unroll
        for (int nt = 0; nt < 4; nt++) {
            int c = col0 + wn * 32 + nt * 8 + (lane & 3) * 2;
#pragma unroll
            for (int rr = 0; rr < 2; rr++) {
                int s = r0 + rr * 8;
                *(float2*)&out[(size_t)s * D + c] =
                    make_float2(acc[mt][nt][rr * 2 + 0], acc[mt][nt][rr * 2 + 1]);
            }
        }
    }
}

// ---------------- launch ----------------------------------------------------------
extern "C" void kernel_launch(void* const* d_in, const int* in_sizes, int n_in,
                              void* d_out, int out_size) {
    const float* x          = (const float*)d_in[0];
    const float* Wq         = (const float*)d_in[1];
    const float* Wk         = (const float*)d_in[2];
    const float* Wv         = (const float*)d_in[3];
    const float* Wo         = (const float*)d_in[4];
    const float* bandwidth  = (const float*)d_in[5];
    const float* diag_scale = (const float*)d_in[6];
    const float* pos        = (const float*)d_in[7];
    const float* proj       = (const float*)d_in[8];
    const float* reg        = (const float*)d_in[9];
    const float* lam        = (const float*)d_in[10];
    float* out = (float*)d_out;

    static bool attr_done = false;
    if (!attr_done) {
        cudaFuncSetAttribute(qkv_tc, cudaFuncAttributeMaxDynamicSharedMemorySize, 71680);
        cudaFuncSetAttribute(wo_tc, cudaFuncAttributeMaxDynamicSharedMemorySize, 55808);
        cudaFuncSetAttribute(kmat_tc, cudaFuncAttributeMaxDynamicSharedMemorySize, 108544);
        cudaFuncSetAttribute(kapply_mma, cudaFuncAttributeMaxDynamicSharedMemorySize, 55296);
        attr_done = true;
    }

    const int NTOT = S * D + 4 * D * D;
    cvt_all<<<(NTOT + 255) / 256, 256>>>(x, Wq, Wk, Wv, Wo);

    qkv_tc<<<dim3(D / 128, S / 128, 3), 256, 71680>>>();
    norms_diag<<<(H * S * 32 + 255) / 256, 256>>>(diag_scale, reg, bandwidth);
    transpose_k<<<dim3(S / 32, DH / 32, H), dim3(32, 8)>>>();
    kmat_tc<<<dim3(S / 128, H), 256, 108544>>>(bandwidth);
    u_kernel<<<dim3(S / 256, H), 256>>>(pos, proj);

    // Richardson iteration 1 (alpha = 0 => r = v)
    utr_kernel<<<dim3(H, 16), 1024>>>();
    update_kernel<<<dim3(S / 16, H), 1024>>>(1);

    // iterations 2..5: utr fused into kapply epilogue
    for (int it = 1; it < 5; it++) {
        kapply_mma<<<dim3(S / 128, H), 256, 55296>>>(0, lam);
        update_kernel<<<dim3(S / 16, H), 1024>>>(0);
    }

    kapply_mma<<<dim3(S / 128, H), 256, 55296>>>(1, lam);
    wo_tc<<<dim3(D / 64, S / 128), 256, 55808>>>(out);
}

// round 17
// speedup vs baseline: 1.0683x; 1.0152x over previous
#include <cuda_runtime.h>
#include <cuda_fp16.h>
#include <math.h>
#include <cstdint>

#define H 16
#define S 2048
#define D 1024
#define DH 64
#define RANK 16

// ---------------- scratch (device globals; no allocation allowed) ----------------
__device__ float g_q[H * S * DH];
__device__ float g_k[H * S * DH];
__device__ float g_v[H * S * DH];
__device__ float g_alpha[H * S * DH];
__device__ __half g_alphaH[H * S * DH];
__device__ float g_r[H * S * DH];
__device__ __half g_ctxH[H * S * DH];   // normalized ctx = K'@alpha (hi)
__device__ __half g_ctxL[H * S * DH];   // normalized ctx (lo)
__device__ __half g_Kh[(size_t)H * S * S];       // 128 MB fp16 row-normalized kernel
__device__ float g_scale[H * S];                 // per-row scale exp(-dmin*inv)
__device__ float g_qn[H * S];
__device__ float g_kn[H * S];
__device__ float g_diagp[H * S];
__device__ float g_U[H * S * RANK];
__device__ float g_utr_part[16 * H * RANK * DH];   // 16 partial blocks (one per M tile)

// split fp16 operands
__device__ __half g_xh[S * D],  g_xl[S * D];
__device__ __half g_Wh[3 * D * D], g_Wl[3 * D * D];   // Wq, Wk, Wv
__device__ __half g_Woh[D * D], g_Wol[D * D];
__device__ __half g_qhh[H * S * DH], g_qll[H * S * DH];
__device__ __half g_kTh[H * DH * S], g_kTl[H * DH * S];  // transposed k (written by qkv)

__device__ __forceinline__ float softplusf(float x) {
    return (x > 20.f) ? x : log1pf(expf(x));
}

// ======================= HMMA helpers (mma.sync + ldmatrix) =======================
__device__ __forceinline__ uint32_t smem_u32(const void* p) {
    uint32_t a;
    asm("{ .reg .u64 t; cvta.to.shared.u64 t, %1; cvt.u32.u64 %0, t; }" : "=r"(a) : "l"(p));
    return a;
}
__device__ __forceinline__ void ldm_x4(uint32_t* r, uint32_t addr) {
    asm volatile("ldmatrix.sync.aligned.m8n8.x4.shared.b16 {%0,%1,%2,%3}, [%4];"
                 : "=r"(r[0]), "=r"(r[1]), "=r"(r[2]), "=r"(r[3]) : "r"(addr));
}
__device__ __forceinline__ void ldm_x4_trans(uint32_t* r, uint32_t addr) {
    asm volatile("ldmatrix.sync.aligned.m8n8.x4.trans.shared.b16 {%0,%1,%2,%3}, [%4];"
                 : "=r"(r[0]), "=r"(r[1]), "=r"(r[2]), "=r"(r[3]) : "r"(addr));
}
__device__ __forceinline__ void mma16816(float* c, const uint32_t* a, uint32_t b0, uint32_t b1) {
    asm volatile(
        "mma.sync.aligned.m16n8k16.row.col.f32.f16.f16.f32 "
        "{%0,%1,%2,%3}, {%4,%5,%6,%7}, {%8,%9}, {%0,%1,%2,%3};"
        : "+f"(c[0]), "+f"(c[1]), "+f"(c[2]), "+f"(c[3])
        : "r"(a[0]), "r"(a[1]), "r"(a[2]), "r"(a[3]), "r"(b0), "r"(b1));
}
__device__ __forceinline__ void cp_async16(uint32_t saddr, const void* gaddr) {
    asm volatile("cp.async.cg.shared.global [%0], [%1], 16;" :: "r"(saddr), "l"(gaddr) : "memory");
}

// ---------------- fp32 -> (hi, lo) fp16 split conversion (merged) -----------------
__global__ void cvt_all(const float* __restrict__ x, const float* __restrict__ wq,
                        const float* __restrict__ wk, const float* __restrict__ wv,
                        const float* __restrict__ wo) {
    int i = blockIdx.x * blockDim.x + threadIdx.x;
    const int NX = S * D, NW = D * D;
    const float* src;
    __half *hi, *lo;
    int off;
    if (i < NX)               { src = x;  hi = g_xh;           lo = g_xl;           off = i; }
    else if (i < NX + NW)     { src = wq; hi = g_Wh;           lo = g_Wl;           off = i - NX; }
    else if (i < NX + 2 * NW) { src = wk; hi = g_Wh + NW;      lo = g_Wl + NW;      off = i - NX - NW; }
    else if (i < NX + 3 * NW) { src = wv; hi = g_Wh + 2 * NW;  lo = g_Wl + 2 * NW;  off = i - NX - 2 * NW; }
    else if (i < NX + 4 * NW) { src = wo; hi = g_Woh;          lo = g_Wol;          off = i - NX - 3 * NW; }
    else return;
    float v = src[off];
    __half h = __float2half(v);
    hi[off] = h;
    lo[off] = __float2half(v - __half2float(h));
}

// ===== QKV split-fp16 tensor GEMM: C = x @ W_z; heads layout; k written TRANSPOSED
__global__ void __launch_bounds__(256) qkv_tc() {
    extern __shared__ __align__(16) char sm[];
    __half* Ah = (__half*)sm;                 // [128][72]
    __half* Alo = (__half*)(sm + 18432);
    __half* Bh = (__half*)(sm + 36864);       // [64][136]
    __half* Bl = (__half*)(sm + 54272);

    int tid = threadIdx.x, lane = tid & 31, wid = tid >> 5;
    int wm = wid >> 1, wn = wid & 1;
    int row0 = blockIdx.y * 128, col0 = blockIdx.x * 128;
    int which = blockIdx.z;
    const __half* Whp = g_Wh + (size_t)which * D * D;
    const __half* Wlp = g_Wl + (size_t)which * D * D;

    float acc[2][8][4];
#pragma unroll
    for (int i = 0; i < 2; i++)
#pragma unroll
        for (int j = 0; j < 8; j++)
#pragma unroll
            for (int l = 0; l < 4; l++) acc[i][j][l] = 0.f;

    uint32_t ah_b = smem_u32(Ah), al_b = smem_u32(Alo);
    uint32_t bh_b = smem_u32(Bh), bl_b = smem_u32(Bl);
    int lm = lane & 15, lh = lane >> 4;

    for (int k0 = 0; k0 < D; k0 += 64) {
#pragma unroll
        for (int e = 0; e < 4; e++) {
            int idx = tid + 256 * e;           // 0..1023
            int m = idx >> 3, c8 = idx & 7;
            *(uint4*)&Ah[m * 72 + c8 * 8]  = *(const uint4*)&g_xh[(size_t)(row0 + m) * D + k0 + c8 * 8];
            *(uint4*)&Alo[m * 72 + c8 * 8] = *(const uint4*)&g_xl[(size_t)(row0 + m) * D + k0 + c8 * 8];
            int kb = idx >> 4, c16 = idx & 15;
            *(uint4*)&Bh[kb * 136 + c16 * 8] = *(const uint4*)&Whp[(size_t)(k0 + kb) * D + col0 + c16 * 8];
            *(uint4*)&Bl[kb * 136 + c16 * 8] = *(const uint4*)&Wlp[(size_t)(k0 + kb) * D + col0 + c16 * 8];
        }
        __syncthreads();
#pragma unroll
        for (int kk = 0; kk < 64; kk += 16) {
            uint32_t a_h[2][4], a_l[2][4];
#pragma unroll
            for (int mt = 0; mt < 2; mt++) {
                ldm_x4(a_h[mt], ah_b + ((wm * 32 + mt * 16 + lm) * 72 + kk + lh * 8) * 2);
                ldm_x4(a_l[mt], al_b + ((wm * 32 + mt * 16 + lm) * 72 + kk + lh * 8) * 2);
            }
#pragma unroll
            for (int ng = 0; ng < 4; ng++) {
                uint32_t b_h[4], b_l[4];
                ldm_x4_trans(b_h, bh_b + ((kk + lm) * 136 + wn * 64 + ng * 16 + lh * 8) * 2);
                ldm_x4_trans(b_l, bl_b + ((kk + lm) * 136 + wn * 64 + ng * 16 + lh * 8) * 2);
#pragma unroll
                for (int mt = 0; mt < 2; mt++) {
                    mma16816(acc[mt][ng * 2 + 0], a_h[mt], b_h[0], b_h[1]);
                    mma16816(acc[mt][ng * 2 + 0], a_h[mt], b_l[0], b_l[1]);
                    mma16816(acc[mt][ng * 2 + 0], a_l[mt], b_h[0], b_h[1]);
                    mma16816(acc[mt][ng * 2 + 1], a_h[mt], b_h[2], b_h[3]);
                    mma16816(acc[mt][ng * 2 + 1], a_h[mt], b_l[2], b_l[3]);
                    mma16816(acc[mt][ng * 2 + 1], a_l[mt], b_h[2], b_h[3]);
                }
            }
        }
        __syncthreads();
    }

    float* outF = (which == 0) ? g_q : (which == 1) ? g_k : g_v;
    // k-transpose staging (tiles are dead after final sync)
    __half* aTh = (__half*)sm;                 // [128 cols][136 rows-pitch]
    __half* aTl = (__half*)(sm + 34816);
#pragma unroll
    for (int mt = 0; mt < 2; mt++) {
        int rl = wm * 32 + mt * 16 + (lane >> 2);
        int r0 = row0 + rl;
#pragma unroll
        for (int nt = 0; nt < 8; nt++) {
            int cl = wn * 64 + nt * 8 + (lane & 3) * 2;
            int c = col0 + cl;
            int hh = c >> 6, dh = c & 63;
#pragma unroll
            for (int rr = 0; rr < 2; rr++) {
                int s = r0 + rr * 8;
                int sl = rl + rr * 8;
                float v0 = acc[mt][nt][rr * 2 + 0], v1 = acc[mt][nt][rr * 2 + 1];
                size_t gi = ((size_t)hh * S + s) * DH + dh;
                *(float2*)&outF[gi] = make_float2(v0, v1);
                if (which == 0) {
                    __half h0 = __float2half(v0), h1 = __float2half(v1);
                    *(__half2*)&g_qhh[gi] = __halves2half2(h0, h1);
                    *(__half2*)&g_qll[gi] = __halves2half2(
                        __float2half(v0 - __half2float(h0)),
                        __float2half(v1 - __half2float(h1)));
                } else if (which == 1) {
                    __half h0 = __float2half(v0), h1 = __float2half(v1);
                    aTh[cl * 136 + sl] = h0;
                    aTh[(cl + 1) * 136 + sl] = h1;
                    aTl[cl * 136 + sl] = __float2half(v0 - __half2float(h0));
                    aTl[(cl + 1) * 136 + sl] = __float2half(v1 - __half2float(h1));
                }
            }
        }
    }
    if (which == 1) {
        __syncthreads();
        // coalesced copy-out: 128 cols x 128 rows, 8 halves (16B) per thread-iter
#pragma unroll
        for (int e = 0; e < 8; e++) {
            int idx = tid + 256 * e;          // 0..2047
            int cl = idx >> 4;                // 0..127
            int mo = (idx & 15) * 8;          // 0..120
            int hh = (col0 + cl) >> 6, dh = (col0 + cl) & 63;
            size_t dst = ((size_t)hh * DH + dh) * S + row0 + mo;
            *(uint4*)&g_kTh[dst] = *(const uint4*)&aTh[cl * 136 + mo];
            *(uint4*)&g_kTl[dst] = *(const uint4*)&aTl[cl * 136 + mo];
        }
    }
}

// ---------------- fused: row norms of q,k + diag_p (one 16MB pass) ----------------
__global__ void norms_diag(const float* __restrict__ diag_scale,
                           const float* __restrict__ reg_p,
                           const float* __restrict__ bw_p) {
    int gw = (blockIdx.x * blockDim.x + threadIdx.x) >> 5;
    int lane = threadIdx.x & 31;
    if (gw >= H * S) return;
    const float* qp = g_q + (size_t)gw * DH;
    const float* kp = g_k + (size_t)gw * DH;
    float qa = qp[lane], qb = qp[lane + 32];
    float ka = kp[lane], kb = kp[lane + 32];
    float qn = qa * qa + qb * qb;
    float kn = ka * ka + kb * kb;
    float da = qa - ka, db = qb - kb;
    float dd = da * da + db * db;
#pragma unroll
    for (int o = 16; o > 0; o >>= 1) {
        qn += __shfl_xor_sync(0xffffffffu, qn, o);
        kn += __shfl_xor_sync(0xffffffffu, kn, o);
        dd += __shfl_xor_sync(0xffffffffu, dd, o);
    }
    if (lane == 0) {
        g_qn[gw] = qn;
        g_kn[gw] = kn;
        float bw = softplusf(bw_p[0]) + 1e-6f;
        float inv = 1.0f / (2.0f * bw * bw);
        float kd = __expf(-dd * inv);
        g_diagp[gw] = softplusf(kd) * diag_scale[gw / S] + reg_p[0];
    }
}

// ===== fused kmat (FULL phase1, cp.async double-buffered B tiles) =================
__global__ void __launch_bounds__(256) kmat_tc(const float* __restrict__ bw_p) {
    extern __shared__ __align__(16) char sm[];
    __half* Qh = (__half*)sm;                 // [128][72] 18432
    __half* Ql = (__half*)(sm + 18432);       // 18432
    float* qn_s = (float*)(sm + 106496);      // 512
    float* kn_p0 = (float*)(sm + 107008);     // 512
    float* kn_p1 = (float*)(sm + 107520);     // 512
    unsigned* minv = (unsigned*)(sm + 108032);// 512   -> total 108544

    uint32_t base = smem_u32(sm);
    uint32_t bhB[2] = {base + 36864u, base + 71680u};
    uint32_t blB[2] = {base + 54272u, base + 89088u};
    uint32_t knB[2] = {base + 107008u, base + 107520u};
    float* kn_p[2] = {kn_p0, kn_p1};

    int tid = threadIdx.x, lane = tid & 31, wid = tid >> 5;
    int h = blockIdx.y, i0 = blockIdx.x * 128;
    float bw = softplusf(bw_p[0]) + 1e-6f;
    float inv = 1.0f / (2.0f * bw * bw);

#pragma unroll
    for (int e = 0; e < 4; e++) {
        int idx = tid + 256 * e;
        int m = idx >> 3, c8 = idx & 7;
        *(uint4*)&Qh[m * 72 + c8 * 8] = *(const uint4*)&g_qhh[((size_t)h * S + i0 + m) * DH + c8 * 8];
        *(uint4*)&Ql[m * 72 + c8 * 8] = *(const uint4*)&g_qll[((size_t)h * S + i0 + m) * DH + c8 * 8];
    }
    if (tid < 128) {
        qn_s[tid] = g_qn[h * S + i0 + tid];
        minv[tid] = 0x7F800000u;
    }
    __syncthreads();

    uint32_t qh_b = smem_u32(Qh), ql_b = smem_u32(Ql);
    int lm = lane & 15, lh = lane >> 4;

    const __half* kThp = g_kTh + (size_t)h * DH * S;
    const __half* kTlp = g_kTl + (size_t)h * DH * S;

    float rmin[16];
#pragma unroll
    for (int i = 0; i < 16; i++) rmin[i] = 3.4e38f;

    // ---------------- phase 1: hi-only dist over ALL columns (pipelined) ----------
    {
#pragma unroll
        for (int e = 0; e < 4; e++) {
            int idx = tid + 256 * e;
            int kb = idx >> 4, c16 = idx & 15;
            cp_async16(bhB[0] + (uint32_t)(kb * 272 + c16 * 16),
                       kThp + (size_t)kb * S + c16 * 8);
        }
        if (tid < 32)
            cp_async16(knB[0] + (uint32_t)(tid * 16), &g_kn[h * S + tid * 4]);
        asm volatile("cp.async.commit_group;" ::: "memory");
    }

    for (int c = 0; c < 16; c++) {
        int st = c & 1;
        if (c < 15) {
            int j0n = (c + 1) * 128;
            int sn = st ^ 1;
#pragma unroll
            for (int e = 0; e < 4; e++) {
                int idx = tid + 256 * e;
                int kb = idx >> 4, c16 = idx & 15;
                cp_async16(bhB[sn] + (uint32_t)(kb * 272 + c16 * 16),
                           kThp + (size_t)kb * S + j0n + c16 * 8);
            }
            if (tid < 32)
                cp_async16(knB[sn] + (uint32_t)(tid * 16), &g_kn[h * S + j0n + tid * 4]);
            asm volatile("cp.async.commit_group;" ::: "memory");
            asm volatile("cp.async.wait_group 1;" ::: "memory");
        } else {
            asm volatile("cp.async.wait_group 0;" ::: "memory");
        }
        __syncthreads();

        uint32_t bf[4][4];
#pragma unroll
        for (int k4 = 0; k4 < 4; k4++)
            ldm_x4_trans(bf[k4], bhB[st] + (uint32_t)(((k4 * 16 + lm) * 136 + wid * 16 + lh * 8) * 2));

        const float* kns = kn_p[st];
#pragma unroll
        for (int mt = 0; mt < 8; mt++) {
            float a0[4] = {0.f, 0.f, 0.f, 0.f}, a1[4] = {0.f, 0.f, 0.f, 0.f};
#pragma unroll
            for (int k4 = 0; k4 < 4; k4++) {
                uint32_t a[4];
                ldm_x4(a, qh_b + ((mt * 16 + lm) * 72 + k4 * 16 + lh * 8) * 2);
                mma16816(a0, a, bf[k4][0], bf[k4][1]);
                mma16816(a1, a, bf[k4][2], bf[k4][3]);
            }
            int r = mt * 16 + (lane >> 2);
            float qn0 = qn_s[r], qn1 = qn_s[r + 8];
            int cb = wid * 16 + (lane & 3) * 2;
            float kn0 = kns[cb], kn1 = kns[cb + 1], kn8 = kns[cb + 8], kn9 = kns[cb + 9];
            float d0 = fminf(fminf(qn0 + kn0 - 2.f * a0[0], qn0 + kn1 - 2.f * a0[1]),
                             fminf(qn0 + kn8 - 2.f * a1[0], qn0 + kn9 - 2.f * a1[1]));
            float d1 = fminf(fminf(qn1 + kn0 - 2.f * a0[2], qn1 + kn1 - 2.f * a0[3]),
                             fminf(qn1 + kn8 - 2.f * a1[2], qn1 + kn9 - 2.f * a1[3]));
            rmin[mt * 2] = fminf(rmin[mt * 2], d0);
            rmin[mt * 2 + 1] = fminf(rmin[mt * 2 + 1], d1);
        }
        __syncthreads();
    }
#pragma unroll
    for (int i = 0; i < 16; i++) {
        rmin[i] = fminf(rmin[i], __shfl_xor_sync(0xffffffffu, rmin[i], 1));
        rmin[i] = fminf(rmin[i], __shfl_xor_sync(0xffffffffu, rmin[i], 2));
    }
    if ((lane & 3) == 0) {
#pragma unroll
        for (int mt = 0; mt < 8; mt++) {
            atomicMin(&minv[mt * 16 + (lane >> 2)], __float_as_uint(fmaxf(rmin[mt * 2], 0.f)));
            atomicMin(&minv[mt * 16 + (lane >> 2) + 8], __float_as_uint(fmaxf(rmin[mt * 2 + 1], 0.f)));
        }
    }
    __syncthreads();
    if (tid < 128)
        g_scale[h * S + i0 + tid] = __expf(-__uint_as_float(minv[tid]) * inv);

    // ---------------- phase 2: split dist, exp -> Kh fp16 (pipelined) -------------
    {
#pragma unroll
        for (int e = 0; e < 4; e++) {
            int idx = tid + 256 * e;
            int kb = idx >> 4, c16 = idx & 15;
            cp_async16(bhB[0] + (uint32_t)(kb * 272 + c16 * 16),
                       kThp + (size_t)kb * S + c16 * 8);
            cp_async16(blB[0] + (uint32_t)(kb * 272 + c16 * 16),
                       kTlp + (size_t)kb * S + c16 * 8);
        }
        if (tid < 32)
            cp_async16(knB[0] + (uint32_t)(tid * 16), &g_kn[h * S + tid * 4]);
        asm volatile("cp.async.commit_group;" ::: "memory");
    }

    for (int c = 0; c < 16; c++) {
        int st = c & 1;
        int j0 = c * 128;
        if (c < 15) {
            int j0n = (c + 1) * 128;
            int sn = st ^ 1;
#pragma unroll
            for (int e = 0; e < 4; e++) {
                int idx = tid + 256 * e;
                int kb = idx >> 4, c16 = idx & 15;
                cp_async16(bhB[sn] + (uint32_t)(kb * 272 + c16 * 16),
                           kThp + (size_t)kb * S + j0n + c16 * 8);
                cp_async16(blB[sn] + (uint32_t)(kb * 272 + c16 * 16),
                           kTlp + (size_t)kb * S + j0n + c16 * 8);
            }
            if (tid < 32)
                cp_async16(knB[sn] + (uint32_t)(tid * 16), &g_kn[h * S + j0n + tid * 4]);
            asm volatile("cp.async.commit_group;" ::: "memory");
            asm volatile("cp.async.wait_group 1;" ::: "memory");
        } else {
            asm volatile("cp.async.wait_group 0;" ::: "memory");
        }
        __syncthreads();

        uint32_t bfh[4][4], bfl[4][4];
#pragma unroll
        for (int k4 = 0; k4 < 4; k4++) {
            ldm_x4_trans(bfh[k4], bhB[st] + (uint32_t)(((k4 * 16 + lm) * 136 + wid * 16 + lh * 8) * 2));
            ldm_x4_trans(bfl[k4], blB[st] + (uint32_t)(((k4 * 16 + lm) * 136 + wid * 16 + lh * 8) * 2));
        }

        const float* kns = kn_p[st];
#pragma unroll
        for (int mt = 0; mt < 8; mt++) {
            float a0[4] = {0.f, 0.f, 0.f, 0.f}, a1[4] = {0.f, 0.f, 0.f, 0.f};
#pragma unroll
            for (int k4 = 0; k4 < 4; k4++) {
                uint32_t ah[4], al[4];
                ldm_x4(ah, qh_b + ((mt * 16 + lm) * 72 + k4 * 16 + lh * 8) * 2);
                ldm_x4(al, ql_b + ((mt * 16 + lm) * 72 + k4 * 16 + lh * 8) * 2);
                mma16816(a0, ah, bfh[k4][0], bfh[k4][1]);
                mma16816(a0, ah, bfl[k4][0], bfl[k4][1]);
                mma16816(a0, al, bfh[k4][0], bfh[k4][1]);
                mma16816(a1, ah, bfh[k4][2], bfh[k4][3]);
                mma16816(a1, ah, bfl[k4][2], bfl[k4][3]);
                mma16816(a1, al, bfh[k4][2], bfh[k4][3]);
            }
            int r = mt * 16 + (lane >> 2);
            float qn0 = qn_s[r], qn1 = qn_s[r + 8];
            float dm0 = __uint_as_float(minv[r]), dm1 = __uint_as_float(minv[r + 8]);
            int cb = wid * 16 + (lane & 3) * 2;
            float kn0 = kns[cb], kn1 = kns[cb + 1], kn8 = kns[cb + 8], kn9 = kns[cb + 9];
            float e00 = __expf((dm0 - fmaxf(qn0 + kn0 - 2.f * a0[0], 0.f)) * inv);
            float e01 = __expf((dm0 - fmaxf(qn0 + kn1 - 2.f * a0[1], 0.f)) * inv);
            float e10 = __expf((dm1 - fmaxf(qn1 + kn0 - 2.f * a0[2], 0.f)) * inv);
            float e11 = __expf((dm1 - fmaxf(qn1 + kn1 - 2.f * a0[3], 0.f)) * inv);
            float f00 = __expf((dm0 - fmaxf(qn0 + kn8 - 2.f * a1[0], 0.f)) * inv);
            float f01 = __expf((dm0 - fmaxf(qn0 + kn9 - 2.f * a1[1], 0.f)) * inv);
            float f10 = __expf((dm1 - fmaxf(qn1 + kn8 - 2.f * a1[2], 0.f)) * inv);
            float f11 = __expf((dm1 - fmaxf(qn1 + kn9 - 2.f * a1[3], 0.f)) * inv);
            __half* Kp0 = &g_Kh[((size_t)(h * S + i0 + r)) * S + j0 + cb];
            __half* Kp1 = Kp0 + (size_t)8 * S;
            *(__half2*)Kp0 = __halves2half2(__float2half(e00), __float2half(e01));
            *(__half2*)(Kp0 + 8) = __halves2half2(__float2half(f00), __float2half(f01));
            *(__half2*)Kp1 = __halves2half2(__float2half(e10), __float2half(e11));
            *(__half2*)(Kp1 + 8) = __halves2half2(__float2half(f10), __float2half(f11));
        }
        __syncthreads();
    }
}

// ---------------- U[h,s,r] = sum_rp pos[s,rp] * proj[h,rp,r] ----------------------
__global__ void u_kernel(const float* __restrict__ pos, const float* __restrict__ proj) {
    __shared__ float pr[RANK][RANK];
    int h = blockIdx.y;
    int tid = threadIdx.x;
    pr[tid >> 4][tid & 15] = proj[h * RANK * RANK + tid];
    __syncthreads();
    int s = blockIdx.x * 256 + tid;
    float pe[RANK];
#pragma unroll
    for (int r = 0; r < RANK; r++) pe[r] = pos[(size_t)s * RANK + r];
#pragma unroll
    for (int r = 0; r < RANK; r++) {
        float acc = 0.f;
#pragma unroll
        for (int rp = 0; rp < RANK; rp++) acc += pe[rp] * pr[rp][r];
        g_U[((size_t)h * S + s) * RANK + r] = acc;
    }
}

// == HMMA K@alpha (2-stage cp.async, 4x2 warp layout) + fused U^T r partials =======
// mode0: r = v - scale*K'a - lam*a, writes g_r AND utr_part[blockIdx.x]
// mode1: store NORMALIZED K'a hi/lo
__global__ void __launch_bounds__(256) kapply_mma(int mode, const float* __restrict__ lam_p) {
    extern __shared__ __align__(16) char sm[];
    uint32_t base = smem_u32(sm);
    uint32_t ksb0 = base, ksb1 = base + 18432;
    uint32_t alb0 = base + 36864, alb1 = base + 46080;

    int tid = threadIdx.x, wid = tid >> 5, lane = tid & 31;
    int wm = wid >> 1, wn = wid & 1;      // 4 M-quarters x 2 N-halves
    int h = blockIdx.y;
    int s0 = blockIdx.x * 128;

    const __half* Kb = g_Kh + ((size_t)h * S + s0) * S;
    const __half* Ab = g_alphaH + (size_t)h * S * DH;

    float acc[2][4][4];
#pragma unroll
    for (int i = 0; i < 2; i++)
#pragma unroll
        for (int j = 0; j < 4; j++)
#pragma unroll
            for (int l = 0; l < 4; l++) acc[i][j][l] = 0.f;

    int lm = lane & 15, lh = lane >> 4;
    int mA = tid >> 3, c8A = tid & 7;

    {
        int t0 = 0;
#pragma unroll
        for (int e = 0; e < 4; e++) {
            int m = mA + 32 * e;
            cp_async16(ksb0 + (uint32_t)(m * 144 + c8A * 16), Kb + (size_t)m * S + t0 + c8A * 8);
        }
#pragma unroll
        for (int e = 0; e < 2; e++) {
            int t = mA + 32 * e;
            cp_async16(alb0 + (uint32_t)(t * 144 + c8A * 16), Ab + (size_t)(t0 + t) * DH + c8A * 8);
        }
        asm volatile("cp.async.commit_group;" ::: "memory");
    }

    for (int c = 0; c < 32; c++) {
        uint32_t ks_cur = (c & 1) ? ksb1 : ksb0;
        uint32_t al_cur = (c & 1) ? alb1 : alb0;
        if (c < 31) {
            uint32_t ks_nxt = (c & 1) ? ksb0 : ksb1;
            uint32_t al_nxt = (c & 1) ? alb0 : alb1;
            int t0 = (c + 1) * 64;
#pragma unroll
            for (int e = 0; e < 4; e++) {
                int m = mA + 32 * e;
                cp_async16(ks_nxt + (uint32_t)(m * 144 + c8A * 16), Kb + (size_t)m * S + t0 + c8A * 8);
            }
#pragma unroll
            for (int e = 0; e < 2; e++) {
                int t = mA + 32 * e;
                cp_async16(al_nxt + (uint32_t)(t * 144 + c8A * 16), Ab + (size_t)(t0 + t) * DH + c8A * 8);
            }
            asm volatile("cp.async.commit_group;" ::: "memory");
            asm volatile("cp.async.wait_group 1;" ::: "memory");
        } else {
            asm volatile("cp.async.wait_group 0;" ::: "memory");
        }
        __syncthreads();

#pragma unroll
        for (int kk = 0; kk < 64; kk += 16) {
            uint32_t a[2][4];
#pragma unroll
            for (int mt = 0; mt < 2; mt++)
                ldm_x4(a[mt], ks_cur + (uint32_t)(((wm * 32 + mt * 16 + lm) * 72 + kk + lh * 8) * 2));
#pragma unroll
            for (int ng = 0; ng < 2; ng++) {
                uint32_t b[4];
                ldm_x4_trans(b, al_cur + (uint32_t)(((kk + lm) * 72 + wn * 32 + ng * 16 + lh * 8) * 2));
#pragma unroll
                for (int mt = 0; mt < 2; mt++) {
                    mma16816(acc[mt][ng * 2 + 0], a[mt], b[0], b[1]);
                    mma16816(acc[mt][ng * 2 + 1], a[mt], b[2], b[3]);
                }
            }
        }
        __syncthreads();
    }

    if (mode == 0) {
        float lam = softplusf(lam_p[0]);
        float* rsm = (float*)sm;              // [128][65] = 33280 B (buffers dead)
        float* Usm = (float*)(sm + 33280);    // [128][16] =  8192 B
#pragma unroll
        for (int e = 0; e < 8; e++) {
            int idx = tid + 256 * e;
            int m = idx >> 4, rr = idx & 15;
            Usm[m * 16 + rr] = g_U[((size_t)h * S + s0 + m) * RANK + rr];
        }
#pragma unroll
        for (int mt = 0; mt < 2; mt++) {
            int rl = wm * 32 + mt * 16 + (lane >> 2);
            int rbase = s0 + rl;
            float sc0 = g_scale[h * S + rbase];
            float sc1 = g_scale[h * S + rbase + 8];
#pragma unroll
            for (int nt = 0; nt < 4; nt++) {
                int col = wn * 32 + nt * 8 + (lane & 3) * 2;
                size_t g0 = ((size_t)h * S + rbase) * DH + col;
                size_t g1 = g0 + 8 * DH;
                float2 v0 = *(const float2*)&g_v[g0];
                float2 v1 = *(const float2*)&g_v[g1];
                float2 a0 = *(const float2*)&g_alpha[g0];
                float2 a1 = *(const float2*)&g_alpha[g1];
                float r00 = v0.x - sc0 * acc[mt][nt][0] - lam * a0.x;
                float r01 = v0.y - sc0 * acc[mt][nt][1] - lam * a0.y;
                float r10 = v1.x - sc1 * acc[mt][nt][2] - lam * a1.x;
                float r11 = v1.y - sc1 * acc[mt][nt][3] - lam * a1.y;
                *(float2*)&g_r[g0] = make_float2(r00, r01);
                *(float2*)&g_r[g1] = make_float2(r10, r11);
                rsm[rl * 65 + col] = r00;
                rsm[rl * 65 + col + 1] = r01;
                rsm[(rl + 8) * 65 + col] = r10;
                rsm[(rl + 8) * 65 + col + 1] = r11;
            }
        }
        __syncthreads();

        int d = tid & 63, rg = tid >> 6;
        float a4[4] = {0.f, 0.f, 0.f, 0.f};
        for (int s = 0; s < 128; s++) {
            float rv = rsm[s * 65 + d];
            a4[0] += Usm[s * 16 + rg] * rv;
            a4[1] += Usm[s * 16 + rg + 4] * rv;
            a4[2] += Usm[s * 16 + rg + 8] * rv;
            a4[3] += Usm[s * 16 + rg + 12] * rv;
        }
        int part = blockIdx.x;
#pragma unroll
        for (int i = 0; i < 4; i++)
            g_utr_part[(((size_t)part * H + h) * RANK + (rg + 4 * i)) * DH + d] = a4[i];
    } else {
#pragma unroll
        for (int mt = 0; mt < 2; mt++) {
            int rl = wm * 32 + mt * 16 + (lane >> 2);
            int rbase = s0 + rl;
#pragma unroll
            for (int nt = 0; nt < 4; nt++) {
                int col = wn * 32 + nt * 8 + (lane & 3) * 2;
                size_t g0 = ((size_t)h * S + rbase) * DH + col;
                size_t g1 = g0 + 8 * DH;
                float c00 = acc[mt][nt][0], c01 = acc[mt][nt][1];
                float c10 = acc[mt][nt][2], c11 = acc[mt][nt][3];
                __half h00 = __float2half(c00), h01 = __float2half(c01);
                __half h10 = __float2half(c10), h11 = __float2half(c11);
                *(__half2*)&g_ctxH[g0] = __halves2half2(h00, h01);
                *(__half2*)&g_ctxH[g1] = __halves2half2(h10, h11);
                *(__half2*)&g_ctxL[g0] = __halves2half2(__float2half(c00 - __half2float(h00)),
                                                        __float2half(c01 - __half2float(h01)));
                *(__half2*)&g_ctxL[g1] = __halves2half2(__float2half(c10 - __half2float(h10)),
                                                        __float2half(c11 - __half2float(h11)));
            }
        }
    }
}

// ------- utr_part[p,h,r,d] = sum_{s in part} U[h,s,r] * v[h,s,d] (iter 1 only) ----
__global__ void utr_kernel() {
    int h = blockIdx.x;
    int part = blockIdx.y;     // 0..15
    int tid = threadIdx.x;
    int d = tid & 63, rr = tid >> 6;
    const float* Ub = g_U + (size_t)h * S * RANK;
    const float* rb = g_v + (size_t)h * S * DH;
    int s0 = part * (S / 16);
    float a0 = 0, a1 = 0, a2 = 0, a3 = 0;
    for (int s = s0; s < s0 + S / 16; s += 4) {
        a0 += Ub[(s + 0) * RANK + rr] * rb[(size_t)(s + 0) * DH + d];
        a1 += Ub[(s + 1) * RANK + rr] * rb[(size_t)(s + 1) * DH + d];
        a2 += Ub[(s + 2) * RANK + rr] * rb[(size_t)(s + 2) * DH + d];
        a3 += Ub[(s + 3) * RANK + rr] * rb[(size_t)(s + 3) * DH + d];
    }
    g_utr_part[((part * H + h) * RANK + rr) * DH + d] = (a0 + a1) + (a2 + a3);
}

// ---------------- alpha = prev + r*diag_p + U @ utr; emit fp16 mirror -------------
__global__ void update_kernel(int first) {
    __shared__ float ut[RANK][DH];
    __shared__ float Us[16][RANK];
    int h = blockIdx.y;
    int tid = threadIdx.x;
    {
        float sum = 0.f;
#pragma unroll
        for (int p = 0; p < 16; p++) sum += g_utr_part[(p * H + h) * RANK * DH + tid];
        ut[tid >> 6][tid & 63] = sum;
    }
    int s0 = blockIdx.x * 16;
    if (tid < 16 * RANK)
        Us[tid >> 4][tid & 15] = g_U[((size_t)h * S + s0 + (tid >> 4)) * RANK + (tid & 15)];
    __syncthreads();

    int sl = tid >> 6;
    int d = tid & 63;
    int s = s0 + sl;
    size_t idx = ((size_t)h * S + s) * DH + d;
    float acc = 0.f;
#pragma unroll
    for (int r2 = 0; r2 < RANK; r2++) acc += Us[sl][r2] * ut[r2][d];
    float rv = first ? g_v[idx] : g_r[idx];
    float prev = first ? 0.f : g_alpha[idx];
    float na = prev + rv * g_diagp[h * S + s] + acc;
    g_alpha[idx] = na;
    g_alphaH[idx] = __float2half(na);
}

// == output GEMM (128x64 tiles): out = (scale ⊙ ctxN)_flat @ Wo ====================
__global__ void __launch_bounds__(256) wo_tc(float* __restrict__ out) {
    extern __shared__ __align__(16) char sm[];
    __half* Ah = (__half*)sm;                 // [128][72]
    __half* Alo = (__half*)(sm + 18432);
    __half* Bh = (__half*)(sm + 36864);       // [64][72]
    __half* Bl = (__half*)(sm + 46080);
    float* scs = (float*)(sm + 55296);        // 128 row scales

    int tid = threadIdx.x, lane = tid & 31, wid = tid >> 5;
    int wm = wid >> 1, wn = wid & 1;
    int row0 = blockIdx.y * 128, col0 = blockIdx.x * 64;

    float acc[2][4][4];
#pragma unroll
    for (int i = 0; i < 2; i++)
#pragma unroll
        for (int j = 0; j < 4; j++)
#pragma unroll
            for (int l = 0; l < 4; l++) acc[i][j][l] = 0.f;

    uint32_t ah_b = smem_u32(Ah), al_b = smem_u32(Alo);
    uint32_t bh_b = smem_u32(Bh), bl_b = smem_u32(Bl);
    int lm = lane & 15, lh = lane >> 4;

    for (int ck = 0; ck < 16; ck++) {
        int k0 = ck * 64;
#pragma unroll
        for (int e = 0; e < 4; e++) {
            int idx = tid + 256 * e;
            int m = idx >> 3, c8 = idx & 7;
            *(uint4*)&Ah[m * 72 + c8 * 8]  = *(const uint4*)&g_ctxH[((size_t)ck * S + row0 + m) * DH + c8 * 8];
            *(uint4*)&Alo[m * 72 + c8 * 8] = *(const uint4*)&g_ctxL[((size_t)ck * S + row0 + m) * DH + c8 * 8];
        }
#pragma unroll
        for (int e = 0; e < 2; e++) {
            int idx = tid + 256 * e;
            int kb = idx >> 3, c8 = idx & 7;
            *(uint4*)&Bh[kb * 72 + c8 * 8] = *(const uint4*)&g_Woh[(size_t)(k0 + kb) * D + col0 + c8 * 8];
            *(uint4*)&Bl[kb * 72 + c8 * 8] = *(const uint4*)&g_Wol[(size_t)(k0 + kb) * D + col0 + c8 * 8];
        }
        if (tid < 128) scs[tid] = g_scale[ck * S + row0 + tid];
        __syncthreads();

        float accp[2][4][4];
#pragma unroll
        for (int i = 0; i < 2; i++)
#pragma unroll
            for (int j = 0; j < 4; j++)
#pragma unroll
                for (int l = 0; l < 4; l++) accp[i][j][l] = 0.f;

#pragma unroll
        for (int kk = 0; kk < 64; kk += 16) {
            uint32_t a_h[2][4], a_l[2][4];
#pragma unroll
            for (int mt = 0; mt < 2; mt++) {
                ldm_x4(a_h[mt], ah_b + ((wm * 32 + mt * 16 + lm) * 72 + kk + lh * 8) * 2);
                ldm_x4(a_l[mt], al_b + ((wm * 32 + mt * 16 + lm) * 72 + kk + lh * 8) * 2);
            }
#pragma unroll
            for (int ng = 0; ng < 2; ng++) {
                uint32_t b_h[4], b_l[4];
                ldm_x4_trans(b_h, bh_b + ((kk + lm) * 72 + wn * 32 + ng * 16 + lh * 8) * 2);
                ldm_x4_trans(b_l, bl_b + ((kk + lm) * 72 + wn * 32 + ng * 16 + lh * 8) * 2);
#pragma unroll
                for (int mt = 0; mt < 2; mt++) {
                    mma16816(accp[mt][ng * 2 + 0], a_h[mt], b_h[0], b_h[1]);
                    mma16816(accp[mt][ng * 2 + 0], a_h[mt], b_l[0], b_l[1]);
                    mma16816(accp[mt][ng * 2 + 0], a_l[mt], b_h[0], b_h[1]);
                    mma16816(accp[mt][ng * 2 + 1], a_h[mt], b_h[2], b_h[3]);
                    mma16816(accp[mt][ng * 2 + 1], a_h[mt], b_l[2], b_l[3]);
                    mma16816(accp[mt][ng * 2 + 1], a_l[mt], b_h[2], b_h[3]);
                }
            }
        }

#pragma unroll
        for (int mt = 0; mt < 2; mt++) {
            int rl = wm * 32 + mt * 16 + (lane >> 2);
            float sc0 = scs[rl], sc1 = scs[rl + 8];
#pragma unroll
            for (int nt = 0; nt < 4; nt++) {
                acc[mt][nt][0] += sc0 * accp[mt][nt][0];
                acc[mt][nt][1] += sc0 * accp[mt][nt][1];
                acc[mt][nt][2] += sc1 * accp[mt][nt][2];
                acc[mt][nt][3] += sc1 * accp[mt][nt][3];
            }
        }
        __syncthreads();
    }

#pragma unroll
    for (int mt = 0; mt < 2; mt++) {
        int r0 = row0 + wm * 32 + mt * 16 + (lane >> 2);
#pragma unroll
        for (int nt = 0; nt < 4; nt++) {
            int c = col0 + wn * 32 + nt * 8 + (lane & 3) * 2;
#pragma unroll
            for (int rr = 0; rr < 2; rr++) {
                int s = r0 + rr * 8;
                *(float2*)&out[(size_t)s * D + c] =
                    make_float2(acc[mt][nt][rr * 2 + 0], acc[mt][nt][rr * 2 + 1]);
            }
        }
    }
}

// ---------------- launch ----------------------------------------------------------
extern "C" void kernel_launch(void* const* d_in, const int* in_sizes, int n_in,
                              void* d_out, int out_size) {
    const float* x          = (const float*)d_in[0];
    const float* Wq         = (const float*)d_in[1];
    const float* Wk         = (const float*)d_in[2];
    const float* Wv         = (const float*)d_in[3];
    const float* Wo         = (const float*)d_in[4];
    const float* bandwidth  = (const float*)d_in[5];
    const float* diag_scale = (const float*)d_in[6];
    const float* pos        = (const float*)d_in[7];
    const float* proj       = (const float*)d_in[8];
    const float* reg        = (const float*)d_in[9];
    const float* lam        = (const float*)d_in[10];
    float* out = (float*)d_out;

    static bool attr_done = false;
    if (!attr_done) {
        cudaFuncSetAttribute(qkv_tc, cudaFuncAttributeMaxDynamicSharedMemorySize, 71680);
        cudaFuncSetAttribute(wo_tc, cudaFuncAttributeMaxDynamicSharedMemorySize, 55808);
        cudaFuncSetAttribute(kmat_tc, cudaFuncAttributeMaxDynamicSharedMemorySize, 108544);
        cudaFuncSetAttribute(kapply_mma, cudaFuncAttributeMaxDynamicSharedMemorySize, 55296);
        attr_done = true;
    }

    const int NTOT = S * D + 4 * D * D;
    cvt_all<<<(NTOT + 255) / 256, 256>>>(x, Wq, Wk, Wv, Wo);

    qkv_tc<<<dim3(D / 128, S / 128, 3), 256, 71680>>>();
    norms_diag<<<(H * S * 32 + 255) / 256, 256>>>(diag_scale, reg, bandwidth);
    kmat_tc<<<dim3(S / 128, H), 256, 108544>>>(bandwidth);
    u_kernel<<<dim3(S / 256, H), 256>>>(pos, proj);

    // Richardson iteration 1 (alpha = 0 => r = v)
    utr_kernel<<<dim3(H, 16), 1024>>>();
    update_kernel<<<dim3(S / 16, H), 1024>>>(1);

    // iterations 2..5: utr fused into kapply epilogue
    for (int it = 1; it < 5; it++) {
        kapply_mma<<<dim3(S / 128, H), 256, 55296>>>(0, lam);
        update_kernel<<<dim3(S / 16, H), 1024>>>(0);
    }

    kapply_mma<<<dim3(S / 128, H), 256, 55296>>>(1, lam);
    wo_tc<<<dim3(D / 64, S / 128), 256, 55808>>>(out);
}